// round 13
// baseline (speedup 1.0000x reference)
#include <cuda_runtime.h>
#include <cuda_fp16.h>
#include <math.h>
#include <stdint.h>

// ---------------- problem constants ----------------
#define CB   2
#define CS   4096
#define CH   12
#define CD   64
#define CW   256
#define CDM  768
#define CDFF 3072
#define CNB  16
#define CL   2
#define CNEG (-1000000000.0f)
#define CSCALE 0.125f

#define MROWS (CB*CS)    // 8192
#define QKV_S 2304

// ---------------- scratch ----------------
__device__ float g_x   [MROWS*CDM];
__device__ float g_y   [MROWS*CDM];
__device__ float g_qkv [(size_t)MROWS*QKV_S];
__device__ float g_qg  [CB*CDM];
__device__ float g_bias[QKV_S];
__device__ float g_t   [CB*CH*CDM];
__device__ float g_p   [(size_t)CB*CH*CS];
__device__ float g_u   [CB*CH*CDM];
__device__ float g_up  [(size_t)32*CB*CH*CDM];   // u partials (32 s-chunks)
// hi/lo fp16 operand buffers (activations hi/lo; weights hi only)
__device__ __half g_xbh[(size_t)MROWS*CDM];
__device__ __half g_xbl[(size_t)MROWS*CDM];
__device__ __half g_abh[(size_t)MROWS*CDM];
__device__ __half g_abl[(size_t)MROWS*CDM];
__device__ __half g_hbh[(size_t)MROWS*CDFF];
__device__ __half g_hbl[(size_t)MROWS*CDFF];
__device__ __half g_wbh[(size_t)CDFF*CDM];

// ---------------- helpers ----------------
__device__ __forceinline__ float gelu_tanh(float x) {
    float x3 = x * x * x;
    return 0.5f * x * (1.0f + tanhf(0.7978845608028654f * (x + 0.044715f * x3)));
}
__device__ __forceinline__ uint32_t smem_u32(const void* p) {
    uint32_t a;
    asm("{ .reg .u64 t; cvta.to.shared.u64 t, %1; cvt.u32.u64 %0, t; }" : "=r"(a) : "l"(p));
    return a;
}
__device__ __forceinline__ void hilo(float v, __half& h, __half& l) {
    h = __float2half_rn(v);
    l = __float2half_rn(v - __half2float(h));
}
__device__ __forceinline__ void hilo2(float a, float b, uint32_t& h, uint32_t& l) {
    __half ha, la, hb, lb;
    hilo(a, ha, la);
    hilo(b, hb, lb);
    __half2 hh = __halves2half2(ha, hb);
    __half2 ll = __halves2half2(la, lb);
    h = *(uint32_t*)&hh;
    l = *(uint32_t*)&ll;
}

// ================= split/convert kernels =================
// weights: hi only (2-term GEMM)
__global__ void split_wt_kernel(const float* __restrict__ W,
                                __half* __restrict__ Wth, int K, int N) {
    __shared__ float t[32][33];
    int n0 = blockIdx.x * 32, k0 = blockIdx.y * 32;
    int tx = threadIdx.x, ty = threadIdx.y;
    #pragma unroll
    for (int r = 0; r < 4; r++) {
        int k = k0 + ty + r * 8;
        t[ty + r * 8][tx] = W[(size_t)k * N + n0 + tx];
    }
    __syncthreads();
    #pragma unroll
    for (int r = 0; r < 4; r++) {
        int n = n0 + ty + r * 8;
        int k = k0 + tx;
        Wth[(size_t)n * K + k] = __float2half_rn(t[tx][ty + r * 8]);
    }
}

__global__ void pack_bias_kernel(float* __restrict__ dst,
                                 const float* __restrict__ s0,
                                 const float* __restrict__ s1,
                                 const float* __restrict__ s2) {
    int i = blockIdx.x * 256 + threadIdx.x;
    int s = i / 768, r = i - s * 768;
    const float* p = (s == 0) ? s0 : (s == 1 ? s1 : s2);
    dst[i] = p[r];
}

// ================= warp-MMA fp16 GEMM (2-term: ah*bh + al*bh) ==============
#define MAT_B 10240
#define STG_BYTES (3*MAT_B)     // Ah | Al | Bh
#define GSM_TOT (2*STG_BYTES)   // 61440

__device__ __forceinline__ void ldm_x4(uint32_t addr, uint32_t& r0, uint32_t& r1,
                                       uint32_t& r2, uint32_t& r3) {
    asm volatile("ldmatrix.sync.aligned.m8n8.x4.shared.b16 {%0,%1,%2,%3}, [%4];"
        : "=r"(r0), "=r"(r1), "=r"(r2), "=r"(r3) : "r"(addr));
}
__device__ __forceinline__ void ldm_x4t(uint32_t addr, uint32_t& r0, uint32_t& r1,
                                        uint32_t& r2, uint32_t& r3) {
    asm volatile("ldmatrix.sync.aligned.m8n8.x4.trans.shared.b16 {%0,%1,%2,%3}, [%4];"
        : "=r"(r0), "=r"(r1), "=r"(r2), "=r"(r3) : "r"(addr));
}
__device__ __forceinline__ void mma_f16(float* c, const uint32_t* a, const uint32_t* b) {
    asm volatile("mma.sync.aligned.m16n8k16.row.col.f32.f16.f16.f32 "
        "{%0,%1,%2,%3}, {%4,%5,%6,%7}, {%8,%9}, {%0,%1,%2,%3};"
        : "+f"(c[0]), "+f"(c[1]), "+f"(c[2]), "+f"(c[3])
        : "r"(a[0]), "r"(a[1]), "r"(a[2]), "r"(a[3]), "r"(b[0]), "r"(b[1]));
}

// mode 0: Cf = acc+bias ; mode 1: +GELU ; mode 2: hi/lo fp16(gelu) -> Cbh/Cbl
__global__ __launch_bounds__(256, 2)
void gemm_mma_kernel(const __half* __restrict__ Ah,
                     const __half* __restrict__ Al,
                     const __half* __restrict__ Bh,
                     const float* __restrict__ bias,
                     float* __restrict__ Cf,
                     __half* __restrict__ Cbh,
                     __half* __restrict__ Cbl,
                     int Kp, int N, int mode) {
    extern __shared__ __align__(1024) char smem[];
    uint32_t sb = smem_u32(smem);
    int tid = threadIdx.x;
    int wid = tid >> 5, lane = tid & 31;
    int m0 = blockIdx.y * 128, n0 = blockIdx.x * 128;
    int warp_m = (wid & 1) * 64;
    int warp_n = (wid >> 1) * 32;
    int NC = Kp / 32;

    const __half* Agh = Ah + (size_t)m0 * Kp;
    const __half* Agl = Al + (size_t)m0 * Kp;
    const __half* Bgh = Bh + (size_t)n0 * Kp;

    float acc[4][4][4];
    #pragma unroll
    for (int i = 0; i < 4; i++)
        #pragma unroll
        for (int j = 0; j < 4; j++)
            #pragma unroll
            for (int r = 0; r < 4; r++) acc[i][j][r] = 0.f;

    auto load_tile = [&](int c, int bf) {
        uint32_t base = sb + bf * STG_BYTES;
        const __half* srcs[3] = {
            Agh + (size_t)c * 32, Agl + (size_t)c * 32, Bgh + (size_t)c * 32 };
        #pragma unroll
        for (int m = 0; m < 3; m++) {
            const __half* S = srcs[m];
            uint32_t mb = base + m * MAT_B;
            #pragma unroll
            for (int i = 0; i < 2; i++) {
                int ch = i * 256 + tid;
                int r = ch >> 2, c8 = (ch & 3) * 8;
                uint32_t d = mb + r * 80 + c8 * 2;
                const void* s = S + (size_t)r * Kp + c8;
                asm volatile("cp.async.cg.shared.global [%0], [%1], 16;" :: "r"(d), "l"(s));
            }
        }
    };

    load_tile(0, 0);
    asm volatile("cp.async.commit_group;" ::: "memory");

    int rsel = lane & 15, hsel = (lane >> 4) * 16;
    for (int c = 0; c < NC; c++) {
        int bf = c & 1;
        if (c + 1 < NC) load_tile(c + 1, bf ^ 1);
        asm volatile("cp.async.commit_group;" ::: "memory");
        asm volatile("cp.async.wait_group 1;" ::: "memory");
        __syncthreads();

        uint32_t ahb = sb + bf * STG_BYTES;
        uint32_t alb = ahb + MAT_B;
        uint32_t bhb = ahb + 2 * MAT_B;

        #pragma unroll
        for (int ks = 0; ks < 2; ks++) {
            uint32_t ah[4][4], al[4][4], bh[4][2];
            #pragma unroll
            for (int mi = 0; mi < 4; mi++) {
                uint32_t off = (warp_m + mi * 16 + rsel) * 80 + ks * 32 + hsel;
                ldm_x4(ahb + off, ah[mi][0], ah[mi][1], ah[mi][2], ah[mi][3]);
                ldm_x4(alb + off, al[mi][0], al[mi][1], al[mi][2], al[mi][3]);
            }
            #pragma unroll
            for (int np = 0; np < 2; np++) {
                uint32_t off = (warp_n + np * 16 + rsel) * 80 + ks * 32 + hsel;
                uint32_t r0, r1, r2, r3;
                ldm_x4(bhb + off, r0, r1, r2, r3);
                bh[np * 2 + 0][0] = r0; bh[np * 2 + 0][1] = r2;
                bh[np * 2 + 1][0] = r1; bh[np * 2 + 1][1] = r3;
            }
            #pragma unroll
            for (int mi = 0; mi < 4; mi++)
                #pragma unroll
                for (int nj = 0; nj < 4; nj++)
                    mma_f16(acc[mi][nj], ah[mi], bh[nj]);
            #pragma unroll
            for (int mi = 0; mi < 4; mi++)
                #pragma unroll
                for (int nj = 0; nj < 4; nj++)
                    mma_f16(acc[mi][nj], al[mi], bh[nj]);
        }
        __syncthreads();
    }

    int g = lane >> 2, t = lane & 3;
    #pragma unroll
    for (int mi = 0; mi < 4; mi++) {
        int row0 = m0 + warp_m + mi * 16 + g;
        #pragma unroll
        for (int nj = 0; nj < 4; nj++) {
            int col = n0 + warp_n + nj * 8 + t * 2;
            float bx = bias[col], by = bias[col + 1];
            float v0 = acc[mi][nj][0] + bx, v1 = acc[mi][nj][1] + by;
            float v2 = acc[mi][nj][2] + bx, v3 = acc[mi][nj][3] + by;
            if (mode >= 1) { v0 = gelu_tanh(v0); v1 = gelu_tanh(v1); v2 = gelu_tanh(v2); v3 = gelu_tanh(v3); }
            if (mode == 2) {
                #pragma unroll
                for (int rr = 0; rr < 2; rr++) {
                    int row = row0 + rr * 8;
                    float a0 = rr ? v2 : v0, a1 = rr ? v3 : v1;
                    uint32_t h2, l2;
                    hilo2(a0, a1, h2, l2);
                    size_t ro = (size_t)row * N + col;
                    *(uint32_t*)&Cbh[ro] = h2;
                    *(uint32_t*)&Cbl[ro] = l2;
                }
            } else {
                *(float2*)&Cf[(size_t)row0 * N + col]       = make_float2(v0, v1);
                *(float2*)&Cf[(size_t)(row0 + 8) * N + col] = make_float2(v2, v3);
            }
        }
    }
}

// ================= fused flash band attention (fp16 hi/lo, 3-term) =========
#define FB_ROWB 144
#define FB_QH 0
#define FB_QL (FB_QH + 64*FB_ROWB)
#define FB_KH (FB_QL + 64*FB_ROWB)
#define FB_KL (FB_KH + 64*FB_ROWB)
#define FB_VH (FB_KL + 64*FB_ROWB)
#define FB_VL (FB_VH + 64*FB_ROWB)
#define FB_SG (FB_VL + 64*FB_ROWB)
#define FB_V0 (FB_SG + 256)
#define FB_CM (FB_V0 + 256)
#define FB_TOT (FB_CM + 256 + 64)

__global__ __launch_bounds__(128)
void flash_band_kernel(const float* __restrict__ qkv,
                       const int* __restrict__ am,
                       __half* __restrict__ outh,
                       __half* __restrict__ outl) {
    extern __shared__ char fsmc[];
    float* fp = (float*)fsmc;
    uint32_t sb = smem_u32(fsmc);
    int z = blockIdx.y;
    int n = z % CNB;
    int h = (z / CNB) % CH;
    int b = z / (CNB * CH);
    int qt = blockIdx.x;
    int tid = threadIdx.x;
    int w = tid >> 5, lane = tid & 31;
    int rsel = lane & 15, hsel = (lane >> 4) * 16;
    int t2 = (lane & 3) * 2;

    int base_s    = n * CW + qt * 64;
    int base_kpos = n * CW - CW;
    int am0 = am[b * CS];

    #pragma unroll
    for (int i = 0; i < 8; i++) {
        int sid = i * 128 + tid;
        int r = sid >> 4, c4 = (sid & 15) * 4;
        float4 vq = *(const float4*)&qkv[((size_t)(b * CS + base_s + r)) * QKV_S + h * 64 + c4];
        vq.x *= CSCALE; vq.y *= CSCALE; vq.z *= CSCALE; vq.w *= CSCALE;
        uint32_t h0, l0, h1, l1;
        hilo2(vq.x, vq.y, h0, l0);
        hilo2(vq.z, vq.w, h1, l1);
        *(uint2*)(fsmc + FB_QH + r * FB_ROWB + c4 * 2) = make_uint2(h0, h1);
        *(uint2*)(fsmc + FB_QL + r * FB_ROWB + c4 * 2) = make_uint2(l0, l1);
    }
    if (tid < 64)
        fp[FB_V0 / 4 + tid] = qkv[((size_t)(b * CS)) * QKV_S + 1536 + h * 64 + tid];
    __syncthreads();

    {
        int row = tid >> 1, half = tid & 1;
        const __half* qh = (const __half*)(fsmc + FB_QH + row * FB_ROWB);
        const __half* ql = (const __half*)(fsmc + FB_QL + row * FB_ROWB);
        const float* k0p = &qkv[((size_t)(b * CS)) * QKV_S + 768 + h * 64];
        float sgv = 0.f;
        #pragma unroll
        for (int d = 0; d < 32; d++) {
            int dd = half * 32 + d;
            sgv += (__half2float(qh[dd]) + __half2float(ql[dd])) * k0p[dd];
        }
        sgv += __shfl_xor_sync(0xffffffffu, sgv, 1);
        if (half == 0) fp[FB_SG / 4 + row] = sgv;
    }

    uint32_t qh[4][4], ql[4][4];
    #pragma unroll
    for (int dk = 0; dk < 4; dk++) {
        uint32_t off = (16 * w + rsel) * FB_ROWB + dk * 32 + hsel;
        ldm_x4(sb + FB_QH + off, qh[dk][0], qh[dk][1], qh[dk][2], qh[dk][3]);
        ldm_x4(sb + FB_QL + off, ql[dk][0], ql[dk][1], ql[dk][2], ql[dk][3]);
    }

    float o[8][4];
    #pragma unroll
    for (int nn = 0; nn < 8; nn++)
        #pragma unroll
        for (int e = 0; e < 4; e++) o[nn][e] = 0.f;
    float mst0 = -1e30f, mst1 = -1e30f, lst0 = 0.f, lst1 = 0.f;

    int qi0 = qt * 64 + 16 * w + (lane >> 2);
    int qi1 = qi0 + 8;

    for (int kc = 0; kc < 12; kc++) {
        __syncthreads();
        #pragma unroll
        for (int i = 0; i < 8; i++) {
            int sid = i * 128 + tid;
            int r = sid >> 4, c4 = (sid & 15) * 4;
            int kpos = base_kpos + kc * 64 + r;
            float4 vk = make_float4(0.f, 0.f, 0.f, 0.f);
            float4 vv = make_float4(0.f, 0.f, 0.f, 0.f);
            if (kpos >= 0 && kpos < CS) {
                size_t rb = ((size_t)(b * CS + kpos)) * QKV_S + h * 64 + c4;
                vk = *(const float4*)&qkv[rb + 768];
                vv = *(const float4*)&qkv[rb + 1536];
            }
            uint32_t h0, l0, h1, l1;
            hilo2(vk.x, vk.y, h0, l0);
            hilo2(vk.z, vk.w, h1, l1);
            *(uint2*)(fsmc + FB_KH + r * FB_ROWB + c4 * 2) = make_uint2(h0, h1);
            *(uint2*)(fsmc + FB_KL + r * FB_ROWB + c4 * 2) = make_uint2(l0, l1);
            hilo2(vv.x, vv.y, h0, l0);
            hilo2(vv.z, vv.w, h1, l1);
            *(uint2*)(fsmc + FB_VH + r * FB_ROWB + c4 * 2) = make_uint2(h0, h1);
            *(uint2*)(fsmc + FB_VL + r * FB_ROWB + c4 * 2) = make_uint2(l0, l1);
        }
        if (tid < 64) {
            int kpos = base_kpos + kc * 64 + tid;
            bool ok = (kpos >= 0) && (kpos < CS) && (kpos != 0);
            if (ok) ok = am[b * CS + kpos] > 0;
            fp[FB_CM / 4 + tid] = ok ? 1.f : 0.f;
        }
        __syncthreads();

        float s[8][4];
        #pragma unroll
        for (int nn = 0; nn < 8; nn++)
            #pragma unroll
            for (int e = 0; e < 4; e++) s[nn][e] = 0.f;
        #pragma unroll
        for (int dk = 0; dk < 4; dk++) {
            #pragma unroll
            for (int np = 0; np < 4; np++) {
                uint32_t off = (np * 16 + rsel) * FB_ROWB + dk * 32 + hsel;
                uint32_t r0, r1, r2, r3;
                uint32_t kha[2], khb[2], kla[2], klb[2];
                ldm_x4(sb + FB_KH + off, r0, r1, r2, r3);
                kha[0] = r0; kha[1] = r2; khb[0] = r1; khb[1] = r3;
                ldm_x4(sb + FB_KL + off, r0, r1, r2, r3);
                kla[0] = r0; kla[1] = r2; klb[0] = r1; klb[1] = r3;
                mma_f16(s[2 * np],     qh[dk], kha);
                mma_f16(s[2 * np + 1], qh[dk], khb);
                mma_f16(s[2 * np],     ql[dk], kha);
                mma_f16(s[2 * np + 1], ql[dk], khb);
                mma_f16(s[2 * np],     qh[dk], kla);
                mma_f16(s[2 * np + 1], qh[dk], klb);
            }
        }

        #pragma unroll
        for (int nn = 0; nn < 8; nn++) {
            #pragma unroll
            for (int e = 0; e < 2; e++) {
                int kj = kc * 64 + 8 * nn + t2 + e;
                float cm = fp[FB_CM / 4 + 8 * nn + t2 + e];
                bool b0 = (kj >= qi0) && (kj <= qi0 + 2 * CW) && (cm > 0.f);
                bool b1 = (kj >= qi1) && (kj <= qi1 + 2 * CW) && (cm > 0.f);
                if (!b0) s[nn][e] = CNEG;
                if (!b1) s[nn][2 + e] = CNEG;
            }
        }

        float mx0 = -1e30f, mx1 = -1e30f;
        #pragma unroll
        for (int nn = 0; nn < 8; nn++) {
            mx0 = fmaxf(mx0, fmaxf(s[nn][0], s[nn][1]));
            mx1 = fmaxf(mx1, fmaxf(s[nn][2], s[nn][3]));
        }
        mx0 = fmaxf(mx0, __shfl_xor_sync(0xffffffffu, mx0, 1));
        mx0 = fmaxf(mx0, __shfl_xor_sync(0xffffffffu, mx0, 2));
        mx1 = fmaxf(mx1, __shfl_xor_sync(0xffffffffu, mx1, 1));
        mx1 = fmaxf(mx1, __shfl_xor_sync(0xffffffffu, mx1, 2));
        float nm0 = fmaxf(mst0, mx0), nm1 = fmaxf(mst1, mx1);
        float a0 = __expf(mst0 - nm0), a1 = __expf(mst1 - nm1);
        mst0 = nm0; mst1 = nm1;
        float rs0 = 0.f, rs1 = 0.f;
        #pragma unroll
        for (int nn = 0; nn < 8; nn++) {
            s[nn][0] = __expf(s[nn][0] - nm0); rs0 += s[nn][0];
            s[nn][1] = __expf(s[nn][1] - nm0); rs0 += s[nn][1];
            s[nn][2] = __expf(s[nn][2] - nm1); rs1 += s[nn][2];
            s[nn][3] = __expf(s[nn][3] - nm1); rs1 += s[nn][3];
        }
        rs0 += __shfl_xor_sync(0xffffffffu, rs0, 1);
        rs0 += __shfl_xor_sync(0xffffffffu, rs0, 2);
        rs1 += __shfl_xor_sync(0xffffffffu, rs1, 1);
        rs1 += __shfl_xor_sync(0xffffffffu, rs1, 2);
        lst0 = lst0 * a0 + rs0;
        lst1 = lst1 * a1 + rs1;
        #pragma unroll
        for (int nn = 0; nn < 8; nn++) {
            o[nn][0] *= a0; o[nn][1] *= a0;
            o[nn][2] *= a1; o[nn][3] *= a1;
        }

        uint32_t ph[4][4], pl[4][4];
        #pragma unroll
        for (int qf = 0; qf < 4; qf++) {
            hilo2(s[2 * qf][0],     s[2 * qf][1],     ph[qf][0], pl[qf][0]);
            hilo2(s[2 * qf][2],     s[2 * qf][3],     ph[qf][1], pl[qf][1]);
            hilo2(s[2 * qf + 1][0], s[2 * qf + 1][1], ph[qf][2], pl[qf][2]);
            hilo2(s[2 * qf + 1][2], s[2 * qf + 1][3], ph[qf][3], pl[qf][3]);
        }

        #pragma unroll
        for (int qf = 0; qf < 4; qf++) {
            #pragma unroll
            for (int dp = 0; dp < 4; dp++) {
                uint32_t off = (qf * 16 + rsel) * FB_ROWB + dp * 32 + hsel;
                uint32_t r0, r1, r2, r3;
                uint32_t vha[2], vhb[2], vla[2], vlb[2];
                ldm_x4t(sb + FB_VH + off, r0, r1, r2, r3);
                vha[0] = r0; vha[1] = r1; vhb[0] = r2; vhb[1] = r3;
                ldm_x4t(sb + FB_VL + off, r0, r1, r2, r3);
                vla[0] = r0; vla[1] = r1; vlb[0] = r2; vlb[1] = r3;
                mma_f16(o[2 * dp],     ph[qf], vha);
                mma_f16(o[2 * dp + 1], ph[qf], vhb);
                mma_f16(o[2 * dp],     pl[qf], vha);
                mma_f16(o[2 * dp + 1], pl[qf], vhb);
                mma_f16(o[2 * dp],     ph[qf], vla);
                mma_f16(o[2 * dp + 1], ph[qf], vlb);
            }
        }
    }

    #pragma unroll
    for (int rr = 0; rr < 2; rr++) {
        int row = 16 * w + (lane >> 2) + 8 * rr;
        float mst = rr ? mst1 : mst0;
        float lst = rr ? lst1 : lst0;
        float sg = fp[FB_SG / 4 + row];
        if (am0 <= 0) sg = CNEG;
        float nm = fmaxf(mst, sg);
        float alpha = __expf(mst - nm);
        float pg = __expf(sg - nm);
        float l = lst * alpha + pg;
        float inv = 1.0f / l;
        int srow = base_s + row;
        size_t ob = ((size_t)(b * CS + srow)) * CDM + h * 64;
        #pragma unroll
        for (int nn = 0; nn < 8; nn++) {
            int d = 8 * nn + t2;
            float v0 = (o[nn][2 * rr + 0] * alpha + pg * fp[FB_V0 / 4 + d])     * inv;
            float v1 = (o[nn][2 * rr + 1] * alpha + pg * fp[FB_V0 / 4 + d + 1]) * inv;
            uint32_t h2, l2;
            hilo2(v0, v1, h2, l2);
            *(uint32_t*)&outh[ob + d] = h2;
            *(uint32_t*)&outl[ob + d] = l2;
        }
    }
}

// ================= small kernels =================
__device__ __forceinline__ float block_reduce_sum256(float v, float* red) {
    int tid = threadIdx.x;
    red[tid] = v; __syncthreads();
    #pragma unroll
    for (int o = 128; o > 0; o >>= 1) {
        if (tid < o) red[tid] += red[tid + o];
        __syncthreads();
    }
    float r = red[0]; __syncthreads();
    return r;
}

__global__ void embed_ln_kernel(const int* __restrict__ ids,
                                const float* __restrict__ we,
                                const float* __restrict__ pe,
                                const float* __restrict__ gam,
                                const float* __restrict__ bet,
                                float* __restrict__ x,
                                __half* __restrict__ xh,
                                __half* __restrict__ xl) {
    __shared__ float red[256];
    int row = blockIdx.x;
    int s = row % CS;
    int id = ids[row];
    int tid = threadIdx.x;
    const float* wp = we + (size_t)id * CDM;
    const float* pp = pe + (size_t)s * CDM;
    float e[3];
    float sm = 0.f;
    #pragma unroll
    for (int i = 0; i < 3; i++) { int d = tid + i * 256; e[i] = wp[d] + pp[d]; sm += e[i]; }
    float mean = block_reduce_sum256(sm, red) * (1.0f / CDM);
    float vs = 0.f;
    #pragma unroll
    for (int i = 0; i < 3; i++) { float t = e[i] - mean; vs += t * t; }
    float var = block_reduce_sum256(vs, red) * (1.0f / CDM);
    float inv = rsqrtf(var + 1e-5f);
    float* xr = x + (size_t)row * CDM;
    size_t ro = (size_t)row * CDM;
    #pragma unroll
    for (int i = 0; i < 3; i++) {
        int d = tid + i * 256;
        float val = (e[i] - mean) * inv * gam[d] + bet[d];
        xr[d] = val;
        __half h, l;
        hilo(val, h, l);
        xh[ro + d] = h; xl[ro + d] = l;
    }
}

__global__ void add_ln_kernel(float* __restrict__ x,
                              const float* __restrict__ y,
                              const float* __restrict__ gam,
                              const float* __restrict__ bet,
                              __half* __restrict__ xh,
                              __half* __restrict__ xl) {
    __shared__ float red[256];
    int row = blockIdx.x;
    int tid = threadIdx.x;
    float* xr = x + (size_t)row * CDM;
    const float* yr = y + (size_t)row * CDM;
    float e[3];
    float sm = 0.f;
    #pragma unroll
    for (int i = 0; i < 3; i++) { int d = tid + i * 256; e[i] = xr[d] + yr[d]; sm += e[i]; }
    float mean = block_reduce_sum256(sm, red) * (1.0f / CDM);
    float vs = 0.f;
    #pragma unroll
    for (int i = 0; i < 3; i++) { float t = e[i] - mean; vs += t * t; }
    float var = block_reduce_sum256(vs, red) * (1.0f / CDM);
    float inv = rsqrtf(var + 1e-5f);
    size_t ro = (size_t)row * CDM;
    #pragma unroll
    for (int i = 0; i < 3; i++) {
        int d = tid + i * 256;
        float val = (e[i] - mean) * inv * gam[d] + bet[d];
        xr[d] = val;
        __half h, l;
        hilo(val, h, l);
        xh[ro + d] = h; xl[ro + d] = l;
    }
}

// qg = (x[:,0] @ Wqg + bqg) * scale   — 4-way k-split, grid (12, CB)
__global__ void qg_kernel(const float* __restrict__ x,
                          const float* __restrict__ Wqg,
                          const float* __restrict__ bqg,
                          float* __restrict__ qg) {
    __shared__ float part[4][64];
    int n0 = blockIdx.x * 64;
    int b = blockIdx.y;
    int tid = threadIdx.x;
    int nl = tid & 63, kq = tid >> 6;     // 4 k-slices of 192
    const float* xr = x + (size_t)(b * CS) * CDM;
    float acc = 0.f;
    for (int kk = kq * 192; kk < (kq + 1) * 192; kk++)
        acc += xr[kk] * Wqg[(size_t)kk * CDM + n0 + nl];
    part[kq][nl] = acc;
    __syncthreads();
    if (kq == 0) {
        float t = part[0][nl] + part[1][nl] + part[2][nl] + part[3][nl];
        qg[b * CDM + n0 + nl] = (t + bqg[n0 + nl]) * CSCALE;
    }
}

__global__ void tk_kernel(const float* __restrict__ Wkg,
                          const float* __restrict__ qg,
                          float* __restrict__ t) {
    int k = blockIdx.x * 128 + threadIdx.x;
    int h = blockIdx.y, b = blockIdx.z;
    const float* W = Wkg + (size_t)k * CDM + h * 64;
    const float* q = qg + b * CDM + h * 64;
    float acc = 0.f;
    #pragma unroll
    for (int d = 0; d < 64; d++) acc += W[d] * q[d];
    t[(b * CH + h) * CDM + k] = acc;
}

__global__ __launch_bounds__(256)
void sgl_kernel(const float* __restrict__ x,
                const float* __restrict__ t,
                const int* __restrict__ am,
                float* __restrict__ p) {
    __shared__ float ts[CH][CDM];
    int b = blockIdx.y;
    int tid = threadIdx.x;
    for (int i = tid; i < CH * CDM; i += 256)
        ((float*)ts)[i] = t[b * CH * CDM + i];
    __syncthreads();
    int w = tid >> 5, lane = tid & 31;
    int s = blockIdx.x * 8 + w;
    const float* xr = x + ((size_t)(b * CS + s)) * CDM;
    float acc[CH];
    #pragma unroll
    for (int h = 0; h < CH; h++) acc[h] = 0.f;
    for (int k = lane; k < CDM; k += 32) {
        float xv = xr[k];
        #pragma unroll
        for (int h = 0; h < CH; h++) acc[h] += xv * ts[h][k];
    }
    #pragma unroll
    for (int h = 0; h < CH; h++) {
        #pragma unroll
        for (int o = 16; o > 0; o >>= 1)
            acc[h] += __shfl_xor_sync(0xffffffffu, acc[h], o);
    }
    bool okm = am[b * CS + s] > 0;
    if (lane < CH)
        p[((size_t)(b * CH + lane)) * CS + s] = okm ? acc[lane] : CNEG;
}

__global__ void softmax_p_kernel(float* __restrict__ p) {
    __shared__ float red[256];
    int h = blockIdx.x, b = blockIdx.y;
    int tid = threadIdx.x;
    float* pr = p + ((size_t)(b * CH + h)) * CS;
    float mx = -1e30f;
    for (int s = tid; s < CS; s += 256) mx = fmaxf(mx, pr[s]);
    red[tid] = mx; __syncthreads();
    #pragma unroll
    for (int o = 128; o > 0; o >>= 1) {
        if (tid < o) red[tid] = fmaxf(red[tid], red[tid + o]);
        __syncthreads();
    }
    mx = red[0]; __syncthreads();
    float sm = 0.f;
    for (int s = tid; s < CS; s += 256) {
        float e = __expf(pr[s] - mx);
        pr[s] = e; sm += e;
    }
    float tot = block_reduce_sum256(sm, red);
    float inv = 1.0f / tot;
    for (int s = tid; s < CS; s += 256) pr[s] *= inv;
}

// stage 1: partial u over one 128-row s-chunk
__global__ __launch_bounds__(256)
void u_part_kernel(const float* __restrict__ p,
                   const float* __restrict__ x,
                   float* __restrict__ up) {
    __shared__ float xs[128][64];
    __shared__ float ps[CH][128];
    int kc = blockIdx.x, sc = blockIdx.y, b = blockIdx.z;
    int k0 = kc * 64;
    int tid = threadIdx.x;
    int kl = tid & 63, h0 = tid >> 6;
    #pragma unroll
    for (int i = 0; i < 32; i++) {
        int idx = i * 256 + tid;
        int r = idx >> 6, c = idx & 63;
        xs[r][c] = x[((size_t)(b * CS + sc * 128 + r)) * CDM + k0 + c];
    }
    #pragma unroll
    for (int i = 0; i < 6; i++) {
        int idx = i * 256 + tid;
        int hh = idx >> 7, ss = idx & 127;
        ps[hh][ss] = p[((size_t)(b * CH + hh)) * CS + sc * 128 + ss];
    }
    __syncthreads();
    float acc[3] = {0.f, 0.f, 0.f};
    for (int s = 0; s < 128; s++) {
        float xv = xs[s][kl];
        acc[0] += ps[h0][s] * xv;
        acc[1] += ps[h0 + 4][s] * xv;
        acc[2] += ps[h0 + 8][s] * xv;
    }
    size_t base = ((size_t)(sc * CB + b)) * CH * CDM;
    up[base + (h0)     * CDM + k0 + kl] = acc[0];
    up[base + (h0 + 4) * CDM + k0 + kl] = acc[1];
    up[base + (h0 + 8) * CDM + k0 + kl] = acc[2];
}

// stage 2: reduce 32 partials
__global__ void u_reduce_kernel(const float* __restrict__ up,
                                float* __restrict__ u) {
    int i = blockIdx.x * 256 + threadIdx.x;   // i over CH*CDM
    int b = blockIdx.y;
    float acc = 0.f;
    #pragma unroll
    for (int sc = 0; sc < 32; sc++)
        acc += up[((size_t)(sc * CB + b)) * CH * CDM + i];
    u[b * CH * CDM + i] = acc;
}

// og — 4-way k-split, grid (CH, CB), block 256
__global__ void og_kernel(const float* __restrict__ u,
                          const float* __restrict__ Wvg,
                          const float* __restrict__ bvg,
                          __half* __restrict__ outh,
                          __half* __restrict__ outl) {
    __shared__ float part[4][64];
    int h = blockIdx.x, b = blockIdx.y;
    int tid = threadIdx.x;
    int d = tid & 63, kq = tid >> 6;
    const float* upr = u + (b * CH + h) * CDM;
    float acc = 0.f;
    for (int k = kq * 192; k < (kq + 1) * 192; k++)
        acc += upr[k] * Wvg[(size_t)k * CDM + h * 64 + d];
    part[kq][d] = acc;
    __syncthreads();
    if (kq == 0) {
        float t = part[0][d] + part[1][d] + part[2][d] + part[3][d] + bvg[h * 64 + d];
        __half hh, ll;
        hilo(t, hh, ll);
        size_t ob = ((size_t)(b * CS)) * CDM + h * 64 + d;
        outh[ob] = hh;
        outl[ob] = ll;
    }
}

__global__ void cls_kernel(const float* __restrict__ x,
                           const float* __restrict__ Wc,
                           const float* __restrict__ bc,
                           float* __restrict__ out) {
    __shared__ float red[256];
    int b = blockIdx.x >> 1, c = blockIdx.x & 1;
    int tid = threadIdx.x;
    const float* xr = x + (size_t)(b * CS) * CDM;
    float acc = 0.f;
    for (int d = tid; d < CDM; d += 256) acc += xr[d] * Wc[d * 2 + c];
    float tot = block_reduce_sum256(acc, red);
    if (tid == 0) out[b * 2 + c] = tot + bc[c];
}

// ================= launch =================
extern "C" void kernel_launch(void* const* d_in, const int* in_sizes, int n_in,
                              void* d_out, int out_size) {
    const int*   ids  = (const int*)d_in[0];
    const int*   am   = (const int*)d_in[1];
    const float* we   = (const float*)d_in[2];
    const float* pe   = (const float*)d_in[3];
    const float* lnes = (const float*)d_in[4];
    const float* lneb = (const float*)d_in[5];
    const float* Wq   = (const float*)d_in[6];
    const float* bq   = (const float*)d_in[7];
    const float* Wk   = (const float*)d_in[8];
    const float* bk   = (const float*)d_in[9];
    const float* Wv   = (const float*)d_in[10];
    const float* bv   = (const float*)d_in[11];
    const float* Wqg  = (const float*)d_in[12];
    const float* bqg  = (const float*)d_in[13];
    const float* Wkg  = (const float*)d_in[14];
    const float* bkg  = (const float*)d_in[15];
    const float* Wvg  = (const float*)d_in[16];
    const float* bvg  = (const float*)d_in[17];
    const float* Wo   = (const float*)d_in[18];
    const float* bo   = (const float*)d_in[19];
    const float* ln1s = (const float*)d_in[20];
    const float* ln1b = (const float*)d_in[21];
    const float* W1   = (const float*)d_in[22];
    const float* b1   = (const float*)d_in[23];
    const float* W2   = (const float*)d_in[24];
    const float* b2   = (const float*)d_in[25];
    const float* ln2s = (const float*)d_in[26];
    const float* ln2b = (const float*)d_in[27];
    const float* Wcls = (const float*)d_in[28];
    const float* bcls = (const float*)d_in[29];
    float* out = (float*)d_out;

    float *xp, *yp, *qkvp, *qgp, *biasp, *tp, *pp, *up, *upp;
    __half *xhp, *xlp, *ahp, *alp, *hhp, *hlp, *whp;
    cudaGetSymbolAddress((void**)&xp,   g_x);
    cudaGetSymbolAddress((void**)&yp,   g_y);
    cudaGetSymbolAddress((void**)&qkvp, g_qkv);
    cudaGetSymbolAddress((void**)&qgp,  g_qg);
    cudaGetSymbolAddress((void**)&biasp, g_bias);
    cudaGetSymbolAddress((void**)&tp,   g_t);
    cudaGetSymbolAddress((void**)&pp,   g_p);
    cudaGetSymbolAddress((void**)&up,   g_u);
    cudaGetSymbolAddress((void**)&upp,  g_up);
    cudaGetSymbolAddress((void**)&xhp,  g_xbh);
    cudaGetSymbolAddress((void**)&xlp,  g_xbl);
    cudaGetSymbolAddress((void**)&ahp,  g_abh);
    cudaGetSymbolAddress((void**)&alp,  g_abl);
    cudaGetSymbolAddress((void**)&hhp,  g_hbh);
    cudaGetSymbolAddress((void**)&hlp,  g_hbl);
    cudaGetSymbolAddress((void**)&whp,  g_wbh);

    cudaFuncSetAttribute(gemm_mma_kernel, cudaFuncAttributeMaxDynamicSharedMemorySize, GSM_TOT);
    cudaFuncSetAttribute(flash_band_kernel, cudaFuncAttributeMaxDynamicSharedMemorySize, FB_TOT);

    embed_ln_kernel<<<MROWS, 256>>>(ids, we, pe, lnes, lneb, xp, xhp, xlp);

    dim3 wt_dm(CDM / 32, CDM / 32);
    dim3 wt_b(32, 8);
    size_t wseg = (size_t)CDM * CDM;

    for (int l = 0; l < CL; l++) {
        size_t woff = (size_t)l * CDM * CDM;
        size_t boff = (size_t)l * CDM;
        size_t w1off = (size_t)l * CDM * CDFF;
        size_t b1off = (size_t)l * CDFF;
        size_t w2off = (size_t)l * CDFF * CDM;

        // --- fused QKV GEMM (2-term) ---
        split_wt_kernel<<<wt_dm, wt_b>>>(Wq + woff, whp,            CDM, CDM);
        split_wt_kernel<<<wt_dm, wt_b>>>(Wk + woff, whp + wseg,     CDM, CDM);
        split_wt_kernel<<<wt_dm, wt_b>>>(Wv + woff, whp + 2 * wseg, CDM, CDM);
        pack_bias_kernel<<<9, 256>>>(biasp, bq + boff, bk + boff, bv + boff);
        gemm_mma_kernel<<<dim3(QKV_S / 128, MROWS / 128), 256, GSM_TOT>>>(
            xhp, xlp, whp, biasp, qkvp, nullptr, nullptr, CDM, QKV_S, 0);

        flash_band_kernel<<<dim3(4, CB * CH * CNB), 128, FB_TOT>>>(qkvp, am, ahp, alp);

        // --- factored global attention (fp32, no GEMM) ---
        qg_kernel<<<dim3(CDM / 64, CB), 256>>>(xp, Wqg + woff, bqg + boff, qgp);
        tk_kernel<<<dim3(CDM / 128, CH, CB), 128>>>(Wkg + woff, qgp, tp);
        sgl_kernel<<<dim3(CS / 8, CB), 256>>>(xp, tp, am, pp);
        softmax_p_kernel<<<dim3(CH, CB), 256>>>(pp);
        u_part_kernel<<<dim3(CDM / 64, 32, CB), 256>>>(pp, xp, upp);
        u_reduce_kernel<<<dim3(CH * CDM / 256, CB), 256>>>(upp, up);
        og_kernel<<<dim3(CH, CB), 256>>>(up, Wvg + woff, bvg + boff, ahp, alp);

        // --- Wo projection (2-term) + LN1 ---
        split_wt_kernel<<<wt_dm, wt_b>>>(Wo + woff, whp, CDM, CDM);
        gemm_mma_kernel<<<dim3(CDM / 128, MROWS / 128), 256, GSM_TOT>>>(
            ahp, alp, whp, bo + boff, yp, nullptr, nullptr, CDM, CDM, 0);
        add_ln_kernel<<<MROWS, 256>>>(xp, yp, ln1s + boff, ln1b + boff, xhp, xlp);

        // --- FFN (2-term) ---
        split_wt_kernel<<<dim3(CDFF / 32, CDM / 32), wt_b>>>(W1 + w1off, whp, CDM, CDFF);
        gemm_mma_kernel<<<dim3(CDFF / 128, MROWS / 128), 256, GSM_TOT>>>(
            xhp, xlp, whp, b1 + b1off, nullptr, hhp, hlp, CDM, CDFF, 2);

        split_wt_kernel<<<dim3(CDM / 32, CDFF / 32), wt_b>>>(W2 + w2off, whp, CDFF, CDM);
        gemm_mma_kernel<<<dim3(CDM / 128, MROWS / 128), 256, GSM_TOT>>>(
            hhp, hlp, whp, b2 + boff, yp, nullptr, nullptr, CDFF, CDM, 0);
        add_ln_kernel<<<MROWS, 256>>>(xp, yp, ln2s + boff, ln2b + boff, xhp, xlp);
    }

    cls_kernel<<<4, 256>>>(xp, Wcls, bcls, out);
}

// round 14
// speedup vs baseline: 1.4067x; 1.4067x over previous
#include <cuda_runtime.h>
#include <cuda_fp16.h>
#include <math.h>
#include <stdint.h>

// ---------------- problem constants ----------------
#define CB   2
#define CS   4096
#define CH   12
#define CD   64
#define CW   256
#define CDM  768
#define CDFF 3072
#define CNB  16
#define CL   2
#define CNEG (-1000000000.0f)
#define CSCALE 0.125f

#define MROWS (CB*CS)    // 8192
#define QKV_S 2304

// ---------------- scratch ----------------
__device__ float g_x   [MROWS*CDM];
__device__ float g_y   [MROWS*CDM];
__device__ float g_qkv [(size_t)MROWS*QKV_S];
__device__ float g_qg  [CB*CDM];
__device__ float g_bias[QKV_S];
__device__ float g_t   [CB*CH*CDM];
__device__ float g_p   [(size_t)CB*CH*CS];
__device__ float g_u   [CB*CH*CDM];
__device__ float g_up  [(size_t)32*CB*CH*CDM];
// hi/lo fp16 operand buffers
__device__ __half g_xbh[(size_t)MROWS*CDM];
__device__ __half g_xbl[(size_t)MROWS*CDM];
__device__ __half g_abh[(size_t)MROWS*CDM];
__device__ __half g_abl[(size_t)MROWS*CDM];
__device__ __half g_hbh[(size_t)MROWS*CDFF];
__device__ __half g_hbl[(size_t)MROWS*CDFF];
__device__ __half g_wbh[(size_t)CDFF*CDM];
__device__ __half g_wbl[(size_t)CDFF*CDM];

// ---------------- helpers ----------------
__device__ __forceinline__ float gelu_tanh(float x) {
    float x3 = x * x * x;
    return 0.5f * x * (1.0f + tanhf(0.7978845608028654f * (x + 0.044715f * x3)));
}
__device__ __forceinline__ uint32_t smem_u32(const void* p) {
    uint32_t a;
    asm("{ .reg .u64 t; cvta.to.shared.u64 t, %1; cvt.u32.u64 %0, t; }" : "=r"(a) : "l"(p));
    return a;
}
__device__ __forceinline__ void hilo(float v, __half& h, __half& l) {
    h = __float2half_rn(v);
    l = __float2half_rn(v - __half2float(h));
}
__device__ __forceinline__ void hilo2(float a, float b, uint32_t& h, uint32_t& l) {
    __half ha, la, hb, lb;
    hilo(a, ha, la);
    hilo(b, hb, lb);
    __half2 hh = __halves2half2(ha, hb);
    __half2 ll = __halves2half2(la, lb);
    h = *(uint32_t*)&hh;
    l = *(uint32_t*)&ll;
}

// ================= split/convert kernels =================
__global__ void split_wt_kernel(const float* __restrict__ W,
                                __half* __restrict__ Wth,
                                __half* __restrict__ Wtl, int K, int N) {
    __shared__ float t[32][33];
    int n0 = blockIdx.x * 32, k0 = blockIdx.y * 32;
    int tx = threadIdx.x, ty = threadIdx.y;
    #pragma unroll
    for (int r = 0; r < 4; r++) {
        int k = k0 + ty + r * 8;
        t[ty + r * 8][tx] = W[(size_t)k * N + n0 + tx];
    }
    __syncthreads();
    #pragma unroll
    for (int r = 0; r < 4; r++) {
        int n = n0 + ty + r * 8;
        int k = k0 + tx;
        __half h, l;
        hilo(t[tx][ty + r * 8], h, l);
        size_t ro = (size_t)n * K + k;
        Wth[ro] = h;
        Wtl[ro] = l;
    }
}

// hi-only variant for 2-term weights (FFN)
__global__ void split_wt_hi_kernel(const float* __restrict__ W,
                                   __half* __restrict__ Wth, int K, int N) {
    __shared__ float t[32][33];
    int n0 = blockIdx.x * 32, k0 = blockIdx.y * 32;
    int tx = threadIdx.x, ty = threadIdx.y;
    #pragma unroll
    for (int r = 0; r < 4; r++) {
        int k = k0 + ty + r * 8;
        t[ty + r * 8][tx] = W[(size_t)k * N + n0 + tx];
    }
    __syncthreads();
    #pragma unroll
    for (int r = 0; r < 4; r++) {
        int n = n0 + ty + r * 8;
        int k = k0 + tx;
        Wth[(size_t)n * K + k] = __float2half_rn(t[tx][ty + r * 8]);
    }
}

__global__ void pack_bias_kernel(float* __restrict__ dst,
                                 const float* __restrict__ s0,
                                 const float* __restrict__ s1,
                                 const float* __restrict__ s2) {
    int i = blockIdx.x * 256 + threadIdx.x;
    int s = i / 768, r = i - s * 768;
    const float* p = (s == 0) ? s0 : (s == 1 ? s1 : s2);
    dst[i] = p[r];
}

// ================= warp-MMA fp16 GEMM (hi/lo fragment reuse) =================
// R12 layout: 4-matrix stage (Ah|Al|Bh|Bl), 2 stages, 81920B -> 2 CTAs/SM.
// TERMS=3: ah*bh + al*bh + ah*bl. TERMS=2: ah*bh + al*bh (Bl load skipped).
#define MAT_B 10240
#define STG_BYTES (4*MAT_B)
#define GSM_TOT (2*STG_BYTES)   // 81920

__device__ __forceinline__ void ldm_x4(uint32_t addr, uint32_t& r0, uint32_t& r1,
                                       uint32_t& r2, uint32_t& r3) {
    asm volatile("ldmatrix.sync.aligned.m8n8.x4.shared.b16 {%0,%1,%2,%3}, [%4];"
        : "=r"(r0), "=r"(r1), "=r"(r2), "=r"(r3) : "r"(addr));
}
__device__ __forceinline__ void ldm_x4t(uint32_t addr, uint32_t& r0, uint32_t& r1,
                                        uint32_t& r2, uint32_t& r3) {
    asm volatile("ldmatrix.sync.aligned.m8n8.x4.trans.shared.b16 {%0,%1,%2,%3}, [%4];"
        : "=r"(r0), "=r"(r1), "=r"(r2), "=r"(r3) : "r"(addr));
}
__device__ __forceinline__ void mma_f16(float* c, const uint32_t* a, const uint32_t* b) {
    asm volatile("mma.sync.aligned.m16n8k16.row.col.f32.f16.f16.f32 "
        "{%0,%1,%2,%3}, {%4,%5,%6,%7}, {%8,%9}, {%0,%1,%2,%3};"
        : "+f"(c[0]), "+f"(c[1]), "+f"(c[2]), "+f"(c[3])
        : "r"(a[0]), "r"(a[1]), "r"(a[2]), "r"(a[3]), "r"(b[0]), "r"(b[1]));
}

// mode 0: Cf = acc+bias ; mode 1: +GELU ; mode 2: hi/lo fp16(gelu) -> Cbh/Cbl
template<int TERMS>
__global__ __launch_bounds__(256, 2)
void gemm_mma_kernel(const __half* __restrict__ Ah,
                     const __half* __restrict__ Al,
                     const __half* __restrict__ Bh,
                     const __half* __restrict__ Bl,
                     const float* __restrict__ bias,
                     float* __restrict__ Cf,
                     __half* __restrict__ Cbh,
                     __half* __restrict__ Cbl,
                     int Kp, int N, int mode) {
    extern __shared__ __align__(1024) char smem[];
    uint32_t sb = smem_u32(smem);
    int tid = threadIdx.x;
    int wid = tid >> 5, lane = tid & 31;
    int m0 = blockIdx.y * 128, n0 = blockIdx.x * 128;
    int warp_m = (wid & 1) * 64;
    int warp_n = (wid >> 1) * 32;
    int NC = Kp / 32;

    const __half* Agh = Ah + (size_t)m0 * Kp;
    const __half* Agl = Al + (size_t)m0 * Kp;
    const __half* Bgh = Bh + (size_t)n0 * Kp;
    const __half* Bgl = (TERMS == 3) ? (Bl + (size_t)n0 * Kp) : nullptr;

    float acc[4][4][4];
    #pragma unroll
    for (int i = 0; i < 4; i++)
        #pragma unroll
        for (int j = 0; j < 4; j++)
            #pragma unroll
            for (int r = 0; r < 4; r++) acc[i][j][r] = 0.f;

    auto load_tile = [&](int c, int bf) {
        uint32_t base = sb + bf * STG_BYTES;
        const int NM = (TERMS == 3) ? 4 : 3;
        const __half* srcs[4] = {
            Agh + (size_t)c * 32, Agl + (size_t)c * 32,
            Bgh + (size_t)c * 32,
            (TERMS == 3) ? (Bgl + (size_t)c * 32) : nullptr };
        #pragma unroll
        for (int m = 0; m < NM; m++) {
            const __half* S = srcs[m];
            uint32_t mb = base + m * MAT_B;
            #pragma unroll
            for (int i = 0; i < 2; i++) {
                int ch = i * 256 + tid;
                int r = ch >> 2, c8 = (ch & 3) * 8;
                uint32_t d = mb + r * 80 + c8 * 2;
                const void* s = S + (size_t)r * Kp + c8;
                asm volatile("cp.async.cg.shared.global [%0], [%1], 16;" :: "r"(d), "l"(s));
            }
        }
    };

    load_tile(0, 0);
    asm volatile("cp.async.commit_group;" ::: "memory");

    int rsel = lane & 15, hsel = (lane >> 4) * 16;
    for (int c = 0; c < NC; c++) {
        int bf = c & 1;
        if (c + 1 < NC) load_tile(c + 1, bf ^ 1);
        asm volatile("cp.async.commit_group;" ::: "memory");
        asm volatile("cp.async.wait_group 1;" ::: "memory");
        __syncthreads();

        uint32_t ahb = sb + bf * STG_BYTES;
        uint32_t alb = ahb + MAT_B;
        uint32_t bhb = ahb + 2 * MAT_B;
        uint32_t blb = ahb + 3 * MAT_B;

        #pragma unroll
        for (int ks = 0; ks < 2; ks++) {
            uint32_t ah[4][4], al[4][4], bh[4][2], bl[4][2];
            #pragma unroll
            for (int mi = 0; mi < 4; mi++) {
                uint32_t off = (warp_m + mi * 16 + rsel) * 80 + ks * 32 + hsel;
                ldm_x4(ahb + off, ah[mi][0], ah[mi][1], ah[mi][2], ah[mi][3]);
                ldm_x4(alb + off, al[mi][0], al[mi][1], al[mi][2], al[mi][3]);
            }
            #pragma unroll
            for (int np = 0; np < 2; np++) {
                uint32_t off = (warp_n + np * 16 + rsel) * 80 + ks * 32 + hsel;
                uint32_t r0, r1, r2, r3;
                ldm_x4(bhb + off, r0, r1, r2, r3);
                bh[np * 2 + 0][0] = r0; bh[np * 2 + 0][1] = r2;
                bh[np * 2 + 1][0] = r1; bh[np * 2 + 1][1] = r3;
                if (TERMS == 3) {
                    ldm_x4(blb + off, r0, r1, r2, r3);
                    bl[np * 2 + 0][0] = r0; bl[np * 2 + 0][1] = r2;
                    bl[np * 2 + 1][0] = r1; bl[np * 2 + 1][1] = r3;
                }
            }
            #pragma unroll
            for (int mi = 0; mi < 4; mi++)
                #pragma unroll
                for (int nj = 0; nj < 4; nj++)
                    mma_f16(acc[mi][nj], ah[mi], bh[nj]);
            #pragma unroll
            for (int mi = 0; mi < 4; mi++)
                #pragma unroll
                for (int nj = 0; nj < 4; nj++)
                    mma_f16(acc[mi][nj], al[mi], bh[nj]);
            if (TERMS == 3) {
                #pragma unroll
                for (int mi = 0; mi < 4; mi++)
                    #pragma unroll
                    for (int nj = 0; nj < 4; nj++)
                        mma_f16(acc[mi][nj], ah[mi], bl[nj]);
            }
        }
        __syncthreads();
    }

    int g = lane >> 2, t = lane & 3;
    #pragma unroll
    for (int mi = 0; mi < 4; mi++) {
        int row0 = m0 + warp_m + mi * 16 + g;
        #pragma unroll
        for (int nj = 0; nj < 4; nj++) {
            int col = n0 + warp_n + nj * 8 + t * 2;
            float bx = bias[col], by = bias[col + 1];
            float v0 = acc[mi][nj][0] + bx, v1 = acc[mi][nj][1] + by;
            float v2 = acc[mi][nj][2] + bx, v3 = acc[mi][nj][3] + by;
            if (mode >= 1) { v0 = gelu_tanh(v0); v1 = gelu_tanh(v1); v2 = gelu_tanh(v2); v3 = gelu_tanh(v3); }
            if (mode == 2) {
                #pragma unroll
                for (int rr = 0; rr < 2; rr++) {
                    int row = row0 + rr * 8;
                    float a0 = rr ? v2 : v0, a1 = rr ? v3 : v1;
                    uint32_t h2, l2;
                    hilo2(a0, a1, h2, l2);
                    size_t ro = (size_t)row * N + col;
                    *(uint32_t*)&Cbh[ro] = h2;
                    *(uint32_t*)&Cbl[ro] = l2;
                }
            } else {
                *(float2*)&Cf[(size_t)row0 * N + col]       = make_float2(v0, v1);
                *(float2*)&Cf[(size_t)(row0 + 8) * N + col] = make_float2(v2, v3);
            }
        }
    }
}

// ================= fused flash band attention (fp16 hi/lo, 3-term) =========
#define FB_ROWB 144
#define FB_QH 0
#define FB_QL (FB_QH + 64*FB_ROWB)
#define FB_KH (FB_QL + 64*FB_ROWB)
#define FB_KL (FB_KH + 64*FB_ROWB)
#define FB_VH (FB_KL + 64*FB_ROWB)
#define FB_VL (FB_VH + 64*FB_ROWB)
#define FB_SG (FB_VL + 64*FB_ROWB)
#define FB_V0 (FB_SG + 256)
#define FB_CM (FB_V0 + 256)
#define FB_TOT (FB_CM + 256 + 64)

__global__ __launch_bounds__(128)
void flash_band_kernel(const float* __restrict__ qkv,
                       const int* __restrict__ am,
                       __half* __restrict__ outh,
                       __half* __restrict__ outl) {
    extern __shared__ char fsmc[];
    float* fp = (float*)fsmc;
    uint32_t sb = smem_u32(fsmc);
    int z = blockIdx.y;
    int n = z % CNB;
    int h = (z / CNB) % CH;
    int b = z / (CNB * CH);
    int qt = blockIdx.x;
    int tid = threadIdx.x;
    int w = tid >> 5, lane = tid & 31;
    int rsel = lane & 15, hsel = (lane >> 4) * 16;
    int t2 = (lane & 3) * 2;

    int base_s    = n * CW + qt * 64;
    int base_kpos = n * CW - CW;
    int am0 = am[b * CS];

    #pragma unroll
    for (int i = 0; i < 8; i++) {
        int sid = i * 128 + tid;
        int r = sid >> 4, c4 = (sid & 15) * 4;
        float4 vq = *(const float4*)&qkv[((size_t)(b * CS + base_s + r)) * QKV_S + h * 64 + c4];
        vq.x *= CSCALE; vq.y *= CSCALE; vq.z *= CSCALE; vq.w *= CSCALE;
        uint32_t h0, l0, h1, l1;
        hilo2(vq.x, vq.y, h0, l0);
        hilo2(vq.z, vq.w, h1, l1);
        *(uint2*)(fsmc + FB_QH + r * FB_ROWB + c4 * 2) = make_uint2(h0, h1);
        *(uint2*)(fsmc + FB_QL + r * FB_ROWB + c4 * 2) = make_uint2(l0, l1);
    }
    if (tid < 64)
        fp[FB_V0 / 4 + tid] = qkv[((size_t)(b * CS)) * QKV_S + 1536 + h * 64 + tid];
    __syncthreads();

    {
        int row = tid >> 1, half = tid & 1;
        const __half* qh = (const __half*)(fsmc + FB_QH + row * FB_ROWB);
        const __half* ql = (const __half*)(fsmc + FB_QL + row * FB_ROWB);
        const float* k0p = &qkv[((size_t)(b * CS)) * QKV_S + 768 + h * 64];
        float sgv = 0.f;
        #pragma unroll
        for (int d = 0; d < 32; d++) {
            int dd = half * 32 + d;
            sgv += (__half2float(qh[dd]) + __half2float(ql[dd])) * k0p[dd];
        }
        sgv += __shfl_xor_sync(0xffffffffu, sgv, 1);
        if (half == 0) fp[FB_SG / 4 + row] = sgv;
    }

    uint32_t qh[4][4], ql[4][4];
    #pragma unroll
    for (int dk = 0; dk < 4; dk++) {
        uint32_t off = (16 * w + rsel) * FB_ROWB + dk * 32 + hsel;
        ldm_x4(sb + FB_QH + off, qh[dk][0], qh[dk][1], qh[dk][2], qh[dk][3]);
        ldm_x4(sb + FB_QL + off, ql[dk][0], ql[dk][1], ql[dk][2], ql[dk][3]);
    }

    float o[8][4];
    #pragma unroll
    for (int nn = 0; nn < 8; nn++)
        #pragma unroll
        for (int e = 0; e < 4; e++) o[nn][e] = 0.f;
    float mst0 = -1e30f, mst1 = -1e30f, lst0 = 0.f, lst1 = 0.f;

    int qi0 = qt * 64 + 16 * w + (lane >> 2);
    int qi1 = qi0 + 8;

    for (int kc = 0; kc < 12; kc++) {
        __syncthreads();
        #pragma unroll
        for (int i = 0; i < 8; i++) {
            int sid = i * 128 + tid;
            int r = sid >> 4, c4 = (sid & 15) * 4;
            int kpos = base_kpos + kc * 64 + r;
            float4 vk = make_float4(0.f, 0.f, 0.f, 0.f);
            float4 vv = make_float4(0.f, 0.f, 0.f, 0.f);
            if (kpos >= 0 && kpos < CS) {
                size_t rb = ((size_t)(b * CS + kpos)) * QKV_S + h * 64 + c4;
                vk = *(const float4*)&qkv[rb + 768];
                vv = *(const float4*)&qkv[rb + 1536];
            }
            uint32_t h0, l0, h1, l1;
            hilo2(vk.x, vk.y, h0, l0);
            hilo2(vk.z, vk.w, h1, l1);
            *(uint2*)(fsmc + FB_KH + r * FB_ROWB + c4 * 2) = make_uint2(h0, h1);
            *(uint2*)(fsmc + FB_KL + r * FB_ROWB + c4 * 2) = make_uint2(l0, l1);
            hilo2(vv.x, vv.y, h0, l0);
            hilo2(vv.z, vv.w, h1, l1);
            *(uint2*)(fsmc + FB_VH + r * FB_ROWB + c4 * 2) = make_uint2(h0, h1);
            *(uint2*)(fsmc + FB_VL + r * FB_ROWB + c4 * 2) = make_uint2(l0, l1);
        }
        if (tid < 64) {
            int kpos = base_kpos + kc * 64 + tid;
            bool ok = (kpos >= 0) && (kpos < CS) && (kpos != 0);
            if (ok) ok = am[b * CS + kpos] > 0;
            fp[FB_CM / 4 + tid] = ok ? 1.f : 0.f;
        }
        __syncthreads();

        float s[8][4];
        #pragma unroll
        for (int nn = 0; nn < 8; nn++)
            #pragma unroll
            for (int e = 0; e < 4; e++) s[nn][e] = 0.f;
        #pragma unroll
        for (int dk = 0; dk < 4; dk++) {
            #pragma unroll
            for (int np = 0; np < 4; np++) {
                uint32_t off = (np * 16 + rsel) * FB_ROWB + dk * 32 + hsel;
                uint32_t r0, r1, r2, r3;
                uint32_t kha[2], khb[2], kla[2], klb[2];
                ldm_x4(sb + FB_KH + off, r0, r1, r2, r3);
                kha[0] = r0; kha[1] = r2; khb[0] = r1; khb[1] = r3;
                ldm_x4(sb + FB_KL + off, r0, r1, r2, r3);
                kla[0] = r0; kla[1] = r2; klb[0] = r1; klb[1] = r3;
                mma_f16(s[2 * np],     qh[dk], kha);
                mma_f16(s[2 * np + 1], qh[dk], khb);
                mma_f16(s[2 * np],     ql[dk], kha);
                mma_f16(s[2 * np + 1], ql[dk], khb);
                mma_f16(s[2 * np],     qh[dk], kla);
                mma_f16(s[2 * np + 1], qh[dk], klb);
            }
        }

        #pragma unroll
        for (int nn = 0; nn < 8; nn++) {
            #pragma unroll
            for (int e = 0; e < 2; e++) {
                int kj = kc * 64 + 8 * nn + t2 + e;
                float cm = fp[FB_CM / 4 + 8 * nn + t2 + e];
                bool b0 = (kj >= qi0) && (kj <= qi0 + 2 * CW) && (cm > 0.f);
                bool b1 = (kj >= qi1) && (kj <= qi1 + 2 * CW) && (cm > 0.f);
                if (!b0) s[nn][e] = CNEG;
                if (!b1) s[nn][2 + e] = CNEG;
            }
        }

        float mx0 = -1e30f, mx1 = -1e30f;
        #pragma unroll
        for (int nn = 0; nn < 8; nn++) {
            mx0 = fmaxf(mx0, fmaxf(s[nn][0], s[nn][1]));
            mx1 = fmaxf(mx1, fmaxf(s[nn][2], s[nn][3]));
        }
        mx0 = fmaxf(mx0, __shfl_xor_sync(0xffffffffu, mx0, 1));
        mx0 = fmaxf(mx0, __shfl_xor_sync(0xffffffffu, mx0, 2));
        mx1 = fmaxf(mx1, __shfl_xor_sync(0xffffffffu, mx1, 1));
        mx1 = fmaxf(mx1, __shfl_xor_sync(0xffffffffu, mx1, 2));
        float nm0 = fmaxf(mst0, mx0), nm1 = fmaxf(mst1, mx1);
        float a0 = __expf(mst0 - nm0), a1 = __expf(mst1 - nm1);
        mst0 = nm0; mst1 = nm1;
        float rs0 = 0.f, rs1 = 0.f;
        #pragma unroll
        for (int nn = 0; nn < 8; nn++) {
            s[nn][0] = __expf(s[nn][0] - nm0); rs0 += s[nn][0];
            s[nn][1] = __expf(s[nn][1] - nm0); rs0 += s[nn][1];
            s[nn][2] = __expf(s[nn][2] - nm1); rs1 += s[nn][2];
            s[nn][3] = __expf(s[nn][3] - nm1); rs1 += s[nn][3];
        }
        rs0 += __shfl_xor_sync(0xffffffffu, rs0, 1);
        rs0 += __shfl_xor_sync(0xffffffffu, rs0, 2);
        rs1 += __shfl_xor_sync(0xffffffffu, rs1, 1);
        rs1 += __shfl_xor_sync(0xffffffffu, rs1, 2);
        lst0 = lst0 * a0 + rs0;
        lst1 = lst1 * a1 + rs1;
        #pragma unroll
        for (int nn = 0; nn < 8; nn++) {
            o[nn][0] *= a0; o[nn][1] *= a0;
            o[nn][2] *= a1; o[nn][3] *= a1;
        }

        uint32_t ph[4][4], pl[4][4];
        #pragma unroll
        for (int qf = 0; qf < 4; qf++) {
            hilo2(s[2 * qf][0],     s[2 * qf][1],     ph[qf][0], pl[qf][0]);
            hilo2(s[2 * qf][2],     s[2 * qf][3],     ph[qf][1], pl[qf][1]);
            hilo2(s[2 * qf + 1][0], s[2 * qf + 1][1], ph[qf][2], pl[qf][2]);
            hilo2(s[2 * qf + 1][2], s[2 * qf + 1][3], ph[qf][3], pl[qf][3]);
        }

        #pragma unroll
        for (int qf = 0; qf < 4; qf++) {
            #pragma unroll
            for (int dp = 0; dp < 4; dp++) {
                uint32_t off = (qf * 16 + rsel) * FB_ROWB + dp * 32 + hsel;
                uint32_t r0, r1, r2, r3;
                uint32_t vha[2], vhb[2], vla[2], vlb[2];
                ldm_x4t(sb + FB_VH + off, r0, r1, r2, r3);
                vha[0] = r0; vha[1] = r1; vhb[0] = r2; vhb[1] = r3;
                ldm_x4t(sb + FB_VL + off, r0, r1, r2, r3);
                vla[0] = r0; vla[1] = r1; vlb[0] = r2; vlb[1] = r3;
                mma_f16(o[2 * dp],     ph[qf], vha);
                mma_f16(o[2 * dp + 1], ph[qf], vhb);
                mma_f16(o[2 * dp],     pl[qf], vha);
                mma_f16(o[2 * dp + 1], pl[qf], vhb);
                mma_f16(o[2 * dp],     ph[qf], vla);
                mma_f16(o[2 * dp + 1], ph[qf], vlb);
            }
        }
    }

    #pragma unroll
    for (int rr = 0; rr < 2; rr++) {
        int row = 16 * w + (lane >> 2) + 8 * rr;
        float mst = rr ? mst1 : mst0;
        float lst = rr ? lst1 : lst0;
        float sg = fp[FB_SG / 4 + row];
        if (am0 <= 0) sg = CNEG;
        float nm = fmaxf(mst, sg);
        float alpha = __expf(mst - nm);
        float pg = __expf(sg - nm);
        float l = lst * alpha + pg;
        float inv = 1.0f / l;
        int srow = base_s + row;
        size_t ob = ((size_t)(b * CS + srow)) * CDM + h * 64;
        #pragma unroll
        for (int nn = 0; nn < 8; nn++) {
            int d = 8 * nn + t2;
            float v0 = (o[nn][2 * rr + 0] * alpha + pg * fp[FB_V0 / 4 + d])     * inv;
            float v1 = (o[nn][2 * rr + 1] * alpha + pg * fp[FB_V0 / 4 + d + 1]) * inv;
            uint32_t h2, l2;
            hilo2(v0, v1, h2, l2);
            *(uint32_t*)&outh[ob + d] = h2;
            *(uint32_t*)&outl[ob + d] = l2;
        }
    }
}

// ================= small kernels =================
__device__ __forceinline__ float block_reduce_sum256(float v, float* red) {
    int tid = threadIdx.x;
    red[tid] = v; __syncthreads();
    #pragma unroll
    for (int o = 128; o > 0; o >>= 1) {
        if (tid < o) red[tid] += red[tid + o];
        __syncthreads();
    }
    float r = red[0]; __syncthreads();
    return r;
}

__global__ void embed_ln_kernel(const int* __restrict__ ids,
                                const float* __restrict__ we,
                                const float* __restrict__ pe,
                                const float* __restrict__ gam,
                                const float* __restrict__ bet,
                                float* __restrict__ x,
                                __half* __restrict__ xh,
                                __half* __restrict__ xl) {
    __shared__ float red[256];
    int row = blockIdx.x;
    int s = row % CS;
    int id = ids[row];
    int tid = threadIdx.x;
    const float* wp = we + (size_t)id * CDM;
    const float* pp = pe + (size_t)s * CDM;
    float e[3];
    float sm = 0.f;
    #pragma unroll
    for (int i = 0; i < 3; i++) { int d = tid + i * 256; e[i] = wp[d] + pp[d]; sm += e[i]; }
    float mean = block_reduce_sum256(sm, red) * (1.0f / CDM);
    float vs = 0.f;
    #pragma unroll
    for (int i = 0; i < 3; i++) { float t = e[i] - mean; vs += t * t; }
    float var = block_reduce_sum256(vs, red) * (1.0f / CDM);
    float inv = rsqrtf(var + 1e-5f);
    float* xr = x + (size_t)row * CDM;
    size_t ro = (size_t)row * CDM;
    #pragma unroll
    for (int i = 0; i < 3; i++) {
        int d = tid + i * 256;
        float val = (e[i] - mean) * inv * gam[d] + bet[d];
        xr[d] = val;
        __half h, l;
        hilo(val, h, l);
        xh[ro + d] = h; xl[ro + d] = l;
    }
}

__global__ void add_ln_kernel(float* __restrict__ x,
                              const float* __restrict__ y,
                              const float* __restrict__ gam,
                              const float* __restrict__ bet,
                              __half* __restrict__ xh,
                              __half* __restrict__ xl) {
    __shared__ float red[256];
    int row = blockIdx.x;
    int tid = threadIdx.x;
    float* xr = x + (size_t)row * CDM;
    const float* yr = y + (size_t)row * CDM;
    float e[3];
    float sm = 0.f;
    #pragma unroll
    for (int i = 0; i < 3; i++) { int d = tid + i * 256; e[i] = xr[d] + yr[d]; sm += e[i]; }
    float mean = block_reduce_sum256(sm, red) * (1.0f / CDM);
    float vs = 0.f;
    #pragma unroll
    for (int i = 0; i < 3; i++) { float t = e[i] - mean; vs += t * t; }
    float var = block_reduce_sum256(vs, red) * (1.0f / CDM);
    float inv = rsqrtf(var + 1e-5f);
    size_t ro = (size_t)row * CDM;
    #pragma unroll
    for (int i = 0; i < 3; i++) {
        int d = tid + i * 256;
        float val = (e[i] - mean) * inv * gam[d] + bet[d];
        xr[d] = val;
        __half h, l;
        hilo(val, h, l);
        xh[ro + d] = h; xl[ro + d] = l;
    }
}

__global__ void qg_kernel(const float* __restrict__ x,
                          const float* __restrict__ Wqg,
                          const float* __restrict__ bqg,
                          float* __restrict__ qg) {
    __shared__ float part[4][64];
    int n0 = blockIdx.x * 64;
    int b = blockIdx.y;
    int tid = threadIdx.x;
    int nl = tid & 63, kq = tid >> 6;
    const float* xr = x + (size_t)(b * CS) * CDM;
    float acc = 0.f;
    for (int kk = kq * 192; kk < (kq + 1) * 192; kk++)
        acc += xr[kk] * Wqg[(size_t)kk * CDM + n0 + nl];
    part[kq][nl] = acc;
    __syncthreads();
    if (kq == 0) {
        float t = part[0][nl] + part[1][nl] + part[2][nl] + part[3][nl];
        qg[b * CDM + n0 + nl] = (t + bqg[n0 + nl]) * CSCALE;
    }
}

__global__ void tk_kernel(const float* __restrict__ Wkg,
                          const float* __restrict__ qg,
                          float* __restrict__ t) {
    int k = blockIdx.x * 128 + threadIdx.x;
    int h = blockIdx.y, b = blockIdx.z;
    const float* W = Wkg + (size_t)k * CDM + h * 64;
    const float* q = qg + b * CDM + h * 64;
    float acc = 0.f;
    #pragma unroll
    for (int d = 0; d < 64; d++) acc += W[d] * q[d];
    t[(b * CH + h) * CDM + k] = acc;
}

__global__ __launch_bounds__(256)
void sgl_kernel(const float* __restrict__ x,
                const float* __restrict__ t,
                const int* __restrict__ am,
                float* __restrict__ p) {
    __shared__ float ts[CH][CDM];
    int b = blockIdx.y;
    int tid = threadIdx.x;
    for (int i = tid; i < CH * CDM; i += 256)
        ((float*)ts)[i] = t[b * CH * CDM + i];
    __syncthreads();
    int w = tid >> 5, lane = tid & 31;
    int s = blockIdx.x * 8 + w;
    const float* xr = x + ((size_t)(b * CS + s)) * CDM;
    float acc[CH];
    #pragma unroll
    for (int h = 0; h < CH; h++) acc[h] = 0.f;
    for (int k = lane; k < CDM; k += 32) {
        float xv = xr[k];
        #pragma unroll
        for (int h = 0; h < CH; h++) acc[h] += xv * ts[h][k];
    }
    #pragma unroll
    for (int h = 0; h < CH; h++) {
        #pragma unroll
        for (int o = 16; o > 0; o >>= 1)
            acc[h] += __shfl_xor_sync(0xffffffffu, acc[h], o);
    }
    bool okm = am[b * CS + s] > 0;
    if (lane < CH)
        p[((size_t)(b * CH + lane)) * CS + s] = okm ? acc[lane] : CNEG;
}

__global__ void softmax_p_kernel(float* __restrict__ p) {
    __shared__ float red[256];
    int h = blockIdx.x, b = blockIdx.y;
    int tid = threadIdx.x;
    float* pr = p + ((size_t)(b * CH + h)) * CS;
    float mx = -1e30f;
    for (int s = tid; s < CS; s += 256) mx = fmaxf(mx, pr[s]);
    red[tid] = mx; __syncthreads();
    #pragma unroll
    for (int o = 128; o > 0; o >>= 1) {
        if (tid < o) red[tid] = fmaxf(red[tid], red[tid + o]);
        __syncthreads();
    }
    mx = red[0]; __syncthreads();
    float sm = 0.f;
    for (int s = tid; s < CS; s += 256) {
        float e = __expf(pr[s] - mx);
        pr[s] = e; sm += e;
    }
    float tot = block_reduce_sum256(sm, red);
    float inv = 1.0f / tot;
    for (int s = tid; s < CS; s += 256) pr[s] *= inv;
}

__global__ __launch_bounds__(256)
void u_part_kernel(const float* __restrict__ p,
                   const float* __restrict__ x,
                   float* __restrict__ up) {
    __shared__ float xs[128][64];
    __shared__ float ps[CH][128];
    int kc = blockIdx.x, sc = blockIdx.y, b = blockIdx.z;
    int k0 = kc * 64;
    int tid = threadIdx.x;
    int kl = tid & 63, h0 = tid >> 6;
    #pragma unroll
    for (int i = 0; i < 32; i++) {
        int idx = i * 256 + tid;
        int r = idx >> 6, c = idx & 63;
        xs[r][c] = x[((size_t)(b * CS + sc * 128 + r)) * CDM + k0 + c];
    }
    #pragma unroll
    for (int i = 0; i < 6; i++) {
        int idx = i * 256 + tid;
        int hh = idx >> 7, ss = idx & 127;
        ps[hh][ss] = p[((size_t)(b * CH + hh)) * CS + sc * 128 + ss];
    }
    __syncthreads();
    float acc[3] = {0.f, 0.f, 0.f};
    for (int s = 0; s < 128; s++) {
        float xv = xs[s][kl];
        acc[0] += ps[h0][s] * xv;
        acc[1] += ps[h0 + 4][s] * xv;
        acc[2] += ps[h0 + 8][s] * xv;
    }
    size_t base = ((size_t)(sc * CB + b)) * CH * CDM;
    up[base + (h0)     * CDM + k0 + kl] = acc[0];
    up[base + (h0 + 4) * CDM + k0 + kl] = acc[1];
    up[base + (h0 + 8) * CDM + k0 + kl] = acc[2];
}

__global__ void u_reduce_kernel(const float* __restrict__ up,
                                float* __restrict__ u) {
    int i = blockIdx.x * 256 + threadIdx.x;
    int b = blockIdx.y;
    float acc = 0.f;
    #pragma unroll
    for (int sc = 0; sc < 32; sc++)
        acc += up[((size_t)(sc * CB + b)) * CH * CDM + i];
    u[b * CH * CDM + i] = acc;
}

__global__ void og_kernel(const float* __restrict__ u,
                          const float* __restrict__ Wvg,
                          const float* __restrict__ bvg,
                          __half* __restrict__ outh,
                          __half* __restrict__ outl) {
    __shared__ float part[4][64];
    int h = blockIdx.x, b = blockIdx.y;
    int tid = threadIdx.x;
    int d = tid & 63, kq = tid >> 6;
    const float* upr = u + (b * CH + h) * CDM;
    float acc = 0.f;
    for (int k = kq * 192; k < (kq + 1) * 192; k++)
        acc += upr[k] * Wvg[(size_t)k * CDM + h * 64 + d];
    part[kq][d] = acc;
    __syncthreads();
    if (kq == 0) {
        float t = part[0][d] + part[1][d] + part[2][d] + part[3][d] + bvg[h * 64 + d];
        __half hh, ll;
        hilo(t, hh, ll);
        size_t ob = ((size_t)(b * CS)) * CDM + h * 64 + d;
        outh[ob] = hh;
        outl[ob] = ll;
    }
}

__global__ void cls_kernel(const float* __restrict__ x,
                           const float* __restrict__ Wc,
                           const float* __restrict__ bc,
                           float* __restrict__ out) {
    __shared__ float red[256];
    int b = blockIdx.x >> 1, c = blockIdx.x & 1;
    int tid = threadIdx.x;
    const float* xr = x + (size_t)(b * CS) * CDM;
    float acc = 0.f;
    for (int d = tid; d < CDM; d += 256) acc += xr[d] * Wc[d * 2 + c];
    float tot = block_reduce_sum256(acc, red);
    if (tid == 0) out[b * 2 + c] = tot + bc[c];
}

// ================= launch =================
extern "C" void kernel_launch(void* const* d_in, const int* in_sizes, int n_in,
                              void* d_out, int out_size) {
    const int*   ids  = (const int*)d_in[0];
    const int*   am   = (const int*)d_in[1];
    const float* we   = (const float*)d_in[2];
    const float* pe   = (const float*)d_in[3];
    const float* lnes = (const float*)d_in[4];
    const float* lneb = (const float*)d_in[5];
    const float* Wq   = (const float*)d_in[6];
    const float* bq   = (const float*)d_in[7];
    const float* Wk   = (const float*)d_in[8];
    const float* bk   = (const float*)d_in[9];
    const float* Wv   = (const float*)d_in[10];
    const float* bv   = (const float*)d_in[11];
    const float* Wqg  = (const float*)d_in[12];
    const float* bqg  = (const float*)d_in[13];
    const float* Wkg  = (const float*)d_in[14];
    const float* bkg  = (const float*)d_in[15];
    const float* Wvg  = (const float*)d_in[16];
    const float* bvg  = (const float*)d_in[17];
    const float* Wo   = (const float*)d_in[18];
    const float* bo   = (const float*)d_in[19];
    const float* ln1s = (const float*)d_in[20];
    const float* ln1b = (const float*)d_in[21];
    const float* W1   = (const float*)d_in[22];
    const float* b1   = (const float*)d_in[23];
    const float* W2   = (const float*)d_in[24];
    const float* b2   = (const float*)d_in[25];
    const float* ln2s = (const float*)d_in[26];
    const float* ln2b = (const float*)d_in[27];
    const float* Wcls = (const float*)d_in[28];
    const float* bcls = (const float*)d_in[29];
    float* out = (float*)d_out;

    float *xp, *yp, *qkvp, *qgp, *biasp, *tp, *pp, *up, *upp;
    __half *xhp, *xlp, *ahp, *alp, *hhp, *hlp, *whp, *wlp;
    cudaGetSymbolAddress((void**)&xp,   g_x);
    cudaGetSymbolAddress((void**)&yp,   g_y);
    cudaGetSymbolAddress((void**)&qkvp, g_qkv);
    cudaGetSymbolAddress((void**)&qgp,  g_qg);
    cudaGetSymbolAddress((void**)&biasp, g_bias);
    cudaGetSymbolAddress((void**)&tp,   g_t);
    cudaGetSymbolAddress((void**)&pp,   g_p);
    cudaGetSymbolAddress((void**)&up,   g_u);
    cudaGetSymbolAddress((void**)&upp,  g_up);
    cudaGetSymbolAddress((void**)&xhp,  g_xbh);
    cudaGetSymbolAddress((void**)&xlp,  g_xbl);
    cudaGetSymbolAddress((void**)&ahp,  g_abh);
    cudaGetSymbolAddress((void**)&alp,  g_abl);
    cudaGetSymbolAddress((void**)&hhp,  g_hbh);
    cudaGetSymbolAddress((void**)&hlp,  g_hbl);
    cudaGetSymbolAddress((void**)&whp,  g_wbh);
    cudaGetSymbolAddress((void**)&wlp,  g_wbl);

    cudaFuncSetAttribute(gemm_mma_kernel<3>, cudaFuncAttributeMaxDynamicSharedMemorySize, GSM_TOT);
    cudaFuncSetAttribute(gemm_mma_kernel<2>, cudaFuncAttributeMaxDynamicSharedMemorySize, GSM_TOT);
    cudaFuncSetAttribute(flash_band_kernel, cudaFuncAttributeMaxDynamicSharedMemorySize, FB_TOT);

    embed_ln_kernel<<<MROWS, 256>>>(ids, we, pe, lnes, lneb, xp, xhp, xlp);

    dim3 wt_dm(CDM / 32, CDM / 32);
    dim3 wt_b(32, 8);
    size_t wseg = (size_t)CDM * CDM;

    for (int l = 0; l < CL; l++) {
        size_t woff = (size_t)l * CDM * CDM;
        size_t boff = (size_t)l * CDM;
        size_t w1off = (size_t)l * CDM * CDFF;
        size_t b1off = (size_t)l * CDFF;
        size_t w2off = (size_t)l * CDFF * CDM;

        // --- fused QKV GEMM (3-term) ---
        split_wt_kernel<<<wt_dm, wt_b>>>(Wq + woff, whp,            wlp,            CDM, CDM);
        split_wt_kernel<<<wt_dm, wt_b>>>(Wk + woff, whp + wseg,     wlp + wseg,     CDM, CDM);
        split_wt_kernel<<<wt_dm, wt_b>>>(Wv + woff, whp + 2 * wseg, wlp + 2 * wseg, CDM, CDM);
        pack_bias_kernel<<<9, 256>>>(biasp, bq + boff, bk + boff, bv + boff);
        gemm_mma_kernel<3><<<dim3(QKV_S / 128, MROWS / 128), 256, GSM_TOT>>>(
            xhp, xlp, whp, wlp, biasp, qkvp, nullptr, nullptr, CDM, QKV_S, 0);

        flash_band_kernel<<<dim3(4, CB * CH * CNB), 128, FB_TOT>>>(qkvp, am, ahp, alp);

        // --- factored global attention (fp32, no GEMM) ---
        qg_kernel<<<dim3(CDM / 64, CB), 256>>>(xp, Wqg + woff, bqg + boff, qgp);
        tk_kernel<<<dim3(CDM / 128, CH, CB), 128>>>(Wkg + woff, qgp, tp);
        sgl_kernel<<<dim3(CS / 8, CB), 256>>>(xp, tp, am, pp);
        softmax_p_kernel<<<dim3(CH, CB), 256>>>(pp);
        u_part_kernel<<<dim3(CDM / 64, 32, CB), 256>>>(pp, xp, upp);
        u_reduce_kernel<<<dim3(CH * CDM / 256, CB), 256>>>(upp, up);
        og_kernel<<<dim3(CH, CB), 256>>>(up, Wvg + woff, bvg + boff, ahp, alp);

        // --- Wo projection (3-term) + LN1 ---
        split_wt_kernel<<<wt_dm, wt_b>>>(Wo + woff, whp, wlp, CDM, CDM);
        gemm_mma_kernel<3><<<dim3(CDM / 128, MROWS / 128), 256, GSM_TOT>>>(
            ahp, alp, whp, wlp, bo + boff, yp, nullptr, nullptr, CDM, CDM, 0);
        add_ln_kernel<<<MROWS, 256>>>(xp, yp, ln1s + boff, ln1b + boff, xhp, xlp);

        // --- FFN (2-term; Bl never loaded) ---
        split_wt_hi_kernel<<<dim3(CDFF / 32, CDM / 32), wt_b>>>(W1 + w1off, whp, CDM, CDFF);
        gemm_mma_kernel<2><<<dim3(CDFF / 128, MROWS / 128), 256, GSM_TOT>>>(
            xhp, xlp, whp, nullptr, b1 + b1off, nullptr, hhp, hlp, CDM, CDFF, 2);

        split_wt_hi_kernel<<<dim3(CDM / 32, CDFF / 32), wt_b>>>(W2 + w2off, whp, CDFF, CDM);
        gemm_mma_kernel<2><<<dim3(CDM / 128, MROWS / 128), 256, GSM_TOT>>>(
            hhp, hlp, whp, nullptr, b2 + boff, yp, nullptr, nullptr, CDFF, CDM, 0);
        add_ln_kernel<<<MROWS, 256>>>(xp, yp, ln2s + boff, ln2b + boff, xhp, xlp);
    }

    cls_kernel<<<4, 256>>>(xp, Wcls, bcls, out);
}

// round 15
// speedup vs baseline: 1.5344x; 1.0907x over previous
#include <cuda_runtime.h>
#include <cuda_fp16.h>
#include <math.h>
#include <stdint.h>

// ---------------- problem constants ----------------
#define CB   2
#define CS   4096
#define CH   12
#define CD   64
#define CW   256
#define CDM  768
#define CDFF 3072
#define CNB  16
#define CL   2
#define CNEG (-1000000000.0f)
#define CSCALE 0.125f

#define MROWS (CB*CS)    // 8192
#define QKV_S 2304

// ---------------- scratch ----------------
__device__ float g_x   [MROWS*CDM];
__device__ float g_y   [MROWS*CDM];
__device__ float g_qg  [CB*CDM];
__device__ float g_bias[QKV_S];
__device__ float g_t   [CB*CH*CDM];
__device__ float g_p   [(size_t)CB*CH*CS];
__device__ float g_u   [CB*CH*CDM];
__device__ float g_up  [(size_t)32*CB*CH*CDM];
// hi/lo fp16 operand buffers
__device__ __half g_qkvh[(size_t)MROWS*QKV_S];
__device__ __half g_qkvl[(size_t)MROWS*QKV_S];
__device__ __half g_xbh[(size_t)MROWS*CDM];
__device__ __half g_xbl[(size_t)MROWS*CDM];
__device__ __half g_abh[(size_t)MROWS*CDM];
__device__ __half g_abl[(size_t)MROWS*CDM];
__device__ __half g_hbh[(size_t)MROWS*CDFF];
__device__ __half g_hbl[(size_t)MROWS*CDFF];
__device__ __half g_wbh[(size_t)CDFF*CDM];

// ---------------- helpers ----------------
__device__ __forceinline__ float gelu_tanh(float x) {
    float x3 = x * x * x;
    return 0.5f * x * (1.0f + tanhf(0.7978845608028654f * (x + 0.044715f * x3)));
}
__device__ __forceinline__ uint32_t smem_u32(const void* p) {
    uint32_t a;
    asm("{ .reg .u64 t; cvta.to.shared.u64 t, %1; cvt.u32.u64 %0, t; }" : "=r"(a) : "l"(p));
    return a;
}
__device__ __forceinline__ void hilo(float v, __half& h, __half& l) {
    h = __float2half_rn(v);
    l = __float2half_rn(v - __half2float(h));
}
__device__ __forceinline__ void hilo2(float a, float b, uint32_t& h, uint32_t& l) {
    __half ha, la, hb, lb;
    hilo(a, ha, la);
    hilo(b, hb, lb);
    __half2 hh = __halves2half2(ha, hb);
    __half2 ll = __halves2half2(la, lb);
    h = *(uint32_t*)&hh;
    l = *(uint32_t*)&ll;
}

// ================= split/convert kernels =================
// weights: hi only (all GEMMs 2-term)
__global__ void split_wt_hi_kernel(const float* __restrict__ W,
                                   __half* __restrict__ Wth, int K, int N) {
    __shared__ float t[32][33];
    int n0 = blockIdx.x * 32, k0 = blockIdx.y * 32;
    int tx = threadIdx.x, ty = threadIdx.y;
    #pragma unroll
    for (int r = 0; r < 4; r++) {
        int k = k0 + ty + r * 8;
        t[ty + r * 8][tx] = W[(size_t)k * N + n0 + tx];
    }
    __syncthreads();
    #pragma unroll
    for (int r = 0; r < 4; r++) {
        int n = n0 + ty + r * 8;
        int k = k0 + tx;
        Wth[(size_t)n * K + k] = __float2half_rn(t[tx][ty + r * 8]);
    }
}

__global__ void pack_bias_kernel(float* __restrict__ dst,
                                 const float* __restrict__ s0,
                                 const float* __restrict__ s1,
                                 const float* __restrict__ s2) {
    int i = blockIdx.x * 256 + threadIdx.x;
    int s = i / 768, r = i - s * 768;
    const float* p = (s == 0) ? s0 : (s == 1 ? s1 : s2);
    dst[i] = p[r];
}

// ================= warp-MMA fp16 GEMM (2-term: ah*bh + al*bh) ==============
// R12/R14-proven layout: 4-matrix stage slots (Bl slot unused), 81920B smem
// -> exactly 2 CTAs/SM.
#define MAT_B 10240
#define STG_BYTES (4*MAT_B)
#define GSM_TOT (2*STG_BYTES)   // 81920

__device__ __forceinline__ void ldm_x4(uint32_t addr, uint32_t& r0, uint32_t& r1,
                                       uint32_t& r2, uint32_t& r3) {
    asm volatile("ldmatrix.sync.aligned.m8n8.x4.shared.b16 {%0,%1,%2,%3}, [%4];"
        : "=r"(r0), "=r"(r1), "=r"(r2), "=r"(r3) : "r"(addr));
}
__device__ __forceinline__ void ldm_x4t(uint32_t addr, uint32_t& r0, uint32_t& r1,
                                        uint32_t& r2, uint32_t& r3) {
    asm volatile("ldmatrix.sync.aligned.m8n8.x4.trans.shared.b16 {%0,%1,%2,%3}, [%4];"
        : "=r"(r0), "=r"(r1), "=r"(r2), "=r"(r3) : "r"(addr));
}
__device__ __forceinline__ void mma_f16(float* c, const uint32_t* a, const uint32_t* b) {
    asm volatile("mma.sync.aligned.m16n8k16.row.col.f32.f16.f16.f32 "
        "{%0,%1,%2,%3}, {%4,%5,%6,%7}, {%8,%9}, {%0,%1,%2,%3};"
        : "+f"(c[0]), "+f"(c[1]), "+f"(c[2]), "+f"(c[3])
        : "r"(a[0]), "r"(a[1]), "r"(a[2]), "r"(a[3]), "r"(b[0]), "r"(b[1]));
}

// mode 0: Cf = acc+bias (fp32)
// mode 2: Cbh/Cbl = hi/lo fp16(gelu(acc+bias))
// mode 3: Cbh/Cbl = hi/lo fp16((acc+bias) * (col<768 ? CSCALE : 1))   [QKV]
__global__ __launch_bounds__(256, 2)
void gemm_mma_kernel(const __half* __restrict__ Ah,
                     const __half* __restrict__ Al,
                     const __half* __restrict__ Bh,
                     const float* __restrict__ bias,
                     float* __restrict__ Cf,
                     __half* __restrict__ Cbh,
                     __half* __restrict__ Cbl,
                     int Kp, int N, int mode) {
    extern __shared__ __align__(1024) char smem[];
    uint32_t sb = smem_u32(smem);
    int tid = threadIdx.x;
    int wid = tid >> 5, lane = tid & 31;
    int m0 = blockIdx.y * 128, n0 = blockIdx.x * 128;
    int warp_m = (wid & 1) * 64;
    int warp_n = (wid >> 1) * 32;
    int NC = Kp / 32;

    const __half* Agh = Ah + (size_t)m0 * Kp;
    const __half* Agl = Al + (size_t)m0 * Kp;
    const __half* Bgh = Bh + (size_t)n0 * Kp;

    float acc[4][4][4];
    #pragma unroll
    for (int i = 0; i < 4; i++)
        #pragma unroll
        for (int j = 0; j < 4; j++)
            #pragma unroll
            for (int r = 0; r < 4; r++) acc[i][j][r] = 0.f;

    auto load_tile = [&](int c, int bf) {
        uint32_t base = sb + bf * STG_BYTES;
        const __half* srcs[3] = {
            Agh + (size_t)c * 32, Agl + (size_t)c * 32, Bgh + (size_t)c * 32 };
        #pragma unroll
        for (int m = 0; m < 3; m++) {
            const __half* S = srcs[m];
            uint32_t mb = base + m * MAT_B;
            #pragma unroll
            for (int i = 0; i < 2; i++) {
                int ch = i * 256 + tid;
                int r = ch >> 2, c8 = (ch & 3) * 8;
                uint32_t d = mb + r * 80 + c8 * 2;
                const void* s = S + (size_t)r * Kp + c8;
                asm volatile("cp.async.cg.shared.global [%0], [%1], 16;" :: "r"(d), "l"(s));
            }
        }
    };

    load_tile(0, 0);
    asm volatile("cp.async.commit_group;" ::: "memory");

    int rsel = lane & 15, hsel = (lane >> 4) * 16;
    for (int c = 0; c < NC; c++) {
        int bf = c & 1;
        if (c + 1 < NC) load_tile(c + 1, bf ^ 1);
        asm volatile("cp.async.commit_group;" ::: "memory");
        asm volatile("cp.async.wait_group 1;" ::: "memory");
        __syncthreads();

        uint32_t ahb = sb + bf * STG_BYTES;
        uint32_t alb = ahb + MAT_B;
        uint32_t bhb = ahb + 2 * MAT_B;

        #pragma unroll
        for (int ks = 0; ks < 2; ks++) {
            uint32_t ah[4][4], al[4][4], bh[4][2];
            #pragma unroll
            for (int mi = 0; mi < 4; mi++) {
                uint32_t off = (warp_m + mi * 16 + rsel) * 80 + ks * 32 + hsel;
                ldm_x4(ahb + off, ah[mi][0], ah[mi][1], ah[mi][2], ah[mi][3]);
                ldm_x4(alb + off, al[mi][0], al[mi][1], al[mi][2], al[mi][3]);
            }
            #pragma unroll
            for (int np = 0; np < 2; np++) {
                uint32_t off = (warp_n + np * 16 + rsel) * 80 + ks * 32 + hsel;
                uint32_t r0, r1, r2, r3;
                ldm_x4(bhb + off, r0, r1, r2, r3);
                bh[np * 2 + 0][0] = r0; bh[np * 2 + 0][1] = r2;
                bh[np * 2 + 1][0] = r1; bh[np * 2 + 1][1] = r3;
            }
            #pragma unroll
            for (int mi = 0; mi < 4; mi++)
                #pragma unroll
                for (int nj = 0; nj < 4; nj++)
                    mma_f16(acc[mi][nj], ah[mi], bh[nj]);
            #pragma unroll
            for (int mi = 0; mi < 4; mi++)
                #pragma unroll
                for (int nj = 0; nj < 4; nj++)
                    mma_f16(acc[mi][nj], al[mi], bh[nj]);
        }
        __syncthreads();
    }

    int g = lane >> 2, t = lane & 3;
    #pragma unroll
    for (int mi = 0; mi < 4; mi++) {
        int row0 = m0 + warp_m + mi * 16 + g;
        #pragma unroll
        for (int nj = 0; nj < 4; nj++) {
            int col = n0 + warp_n + nj * 8 + t * 2;
            float bx = bias[col], by = bias[col + 1];
            float v0 = acc[mi][nj][0] + bx, v1 = acc[mi][nj][1] + by;
            float v2 = acc[mi][nj][2] + bx, v3 = acc[mi][nj][3] + by;
            if (mode == 2) {
                v0 = gelu_tanh(v0); v1 = gelu_tanh(v1);
                v2 = gelu_tanh(v2); v3 = gelu_tanh(v3);
            } else if (mode == 3) {
                float sc = (col < 768) ? CSCALE : 1.0f;   // col,col+1 same side
                v0 *= sc; v1 *= sc; v2 *= sc; v3 *= sc;
            }
            if (mode >= 2) {
                #pragma unroll
                for (int rr = 0; rr < 2; rr++) {
                    int row = row0 + rr * 8;
                    float a0 = rr ? v2 : v0, a1 = rr ? v3 : v1;
                    uint32_t h2, l2;
                    hilo2(a0, a1, h2, l2);
                    size_t ro = (size_t)row * N + col;
                    *(uint32_t*)&Cbh[ro] = h2;
                    *(uint32_t*)&Cbl[ro] = l2;
                }
            } else {
                *(float2*)&Cf[(size_t)row0 * N + col]       = make_float2(v0, v1);
                *(float2*)&Cf[(size_t)(row0 + 8) * N + col] = make_float2(v2, v3);
            }
        }
    }
}

// ================= fused flash band attention (fp16 hi/lo inputs) ==========
#define FB_ROWB 144
#define FB_QH 0
#define FB_QL (FB_QH + 64*FB_ROWB)
#define FB_KH (FB_QL + 64*FB_ROWB)
#define FB_KL (FB_KH + 64*FB_ROWB)
#define FB_VH (FB_KL + 64*FB_ROWB)
#define FB_VL (FB_VH + 64*FB_ROWB)
#define FB_SG (FB_VL + 64*FB_ROWB)
#define FB_V0 (FB_SG + 256)
#define FB_CM (FB_V0 + 256)
#define FB_TOT (FB_CM + 256 + 64)

__global__ __launch_bounds__(128)
void flash_band_kernel(const __half* __restrict__ qkvh,
                       const __half* __restrict__ qkvl,
                       const int* __restrict__ am,
                       __half* __restrict__ outh,
                       __half* __restrict__ outl) {
    extern __shared__ char fsmc[];
    float* fp = (float*)fsmc;
    uint32_t sb = smem_u32(fsmc);
    int z = blockIdx.y;
    int n = z % CNB;
    int h = (z / CNB) % CH;
    int b = z / (CNB * CH);
    int qt = blockIdx.x;
    int tid = threadIdx.x;
    int w = tid >> 5, lane = tid & 31;
    int rsel = lane & 15, hsel = (lane >> 4) * 16;
    int t2 = (lane & 3) * 2;

    int base_s    = n * CW + qt * 64;
    int base_kpos = n * CW - CW;
    int am0 = am[b * CS];

    // Q already scaled & split — plain copies
    #pragma unroll
    for (int i = 0; i < 8; i++) {
        int sid = i * 128 + tid;
        int r = sid >> 4, c4 = (sid & 15) * 4;
        size_t gb = ((size_t)(b * CS + base_s + r)) * QKV_S + h * 64 + c4;
        *(uint2*)(fsmc + FB_QH + r * FB_ROWB + c4 * 2) = *(const uint2*)&qkvh[gb];
        *(uint2*)(fsmc + FB_QL + r * FB_ROWB + c4 * 2) = *(const uint2*)&qkvl[gb];
    }
    if (tid < 64) {
        size_t gb = ((size_t)(b * CS)) * QKV_S + 1536 + h * 64 + tid;
        fp[FB_V0 / 4 + tid] = __half2float(qkvh[gb]) + __half2float(qkvl[gb]);
    }
    __syncthreads();

    {
        int row = tid >> 1, half = tid & 1;
        const __half* qh = (const __half*)(fsmc + FB_QH + row * FB_ROWB);
        const __half* ql = (const __half*)(fsmc + FB_QL + row * FB_ROWB);
        size_t k0b = ((size_t)(b * CS)) * QKV_S + 768 + h * 64;
        float sgv = 0.f;
        #pragma unroll
        for (int d = 0; d < 32; d++) {
            int dd = half * 32 + d;
            float kv = __half2float(qkvh[k0b + dd]) + __half2float(qkvl[k0b + dd]);
            sgv += (__half2float(qh[dd]) + __half2float(ql[dd])) * kv;
        }
        sgv += __shfl_xor_sync(0xffffffffu, sgv, 1);
        if (half == 0) fp[FB_SG / 4 + row] = sgv;
    }

    uint32_t qh[4][4], ql[4][4];
    #pragma unroll
    for (int dk = 0; dk < 4; dk++) {
        uint32_t off = (16 * w + rsel) * FB_ROWB + dk * 32 + hsel;
        ldm_x4(sb + FB_QH + off, qh[dk][0], qh[dk][1], qh[dk][2], qh[dk][3]);
        ldm_x4(sb + FB_QL + off, ql[dk][0], ql[dk][1], ql[dk][2], ql[dk][3]);
    }

    float o[8][4];
    #pragma unroll
    for (int nn = 0; nn < 8; nn++)
        #pragma unroll
        for (int e = 0; e < 4; e++) o[nn][e] = 0.f;
    float mst0 = -1e30f, mst1 = -1e30f, lst0 = 0.f, lst1 = 0.f;

    int qi0 = qt * 64 + 16 * w + (lane >> 2);
    int qi1 = qi0 + 8;

    for (int kc = 0; kc < 12; kc++) {
        __syncthreads();
        #pragma unroll
        for (int i = 0; i < 8; i++) {
            int sid = i * 128 + tid;
            int r = sid >> 4, c4 = (sid & 15) * 4;
            int kpos = base_kpos + kc * 64 + r;
            uint2 kh = make_uint2(0u, 0u), kl = make_uint2(0u, 0u);
            uint2 vh = make_uint2(0u, 0u), vl = make_uint2(0u, 0u);
            if (kpos >= 0 && kpos < CS) {
                size_t rb = ((size_t)(b * CS + kpos)) * QKV_S + h * 64 + c4;
                kh = *(const uint2*)&qkvh[rb + 768];
                kl = *(const uint2*)&qkvl[rb + 768];
                vh = *(const uint2*)&qkvh[rb + 1536];
                vl = *(const uint2*)&qkvl[rb + 1536];
            }
            *(uint2*)(fsmc + FB_KH + r * FB_ROWB + c4 * 2) = kh;
            *(uint2*)(fsmc + FB_KL + r * FB_ROWB + c4 * 2) = kl;
            *(uint2*)(fsmc + FB_VH + r * FB_ROWB + c4 * 2) = vh;
            *(uint2*)(fsmc + FB_VL + r * FB_ROWB + c4 * 2) = vl;
        }
        if (tid < 64) {
            int kpos = base_kpos + kc * 64 + tid;
            bool ok = (kpos >= 0) && (kpos < CS) && (kpos != 0);
            if (ok) ok = am[b * CS + kpos] > 0;
            fp[FB_CM / 4 + tid] = ok ? 1.f : 0.f;
        }
        __syncthreads();

        float s[8][4];
        #pragma unroll
        for (int nn = 0; nn < 8; nn++)
            #pragma unroll
            for (int e = 0; e < 4; e++) s[nn][e] = 0.f;
        #pragma unroll
        for (int dk = 0; dk < 4; dk++) {
            #pragma unroll
            for (int np = 0; np < 4; np++) {
                uint32_t off = (np * 16 + rsel) * FB_ROWB + dk * 32 + hsel;
                uint32_t r0, r1, r2, r3;
                uint32_t kha[2], khb[2], kla[2], klb[2];
                ldm_x4(sb + FB_KH + off, r0, r1, r2, r3);
                kha[0] = r0; kha[1] = r2; khb[0] = r1; khb[1] = r3;
                ldm_x4(sb + FB_KL + off, r0, r1, r2, r3);
                kla[0] = r0; kla[1] = r2; klb[0] = r1; klb[1] = r3;
                mma_f16(s[2 * np],     qh[dk], kha);
                mma_f16(s[2 * np + 1], qh[dk], khb);
                mma_f16(s[2 * np],     ql[dk], kha);
                mma_f16(s[2 * np + 1], ql[dk], khb);
                mma_f16(s[2 * np],     qh[dk], kla);
                mma_f16(s[2 * np + 1], qh[dk], klb);
            }
        }

        #pragma unroll
        for (int nn = 0; nn < 8; nn++) {
            #pragma unroll
            for (int e = 0; e < 2; e++) {
                int kj = kc * 64 + 8 * nn + t2 + e;
                float cm = fp[FB_CM / 4 + 8 * nn + t2 + e];
                bool b0 = (kj >= qi0) && (kj <= qi0 + 2 * CW) && (cm > 0.f);
                bool b1 = (kj >= qi1) && (kj <= qi1 + 2 * CW) && (cm > 0.f);
                if (!b0) s[nn][e] = CNEG;
                if (!b1) s[nn][2 + e] = CNEG;
            }
        }

        float mx0 = -1e30f, mx1 = -1e30f;
        #pragma unroll
        for (int nn = 0; nn < 8; nn++) {
            mx0 = fmaxf(mx0, fmaxf(s[nn][0], s[nn][1]));
            mx1 = fmaxf(mx1, fmaxf(s[nn][2], s[nn][3]));
        }
        mx0 = fmaxf(mx0, __shfl_xor_sync(0xffffffffu, mx0, 1));
        mx0 = fmaxf(mx0, __shfl_xor_sync(0xffffffffu, mx0, 2));
        mx1 = fmaxf(mx1, __shfl_xor_sync(0xffffffffu, mx1, 1));
        mx1 = fmaxf(mx1, __shfl_xor_sync(0xffffffffu, mx1, 2));
        float nm0 = fmaxf(mst0, mx0), nm1 = fmaxf(mst1, mx1);
        float a0 = __expf(mst0 - nm0), a1 = __expf(mst1 - nm1);
        mst0 = nm0; mst1 = nm1;
        float rs0 = 0.f, rs1 = 0.f;
        #pragma unroll
        for (int nn = 0; nn < 8; nn++) {
            s[nn][0] = __expf(s[nn][0] - nm0); rs0 += s[nn][0];
            s[nn][1] = __expf(s[nn][1] - nm0); rs0 += s[nn][1];
            s[nn][2] = __expf(s[nn][2] - nm1); rs1 += s[nn][2];
            s[nn][3] = __expf(s[nn][3] - nm1); rs1 += s[nn][3];
        }
        rs0 += __shfl_xor_sync(0xffffffffu, rs0, 1);
        rs0 += __shfl_xor_sync(0xffffffffu, rs0, 2);
        rs1 += __shfl_xor_sync(0xffffffffu, rs1, 1);
        rs1 += __shfl_xor_sync(0xffffffffu, rs1, 2);
        lst0 = lst0 * a0 + rs0;
        lst1 = lst1 * a1 + rs1;
        #pragma unroll
        for (int nn = 0; nn < 8; nn++) {
            o[nn][0] *= a0; o[nn][1] *= a0;
            o[nn][2] *= a1; o[nn][3] *= a1;
        }

        uint32_t ph[4][4], pl[4][4];
        #pragma unroll
        for (int qf = 0; qf < 4; qf++) {
            hilo2(s[2 * qf][0],     s[2 * qf][1],     ph[qf][0], pl[qf][0]);
            hilo2(s[2 * qf][2],     s[2 * qf][3],     ph[qf][1], pl[qf][1]);
            hilo2(s[2 * qf + 1][0], s[2 * qf + 1][1], ph[qf][2], pl[qf][2]);
            hilo2(s[2 * qf + 1][2], s[2 * qf + 1][3], ph[qf][3], pl[qf][3]);
        }

        #pragma unroll
        for (int qf = 0; qf < 4; qf++) {
            #pragma unroll
            for (int dp = 0; dp < 4; dp++) {
                uint32_t off = (qf * 16 + rsel) * FB_ROWB + dp * 32 + hsel;
                uint32_t r0, r1, r2, r3;
                uint32_t vha[2], vhb[2], vla[2], vlb[2];
                ldm_x4t(sb + FB_VH + off, r0, r1, r2, r3);
                vha[0] = r0; vha[1] = r1; vhb[0] = r2; vhb[1] = r3;
                ldm_x4t(sb + FB_VL + off, r0, r1, r2, r3);
                vla[0] = r0; vla[1] = r1; vlb[0] = r2; vlb[1] = r3;
                mma_f16(o[2 * dp],     ph[qf], vha);
                mma_f16(o[2 * dp + 1], ph[qf], vhb);
                mma_f16(o[2 * dp],     pl[qf], vha);
                mma_f16(o[2 * dp + 1], pl[qf], vhb);
                mma_f16(o[2 * dp],     ph[qf], vla);
                mma_f16(o[2 * dp + 1], ph[qf], vlb);
            }
        }
    }

    #pragma unroll
    for (int rr = 0; rr < 2; rr++) {
        int row = 16 * w + (lane >> 2) + 8 * rr;
        float mst = rr ? mst1 : mst0;
        float lst = rr ? lst1 : lst0;
        float sg = fp[FB_SG / 4 + row];
        if (am0 <= 0) sg = CNEG;
        float nm = fmaxf(mst, sg);
        float alpha = __expf(mst - nm);
        float pg = __expf(sg - nm);
        float l = lst * alpha + pg;
        float inv = 1.0f / l;
        int srow = base_s + row;
        size_t ob = ((size_t)(b * CS + srow)) * CDM + h * 64;
        #pragma unroll
        for (int nn = 0; nn < 8; nn++) {
            int d = 8 * nn + t2;
            float v0 = (o[nn][2 * rr + 0] * alpha + pg * fp[FB_V0 / 4 + d])     * inv;
            float v1 = (o[nn][2 * rr + 1] * alpha + pg * fp[FB_V0 / 4 + d + 1]) * inv;
            uint32_t h2, l2;
            hilo2(v0, v1, h2, l2);
            *(uint32_t*)&outh[ob + d] = h2;
            *(uint32_t*)&outl[ob + d] = l2;
        }
    }
}

// ================= small kernels =================
__device__ __forceinline__ float block_reduce_sum256(float v, float* red) {
    int tid = threadIdx.x;
    red[tid] = v; __syncthreads();
    #pragma unroll
    for (int o = 128; o > 0; o >>= 1) {
        if (tid < o) red[tid] += red[tid + o];
        __syncthreads();
    }
    float r = red[0]; __syncthreads();
    return r;
}

__global__ void embed_ln_kernel(const int* __restrict__ ids,
                                const float* __restrict__ we,
                                const float* __restrict__ pe,
                                const float* __restrict__ gam,
                                const float* __restrict__ bet,
                                float* __restrict__ x,
                                __half* __restrict__ xh,
                                __half* __restrict__ xl) {
    __shared__ float red[256];
    int row = blockIdx.x;
    int s = row % CS;
    int id = ids[row];
    int tid = threadIdx.x;
    const float* wp = we + (size_t)id * CDM;
    const float* pp = pe + (size_t)s * CDM;
    float e[3];
    float sm = 0.f;
    #pragma unroll
    for (int i = 0; i < 3; i++) { int d = tid + i * 256; e[i] = wp[d] + pp[d]; sm += e[i]; }
    float mean = block_reduce_sum256(sm, red) * (1.0f / CDM);
    float vs = 0.f;
    #pragma unroll
    for (int i = 0; i < 3; i++) { float t = e[i] - mean; vs += t * t; }
    float var = block_reduce_sum256(vs, red) * (1.0f / CDM);
    float inv = rsqrtf(var + 1e-5f);
    float* xr = x + (size_t)row * CDM;
    size_t ro = (size_t)row * CDM;
    #pragma unroll
    for (int i = 0; i < 3; i++) {
        int d = tid + i * 256;
        float val = (e[i] - mean) * inv * gam[d] + bet[d];
        xr[d] = val;
        __half h, l;
        hilo(val, h, l);
        xh[ro + d] = h; xl[ro + d] = l;
    }
}

__global__ void add_ln_kernel(float* __restrict__ x,
                              const float* __restrict__ y,
                              const float* __restrict__ gam,
                              const float* __restrict__ bet,
                              __half* __restrict__ xh,
                              __half* __restrict__ xl) {
    __shared__ float red[256];
    int row = blockIdx.x;
    int tid = threadIdx.x;
    float* xr = x + (size_t)row * CDM;
    const float* yr = y + (size_t)row * CDM;
    float e[3];
    float sm = 0.f;
    #pragma unroll
    for (int i = 0; i < 3; i++) { int d = tid + i * 256; e[i] = xr[d] + yr[d]; sm += e[i]; }
    float mean = block_reduce_sum256(sm, red) * (1.0f / CDM);
    float vs = 0.f;
    #pragma unroll
    for (int i = 0; i < 3; i++) { float t = e[i] - mean; vs += t * t; }
    float var = block_reduce_sum256(vs, red) * (1.0f / CDM);
    float inv = rsqrtf(var + 1e-5f);
    size_t ro = (size_t)row * CDM;
    #pragma unroll
    for (int i = 0; i < 3; i++) {
        int d = tid + i * 256;
        float val = (e[i] - mean) * inv * gam[d] + bet[d];
        xr[d] = val;
        __half h, l;
        hilo(val, h, l);
        xh[ro + d] = h; xl[ro + d] = l;
    }
}

__global__ void qg_kernel(const float* __restrict__ x,
                          const float* __restrict__ Wqg,
                          const float* __restrict__ bqg,
                          float* __restrict__ qg) {
    __shared__ float part[4][64];
    int n0 = blockIdx.x * 64;
    int b = blockIdx.y;
    int tid = threadIdx.x;
    int nl = tid & 63, kq = tid >> 6;
    const float* xr = x + (size_t)(b * CS) * CDM;
    float acc = 0.f;
    for (int kk = kq * 192; kk < (kq + 1) * 192; kk++)
        acc += xr[kk] * Wqg[(size_t)kk * CDM + n0 + nl];
    part[kq][nl] = acc;
    __syncthreads();
    if (kq == 0) {
        float t = part[0][nl] + part[1][nl] + part[2][nl] + part[3][nl];
        qg[b * CDM + n0 + nl] = (t + bqg[n0 + nl]) * CSCALE;
    }
}

__global__ void tk_kernel(const float* __restrict__ Wkg,
                          const float* __restrict__ qg,
                          float* __restrict__ t) {
    int k = blockIdx.x * 128 + threadIdx.x;
    int h = blockIdx.y, b = blockIdx.z;
    const float* W = Wkg + (size_t)k * CDM + h * 64;
    const float* q = qg + b * CDM + h * 64;
    float acc = 0.f;
    #pragma unroll
    for (int d = 0; d < 64; d++) acc += W[d] * q[d];
    t[(b * CH + h) * CDM + k] = acc;
}

__global__ __launch_bounds__(256)
void sgl_kernel(const float* __restrict__ x,
                const float* __restrict__ t,
                const int* __restrict__ am,
                float* __restrict__ p) {
    __shared__ float ts[CH][CDM];
    int b = blockIdx.y;
    int tid = threadIdx.x;
    for (int i = tid; i < CH * CDM; i += 256)
        ((float*)ts)[i] = t[b * CH * CDM + i];
    __syncthreads();
    int w = tid >> 5, lane = tid & 31;
    int s = blockIdx.x * 8 + w;
    const float* xr = x + ((size_t)(b * CS + s)) * CDM;
    float acc[CH];
    #pragma unroll
    for (int h = 0; h < CH; h++) acc[h] = 0.f;
    for (int k = lane; k < CDM; k += 32) {
        float xv = xr[k];
        #pragma unroll
        for (int h = 0; h < CH; h++) acc[h] += xv * ts[h][k];
    }
    #pragma unroll
    for (int h = 0; h < CH; h++) {
        #pragma unroll
        for (int o = 16; o > 0; o >>= 1)
            acc[h] += __shfl_xor_sync(0xffffffffu, acc[h], o);
    }
    bool okm = am[b * CS + s] > 0;
    if (lane < CH)
        p[((size_t)(b * CH + lane)) * CS + s] = okm ? acc[lane] : CNEG;
}

__global__ void softmax_p_kernel(float* __restrict__ p) {
    __shared__ float red[256];
    int h = blockIdx.x, b = blockIdx.y;
    int tid = threadIdx.x;
    float* pr = p + ((size_t)(b * CH + h)) * CS;
    float mx = -1e30f;
    for (int s = tid; s < CS; s += 256) mx = fmaxf(mx, pr[s]);
    red[tid] = mx; __syncthreads();
    #pragma unroll
    for (int o = 128; o > 0; o >>= 1) {
        if (tid < o) red[tid] = fmaxf(red[tid], red[tid + o]);
        __syncthreads();
    }
    mx = red[0]; __syncthreads();
    float sm = 0.f;
    for (int s = tid; s < CS; s += 256) {
        float e = __expf(pr[s] - mx);
        pr[s] = e; sm += e;
    }
    float tot = block_reduce_sum256(sm, red);
    float inv = 1.0f / tot;
    for (int s = tid; s < CS; s += 256) pr[s] *= inv;
}

__global__ __launch_bounds__(256)
void u_part_kernel(const float* __restrict__ p,
                   const float* __restrict__ x,
                   float* __restrict__ up) {
    __shared__ float xs[128][64];
    __shared__ float ps[CH][128];
    int kc = blockIdx.x, sc = blockIdx.y, b = blockIdx.z;
    int k0 = kc * 64;
    int tid = threadIdx.x;
    int kl = tid & 63, h0 = tid >> 6;
    #pragma unroll
    for (int i = 0; i < 32; i++) {
        int idx = i * 256 + tid;
        int r = idx >> 6, c = idx & 63;
        xs[r][c] = x[((size_t)(b * CS + sc * 128 + r)) * CDM + k0 + c];
    }
    #pragma unroll
    for (int i = 0; i < 6; i++) {
        int idx = i * 256 + tid;
        int hh = idx >> 7, ss = idx & 127;
        ps[hh][ss] = p[((size_t)(b * CH + hh)) * CS + sc * 128 + ss];
    }
    __syncthreads();
    float acc[3] = {0.f, 0.f, 0.f};
    for (int s = 0; s < 128; s++) {
        float xv = xs[s][kl];
        acc[0] += ps[h0][s] * xv;
        acc[1] += ps[h0 + 4][s] * xv;
        acc[2] += ps[h0 + 8][s] * xv;
    }
    size_t base = ((size_t)(sc * CB + b)) * CH * CDM;
    up[base + (h0)     * CDM + k0 + kl] = acc[0];
    up[base + (h0 + 4) * CDM + k0 + kl] = acc[1];
    up[base + (h0 + 8) * CDM + k0 + kl] = acc[2];
}

__global__ void u_reduce_kernel(const float* __restrict__ up,
                                float* __restrict__ u) {
    int i = blockIdx.x * 256 + threadIdx.x;
    int b = blockIdx.y;
    float acc = 0.f;
    #pragma unroll
    for (int sc = 0; sc < 32; sc++)
        acc += up[((size_t)(sc * CB + b)) * CH * CDM + i];
    u[b * CH * CDM + i] = acc;
}

__global__ void og_kernel(const float* __restrict__ u,
                          const float* __restrict__ Wvg,
                          const float* __restrict__ bvg,
                          __half* __restrict__ outh,
                          __half* __restrict__ outl) {
    __shared__ float part[4][64];
    int h = blockIdx.x, b = blockIdx.y;
    int tid = threadIdx.x;
    int d = tid & 63, kq = tid >> 6;
    const float* upr = u + (b * CH + h) * CDM;
    float acc = 0.f;
    for (int k = kq * 192; k < (kq + 1) * 192; k++)
        acc += upr[k] * Wvg[(size_t)k * CDM + h * 64 + d];
    part[kq][d] = acc;
    __syncthreads();
    if (kq == 0) {
        float t = part[0][d] + part[1][d] + part[2][d] + part[3][d] + bvg[h * 64 + d];
        __half hh, ll;
        hilo(t, hh, ll);
        size_t ob = ((size_t)(b * CS)) * CDM + h * 64 + d;
        outh[ob] = hh;
        outl[ob] = ll;
    }
}

__global__ void cls_kernel(const float* __restrict__ x,
                           const float* __restrict__ Wc,
                           const float* __restrict__ bc,
                           float* __restrict__ out) {
    __shared__ float red[256];
    int b = blockIdx.x >> 1, c = blockIdx.x & 1;
    int tid = threadIdx.x;
    const float* xr = x + (size_t)(b * CS) * CDM;
    float acc = 0.f;
    for (int d = tid; d < CDM; d += 256) acc += xr[d] * Wc[d * 2 + c];
    float tot = block_reduce_sum256(acc, red);
    if (tid == 0) out[b * 2 + c] = tot + bc[c];
}

// ================= launch =================
extern "C" void kernel_launch(void* const* d_in, const int* in_sizes, int n_in,
                              void* d_out, int out_size) {
    const int*   ids  = (const int*)d_in[0];
    const int*   am   = (const int*)d_in[1];
    const float* we   = (const float*)d_in[2];
    const float* pe   = (const float*)d_in[3];
    const float* lnes = (const float*)d_in[4];
    const float* lneb = (const float*)d_in[5];
    const float* Wq   = (const float*)d_in[6];
    const float* bq   = (const float*)d_in[7];
    const float* Wk   = (const float*)d_in[8];
    const float* bk   = (const float*)d_in[9];
    const float* Wv   = (const float*)d_in[10];
    const float* bv   = (const float*)d_in[11];
    const float* Wqg  = (const float*)d_in[12];
    const float* bqg  = (const float*)d_in[13];
    const float* Wkg  = (const float*)d_in[14];
    const float* bkg  = (const float*)d_in[15];
    const float* Wvg  = (const float*)d_in[16];
    const float* bvg  = (const float*)d_in[17];
    const float* Wo   = (const float*)d_in[18];
    const float* bo   = (const float*)d_in[19];
    const float* ln1s = (const float*)d_in[20];
    const float* ln1b = (const float*)d_in[21];
    const float* W1   = (const float*)d_in[22];
    const float* b1   = (const float*)d_in[23];
    const float* W2   = (const float*)d_in[24];
    const float* b2   = (const float*)d_in[25];
    const float* ln2s = (const float*)d_in[26];
    const float* ln2b = (const float*)d_in[27];
    const float* Wcls = (const float*)d_in[28];
    const float* bcls = (const float*)d_in[29];
    float* out = (float*)d_out;

    float *xp, *yp, *qgp, *biasp, *tp, *pp, *up, *upp;
    __half *qkvhp, *qkvlp, *xhp, *xlp, *ahp, *alp, *hhp, *hlp, *whp;
    cudaGetSymbolAddress((void**)&xp,   g_x);
    cudaGetSymbolAddress((void**)&yp,   g_y);
    cudaGetSymbolAddress((void**)&qgp,  g_qg);
    cudaGetSymbolAddress((void**)&biasp, g_bias);
    cudaGetSymbolAddress((void**)&tp,   g_t);
    cudaGetSymbolAddress((void**)&pp,   g_p);
    cudaGetSymbolAddress((void**)&up,   g_u);
    cudaGetSymbolAddress((void**)&upp,  g_up);
    cudaGetSymbolAddress((void**)&qkvhp, g_qkvh);
    cudaGetSymbolAddress((void**)&qkvlp, g_qkvl);
    cudaGetSymbolAddress((void**)&xhp,  g_xbh);
    cudaGetSymbolAddress((void**)&xlp,  g_xbl);
    cudaGetSymbolAddress((void**)&ahp,  g_abh);
    cudaGetSymbolAddress((void**)&alp,  g_abl);
    cudaGetSymbolAddress((void**)&hhp,  g_hbh);
    cudaGetSymbolAddress((void**)&hlp,  g_hbl);
    cudaGetSymbolAddress((void**)&whp,  g_wbh);

    cudaFuncSetAttribute(gemm_mma_kernel, cudaFuncAttributeMaxDynamicSharedMemorySize, GSM_TOT);
    cudaFuncSetAttribute(flash_band_kernel, cudaFuncAttributeMaxDynamicSharedMemorySize, FB_TOT);

    embed_ln_kernel<<<MROWS, 256>>>(ids, we, pe, lnes, lneb, xp, xhp, xlp);

    dim3 wt_dm(CDM / 32, CDM / 32);
    dim3 wt_b(32, 8);
    size_t wseg = (size_t)CDM * CDM;

    for (int l = 0; l < CL; l++) {
        size_t woff = (size_t)l * CDM * CDM;
        size_t boff = (size_t)l * CDM;
        size_t w1off = (size_t)l * CDM * CDFF;
        size_t b1off = (size_t)l * CDFF;
        size_t w2off = (size_t)l * CDFF * CDM;

        // --- fused QKV GEMM (2-term, fp16 hi/lo output, Q pre-scaled) ---
        split_wt_hi_kernel<<<wt_dm, wt_b>>>(Wq + woff, whp,            CDM, CDM);
        split_wt_hi_kernel<<<wt_dm, wt_b>>>(Wk + woff, whp + wseg,     CDM, CDM);
        split_wt_hi_kernel<<<wt_dm, wt_b>>>(Wv + woff, whp + 2 * wseg, CDM, CDM);
        pack_bias_kernel<<<9, 256>>>(biasp, bq + boff, bk + boff, bv + boff);
        gemm_mma_kernel<<<dim3(QKV_S / 128, MROWS / 128), 256, GSM_TOT>>>(
            xhp, xlp, whp, biasp, nullptr, qkvhp, qkvlp, CDM, QKV_S, 3);

        flash_band_kernel<<<dim3(4, CB * CH * CNB), 128, FB_TOT>>>(qkvhp, qkvlp, am, ahp, alp);

        // --- factored global attention (fp32, no GEMM) ---
        qg_kernel<<<dim3(CDM / 64, CB), 256>>>(xp, Wqg + woff, bqg + boff, qgp);
        tk_kernel<<<dim3(CDM / 128, CH, CB), 128>>>(Wkg + woff, qgp, tp);
        sgl_kernel<<<dim3(CS / 8, CB), 256>>>(xp, tp, am, pp);
        softmax_p_kernel<<<dim3(CH, CB), 256>>>(pp);
        u_part_kernel<<<dim3(CDM / 64, 32, CB), 256>>>(pp, xp, upp);
        u_reduce_kernel<<<dim3(CH * CDM / 256, CB), 256>>>(upp, up);
        og_kernel<<<dim3(CH, CB), 256>>>(up, Wvg + woff, bvg + boff, ahp, alp);

        // --- Wo projection (2-term) + LN1 ---
        split_wt_hi_kernel<<<wt_dm, wt_b>>>(Wo + woff, whp, CDM, CDM);
        gemm_mma_kernel<<<dim3(CDM / 128, MROWS / 128), 256, GSM_TOT>>>(
            ahp, alp, whp, bo + boff, yp, nullptr, nullptr, CDM, CDM, 0);
        add_ln_kernel<<<MROWS, 256>>>(xp, yp, ln1s + boff, ln1b + boff, xhp, xlp);

        // --- FFN (2-term) ---
        split_wt_hi_kernel<<<dim3(CDFF / 32, CDM / 32), wt_b>>>(W1 + w1off, whp, CDM, CDFF);
        gemm_mma_kernel<<<dim3(CDFF / 128, MROWS / 128), 256, GSM_TOT>>>(
            xhp, xlp, whp, b1 + b1off, nullptr, hhp, hlp, CDM, CDFF, 2);

        split_wt_hi_kernel<<<dim3(CDM / 32, CDFF / 32), wt_b>>>(W2 + w2off, whp, CDFF, CDM);
        gemm_mma_kernel<<<dim3(CDM / 128, MROWS / 128), 256, GSM_TOT>>>(
            hhp, hlp, whp, b2 + boff, yp, nullptr, nullptr, CDFF, CDM, 0);
        add_ln_kernel<<<MROWS, 256>>>(xp, yp, ln2s + boff, ln2b + boff, xhp, xlp);
    }

    cls_kernel<<<4, 256>>>(xp, Wcls, bcls, out);
}

// round 16
// speedup vs baseline: 2.5650x; 1.6716x over previous
#include <cuda_runtime.h>
#include <cuda_fp16.h>
#include <math.h>
#include <stdint.h>

// ---------------- problem constants ----------------
#define CB   2
#define CS   4096
#define CH   12
#define CD   64
#define CW   256
#define CDM  768
#define CDFF 3072
#define CNB  16
#define CL   2
#define CNEG (-1000000000.0f)
#define CSCALE 0.125f

#define MROWS (CB*CS)    // 8192
#define QKV_S 2304

// ---------------- scratch ----------------
__device__ float g_x   [MROWS*CDM];
__device__ float g_y   [MROWS*CDM];
__device__ float g_qg  [CB*CDM];
__device__ float g_bias[QKV_S];
__device__ float g_t   [CB*CH*CDM];
__device__ float g_p   [(size_t)CB*CH*CS];
__device__ float g_u   [CB*CH*CDM];
__device__ float g_up  [(size_t)32*CB*CH*CDM];
// single fp16 operand buffers
__device__ __half g_qkv[(size_t)MROWS*QKV_S];
__device__ __half g_xb [(size_t)MROWS*CDM];
__device__ __half g_ab [(size_t)MROWS*CDM];
__device__ __half g_hb [(size_t)MROWS*CDFF];
__device__ __half g_wb [(size_t)CDFF*CDM];

// ---------------- helpers ----------------
__device__ __forceinline__ float gelu_tanh(float x) {
    float x3 = x * x * x;
    return 0.5f * x * (1.0f + tanhf(0.7978845608028654f * (x + 0.044715f * x3)));
}
__device__ __forceinline__ uint32_t smem_u32(const void* p) {
    uint32_t a;
    asm("{ .reg .u64 t; cvta.to.shared.u64 t, %1; cvt.u32.u64 %0, t; }" : "=r"(a) : "l"(p));
    return a;
}
__device__ __forceinline__ uint32_t pack2(float a, float b) {
    __half2 t = __floats2half2_rn(a, b);
    return *(uint32_t*)&t;
}

// ================= split/convert kernels =================
__global__ void split_wt_hi_kernel(const float* __restrict__ W,
                                   __half* __restrict__ Wth, int K, int N) {
    __shared__ float t[32][33];
    int n0 = blockIdx.x * 32, k0 = blockIdx.y * 32;
    int tx = threadIdx.x, ty = threadIdx.y;
    #pragma unroll
    for (int r = 0; r < 4; r++) {
        int k = k0 + ty + r * 8;
        t[ty + r * 8][tx] = W[(size_t)k * N + n0 + tx];
    }
    __syncthreads();
    #pragma unroll
    for (int r = 0; r < 4; r++) {
        int n = n0 + ty + r * 8;
        int k = k0 + tx;
        Wth[(size_t)n * K + k] = __float2half_rn(t[tx][ty + r * 8]);
    }
}

__global__ void pack_bias_kernel(float* __restrict__ dst,
                                 const float* __restrict__ s0,
                                 const float* __restrict__ s1,
                                 const float* __restrict__ s2) {
    int i = blockIdx.x * 256 + threadIdx.x;
    int s = i / 768, r = i - s * 768;
    const float* p = (s == 0) ? s0 : (s == 1 ? s1 : s2);
    dst[i] = p[r];
}

// ================= warp-MMA fp16 GEMM (single precision, 4-stage) ==========
// Stage = A | B (20480B); 4 stages = 81920B -> exactly 2 CTAs/SM (proven).
#define MAT_B 10240
#define STG_BYTES (2*MAT_B)
#define GSM_TOT (4*STG_BYTES)   // 81920

__device__ __forceinline__ void ldm_x4(uint32_t addr, uint32_t& r0, uint32_t& r1,
                                       uint32_t& r2, uint32_t& r3) {
    asm volatile("ldmatrix.sync.aligned.m8n8.x4.shared.b16 {%0,%1,%2,%3}, [%4];"
        : "=r"(r0), "=r"(r1), "=r"(r2), "=r"(r3) : "r"(addr));
}
__device__ __forceinline__ void ldm_x4t(uint32_t addr, uint32_t& r0, uint32_t& r1,
                                        uint32_t& r2, uint32_t& r3) {
    asm volatile("ldmatrix.sync.aligned.m8n8.x4.trans.shared.b16 {%0,%1,%2,%3}, [%4];"
        : "=r"(r0), "=r"(r1), "=r"(r2), "=r"(r3) : "r"(addr));
}
__device__ __forceinline__ void mma_f16(float* c, const uint32_t* a, const uint32_t* b) {
    asm volatile("mma.sync.aligned.m16n8k16.row.col.f32.f16.f16.f32 "
        "{%0,%1,%2,%3}, {%4,%5,%6,%7}, {%8,%9}, {%0,%1,%2,%3};"
        : "+f"(c[0]), "+f"(c[1]), "+f"(c[2]), "+f"(c[3])
        : "r"(a[0]), "r"(a[1]), "r"(a[2]), "r"(a[3]), "r"(b[0]), "r"(b[1]));
}

// mode 0: Cf = acc+bias (fp32)
// mode 2: Cb = fp16(gelu(acc+bias))
// mode 3: Cb = fp16((acc+bias) * (col<768 ? CSCALE : 1))   [QKV]
__global__ __launch_bounds__(256, 2)
void gemm_mma_kernel(const __half* __restrict__ A,
                     const __half* __restrict__ Bt,
                     const float* __restrict__ bias,
                     float* __restrict__ Cf,
                     __half* __restrict__ Cb,
                     int Kp, int N, int mode) {
    extern __shared__ __align__(1024) char smem[];
    uint32_t sb = smem_u32(smem);
    int tid = threadIdx.x;
    int wid = tid >> 5, lane = tid & 31;
    int m0 = blockIdx.y * 128, n0 = blockIdx.x * 128;
    int warp_m = (wid & 1) * 64;
    int warp_n = (wid >> 1) * 32;
    int NC = Kp / 32;

    const __half* Ag = A  + (size_t)m0 * Kp;
    const __half* Bg = Bt + (size_t)n0 * Kp;

    float acc[4][4][4];
    #pragma unroll
    for (int i = 0; i < 4; i++)
        #pragma unroll
        for (int j = 0; j < 4; j++)
            #pragma unroll
            for (int r = 0; r < 4; r++) acc[i][j][r] = 0.f;

    auto load_tile = [&](int c, int bf) {
        uint32_t base = sb + bf * STG_BYTES;
        const __half* srcs[2] = { Ag + (size_t)c * 32, Bg + (size_t)c * 32 };
        #pragma unroll
        for (int m = 0; m < 2; m++) {
            const __half* S = srcs[m];
            uint32_t mb = base + m * MAT_B;
            #pragma unroll
            for (int i = 0; i < 2; i++) {
                int ch = i * 256 + tid;
                int r = ch >> 2, c8 = (ch & 3) * 8;
                uint32_t d = mb + r * 80 + c8 * 2;
                const void* s = S + (size_t)r * Kp + c8;
                asm volatile("cp.async.cg.shared.global [%0], [%1], 16;" :: "r"(d), "l"(s));
            }
        }
    };

    load_tile(0, 0);
    asm volatile("cp.async.commit_group;" ::: "memory");
    load_tile(1, 1);
    asm volatile("cp.async.commit_group;" ::: "memory");
    load_tile(2, 2);
    asm volatile("cp.async.commit_group;" ::: "memory");

    int rsel = lane & 15, hsel = (lane >> 4) * 16;
    for (int c = 0; c < NC; c++) {
        int bf = c & 3;
        asm volatile("cp.async.wait_group 2;" ::: "memory");
        __syncthreads();
        if (c + 3 < NC) load_tile(c + 3, (c + 3) & 3);
        asm volatile("cp.async.commit_group;" ::: "memory");

        uint32_t ab = sb + bf * STG_BYTES;
        uint32_t bb = ab + MAT_B;

        #pragma unroll
        for (int ks = 0; ks < 2; ks++) {
            uint32_t a[4][4], b[4][2];
            #pragma unroll
            for (int mi = 0; mi < 4; mi++) {
                uint32_t off = (warp_m + mi * 16 + rsel) * 80 + ks * 32 + hsel;
                ldm_x4(ab + off, a[mi][0], a[mi][1], a[mi][2], a[mi][3]);
            }
            #pragma unroll
            for (int np = 0; np < 2; np++) {
                uint32_t off = (warp_n + np * 16 + rsel) * 80 + ks * 32 + hsel;
                uint32_t r0, r1, r2, r3;
                ldm_x4(bb + off, r0, r1, r2, r3);
                b[np * 2 + 0][0] = r0; b[np * 2 + 0][1] = r2;
                b[np * 2 + 1][0] = r1; b[np * 2 + 1][1] = r3;
            }
            #pragma unroll
            for (int mi = 0; mi < 4; mi++)
                #pragma unroll
                for (int nj = 0; nj < 4; nj++)
                    mma_f16(acc[mi][nj], a[mi], b[nj]);
        }
        __syncthreads();
    }

    int g = lane >> 2, t = lane & 3;
    #pragma unroll
    for (int mi = 0; mi < 4; mi++) {
        int row0 = m0 + warp_m + mi * 16 + g;
        #pragma unroll
        for (int nj = 0; nj < 4; nj++) {
            int col = n0 + warp_n + nj * 8 + t * 2;
            float bx = bias[col], by = bias[col + 1];
            float v0 = acc[mi][nj][0] + bx, v1 = acc[mi][nj][1] + by;
            float v2 = acc[mi][nj][2] + bx, v3 = acc[mi][nj][3] + by;
            if (mode == 2) {
                v0 = gelu_tanh(v0); v1 = gelu_tanh(v1);
                v2 = gelu_tanh(v2); v3 = gelu_tanh(v3);
            } else if (mode == 3) {
                float sc = (col < 768) ? CSCALE : 1.0f;
                v0 *= sc; v1 *= sc; v2 *= sc; v3 *= sc;
            }
            if (mode >= 2) {
                size_t ro0 = (size_t)row0 * N + col;
                size_t ro1 = (size_t)(row0 + 8) * N + col;
                *(uint32_t*)&Cb[ro0] = pack2(v0, v1);
                *(uint32_t*)&Cb[ro1] = pack2(v2, v3);
            } else {
                *(float2*)&Cf[(size_t)row0 * N + col]       = make_float2(v0, v1);
                *(float2*)&Cf[(size_t)(row0 + 8) * N + col] = make_float2(v2, v3);
            }
        }
    }
}

// ================= fused flash band attention (single fp16) =================
#define FB_ROWB 144
#define FB_Q  0
#define FB_K  (FB_Q + 64*FB_ROWB)
#define FB_V  (FB_K + 64*FB_ROWB)
#define FB_SG (FB_V + 64*FB_ROWB)     // 64 floats
#define FB_V0 (FB_SG + 256)
#define FB_CM (FB_V0 + 256)
#define FB_TOT (FB_CM + 256 + 64)

__global__ __launch_bounds__(128)
void flash_band_kernel(const __half* __restrict__ qkv,
                       const int* __restrict__ am,
                       __half* __restrict__ outb) {
    extern __shared__ char fsmc[];
    float* fp = (float*)fsmc;
    uint32_t sb = smem_u32(fsmc);
    int z = blockIdx.y;
    int n = z % CNB;
    int h = (z / CNB) % CH;
    int b = z / (CNB * CH);
    int qt = blockIdx.x;
    int tid = threadIdx.x;
    int w = tid >> 5, lane = tid & 31;
    int rsel = lane & 15, hsel = (lane >> 4) * 16;
    int t2 = (lane & 3) * 2;

    int base_s    = n * CW + qt * 64;
    int base_kpos = n * CW - CW;
    int am0 = am[b * CS];

    // Q already scaled — plain copy
    #pragma unroll
    for (int i = 0; i < 8; i++) {
        int sid = i * 128 + tid;
        int r = sid >> 4, c4 = (sid & 15) * 4;
        size_t gb = ((size_t)(b * CS + base_s + r)) * QKV_S + h * 64 + c4;
        *(uint2*)(fsmc + FB_Q + r * FB_ROWB + c4 * 2) = *(const uint2*)&qkv[gb];
    }
    if (tid < 64) {
        size_t gb = ((size_t)(b * CS)) * QKV_S + 1536 + h * 64 + tid;
        fp[FB_V0 / 4 + tid] = __half2float(qkv[gb]);
    }
    __syncthreads();

    {
        int row = tid >> 1, half = tid & 1;
        const __half* qh = (const __half*)(fsmc + FB_Q + row * FB_ROWB);
        size_t k0b = ((size_t)(b * CS)) * QKV_S + 768 + h * 64;
        float sgv = 0.f;
        #pragma unroll
        for (int d = 0; d < 32; d++) {
            int dd = half * 32 + d;
            sgv += __half2float(qh[dd]) * __half2float(qkv[k0b + dd]);
        }
        sgv += __shfl_xor_sync(0xffffffffu, sgv, 1);
        if (half == 0) fp[FB_SG / 4 + row] = sgv;
    }

    uint32_t qh[4][4];
    #pragma unroll
    for (int dk = 0; dk < 4; dk++) {
        uint32_t off = (16 * w + rsel) * FB_ROWB + dk * 32 + hsel;
        ldm_x4(sb + FB_Q + off, qh[dk][0], qh[dk][1], qh[dk][2], qh[dk][3]);
    }

    float o[8][4];
    #pragma unroll
    for (int nn = 0; nn < 8; nn++)
        #pragma unroll
        for (int e = 0; e < 4; e++) o[nn][e] = 0.f;
    float mst0 = -1e30f, mst1 = -1e30f, lst0 = 0.f, lst1 = 0.f;

    int qi0 = qt * 64 + 16 * w + (lane >> 2);
    int qi1 = qi0 + 8;

    for (int kc = 0; kc < 12; kc++) {
        __syncthreads();
        #pragma unroll
        for (int i = 0; i < 8; i++) {
            int sid = i * 128 + tid;
            int r = sid >> 4, c4 = (sid & 15) * 4;
            int kpos = base_kpos + kc * 64 + r;
            uint2 kh = make_uint2(0u, 0u), vh = make_uint2(0u, 0u);
            if (kpos >= 0 && kpos < CS) {
                size_t rb = ((size_t)(b * CS + kpos)) * QKV_S + h * 64 + c4;
                kh = *(const uint2*)&qkv[rb + 768];
                vh = *(const uint2*)&qkv[rb + 1536];
            }
            *(uint2*)(fsmc + FB_K + r * FB_ROWB + c4 * 2) = kh;
            *(uint2*)(fsmc + FB_V + r * FB_ROWB + c4 * 2) = vh;
        }
        if (tid < 64) {
            int kpos = base_kpos + kc * 64 + tid;
            bool ok = (kpos >= 0) && (kpos < CS) && (kpos != 0);
            if (ok) ok = am[b * CS + kpos] > 0;
            fp[FB_CM / 4 + tid] = ok ? 1.f : 0.f;
        }
        __syncthreads();

        float s[8][4];
        #pragma unroll
        for (int nn = 0; nn < 8; nn++)
            #pragma unroll
            for (int e = 0; e < 4; e++) s[nn][e] = 0.f;
        #pragma unroll
        for (int dk = 0; dk < 4; dk++) {
            #pragma unroll
            for (int np = 0; np < 4; np++) {
                uint32_t off = (np * 16 + rsel) * FB_ROWB + dk * 32 + hsel;
                uint32_t r0, r1, r2, r3;
                uint32_t ka[2], kb[2];
                ldm_x4(sb + FB_K + off, r0, r1, r2, r3);
                ka[0] = r0; ka[1] = r2; kb[0] = r1; kb[1] = r3;
                mma_f16(s[2 * np],     qh[dk], ka);
                mma_f16(s[2 * np + 1], qh[dk], kb);
            }
        }

        #pragma unroll
        for (int nn = 0; nn < 8; nn++) {
            #pragma unroll
            for (int e = 0; e < 2; e++) {
                int kj = kc * 64 + 8 * nn + t2 + e;
                float cm = fp[FB_CM / 4 + 8 * nn + t2 + e];
                bool b0 = (kj >= qi0) && (kj <= qi0 + 2 * CW) && (cm > 0.f);
                bool b1 = (kj >= qi1) && (kj <= qi1 + 2 * CW) && (cm > 0.f);
                if (!b0) s[nn][e] = CNEG;
                if (!b1) s[nn][2 + e] = CNEG;
            }
        }

        float mx0 = -1e30f, mx1 = -1e30f;
        #pragma unroll
        for (int nn = 0; nn < 8; nn++) {
            mx0 = fmaxf(mx0, fmaxf(s[nn][0], s[nn][1]));
            mx1 = fmaxf(mx1, fmaxf(s[nn][2], s[nn][3]));
        }
        mx0 = fmaxf(mx0, __shfl_xor_sync(0xffffffffu, mx0, 1));
        mx0 = fmaxf(mx0, __shfl_xor_sync(0xffffffffu, mx0, 2));
        mx1 = fmaxf(mx1, __shfl_xor_sync(0xffffffffu, mx1, 1));
        mx1 = fmaxf(mx1, __shfl_xor_sync(0xffffffffu, mx1, 2));
        float nm0 = fmaxf(mst0, mx0), nm1 = fmaxf(mst1, mx1);
        float a0 = __expf(mst0 - nm0), a1 = __expf(mst1 - nm1);
        mst0 = nm0; mst1 = nm1;
        float rs0 = 0.f, rs1 = 0.f;
        #pragma unroll
        for (int nn = 0; nn < 8; nn++) {
            s[nn][0] = __expf(s[nn][0] - nm0); rs0 += s[nn][0];
            s[nn][1] = __expf(s[nn][1] - nm0); rs0 += s[nn][1];
            s[nn][2] = __expf(s[nn][2] - nm1); rs1 += s[nn][2];
            s[nn][3] = __expf(s[nn][3] - nm1); rs1 += s[nn][3];
        }
        rs0 += __shfl_xor_sync(0xffffffffu, rs0, 1);
        rs0 += __shfl_xor_sync(0xffffffffu, rs0, 2);
        rs1 += __shfl_xor_sync(0xffffffffu, rs1, 1);
        rs1 += __shfl_xor_sync(0xffffffffu, rs1, 2);
        lst0 = lst0 * a0 + rs0;
        lst1 = lst1 * a1 + rs1;
        #pragma unroll
        for (int nn = 0; nn < 8; nn++) {
            o[nn][0] *= a0; o[nn][1] *= a0;
            o[nn][2] *= a1; o[nn][3] *= a1;
        }

        uint32_t ph[4][4];
        #pragma unroll
        for (int qf = 0; qf < 4; qf++) {
            ph[qf][0] = pack2(s[2 * qf][0],     s[2 * qf][1]);
            ph[qf][1] = pack2(s[2 * qf][2],     s[2 * qf][3]);
            ph[qf][2] = pack2(s[2 * qf + 1][0], s[2 * qf + 1][1]);
            ph[qf][3] = pack2(s[2 * qf + 1][2], s[2 * qf + 1][3]);
        }

        #pragma unroll
        for (int qf = 0; qf < 4; qf++) {
            #pragma unroll
            for (int dp = 0; dp < 4; dp++) {
                uint32_t off = (qf * 16 + rsel) * FB_ROWB + dp * 32 + hsel;
                uint32_t r0, r1, r2, r3;
                uint32_t va[2], vb[2];
                ldm_x4t(sb + FB_V + off, r0, r1, r2, r3);
                va[0] = r0; va[1] = r1; vb[0] = r2; vb[1] = r3;
                mma_f16(o[2 * dp],     ph[qf], va);
                mma_f16(o[2 * dp + 1], ph[qf], vb);
            }
        }
    }

    #pragma unroll
    for (int rr = 0; rr < 2; rr++) {
        int row = 16 * w + (lane >> 2) + 8 * rr;
        float mst = rr ? mst1 : mst0;
        float lst = rr ? lst1 : lst0;
        float sg = fp[FB_SG / 4 + row];
        if (am0 <= 0) sg = CNEG;
        float nm = fmaxf(mst, sg);
        float alpha = __expf(mst - nm);
        float pg = __expf(sg - nm);
        float l = lst * alpha + pg;
        float inv = 1.0f / l;
        int srow = base_s + row;
        size_t ob = ((size_t)(b * CS + srow)) * CDM + h * 64;
        #pragma unroll
        for (int nn = 0; nn < 8; nn++) {
            int d = 8 * nn + t2;
            float v0 = (o[nn][2 * rr + 0] * alpha + pg * fp[FB_V0 / 4 + d])     * inv;
            float v1 = (o[nn][2 * rr + 1] * alpha + pg * fp[FB_V0 / 4 + d + 1]) * inv;
            *(uint32_t*)&outb[ob + d] = pack2(v0, v1);
        }
    }
}

// ================= small kernels =================
__device__ __forceinline__ float block_reduce_sum256(float v, float* red) {
    int tid = threadIdx.x;
    red[tid] = v; __syncthreads();
    #pragma unroll
    for (int o = 128; o > 0; o >>= 1) {
        if (tid < o) red[tid] += red[tid + o];
        __syncthreads();
    }
    float r = red[0]; __syncthreads();
    return r;
}

__global__ void embed_ln_kernel(const int* __restrict__ ids,
                                const float* __restrict__ we,
                                const float* __restrict__ pe,
                                const float* __restrict__ gam,
                                const float* __restrict__ bet,
                                float* __restrict__ x,
                                __half* __restrict__ xb) {
    __shared__ float red[256];
    int row = blockIdx.x;
    int s = row % CS;
    int id = ids[row];
    int tid = threadIdx.x;
    const float* wp = we + (size_t)id * CDM;
    const float* pp = pe + (size_t)s * CDM;
    float e[3];
    float sm = 0.f;
    #pragma unroll
    for (int i = 0; i < 3; i++) { int d = tid + i * 256; e[i] = wp[d] + pp[d]; sm += e[i]; }
    float mean = block_reduce_sum256(sm, red) * (1.0f / CDM);
    float vs = 0.f;
    #pragma unroll
    for (int i = 0; i < 3; i++) { float t = e[i] - mean; vs += t * t; }
    float var = block_reduce_sum256(vs, red) * (1.0f / CDM);
    float inv = rsqrtf(var + 1e-5f);
    float* xr = x + (size_t)row * CDM;
    size_t ro = (size_t)row * CDM;
    #pragma unroll
    for (int i = 0; i < 3; i++) {
        int d = tid + i * 256;
        float val = (e[i] - mean) * inv * gam[d] + bet[d];
        xr[d] = val;
        xb[ro + d] = __float2half_rn(val);
    }
}

__global__ void add_ln_kernel(float* __restrict__ x,
                              const float* __restrict__ y,
                              const float* __restrict__ gam,
                              const float* __restrict__ bet,
                              __half* __restrict__ xb) {
    __shared__ float red[256];
    int row = blockIdx.x;
    int tid = threadIdx.x;
    float* xr = x + (size_t)row * CDM;
    const float* yr = y + (size_t)row * CDM;
    float e[3];
    float sm = 0.f;
    #pragma unroll
    for (int i = 0; i < 3; i++) { int d = tid + i * 256; e[i] = xr[d] + yr[d]; sm += e[i]; }
    float mean = block_reduce_sum256(sm, red) * (1.0f / CDM);
    float vs = 0.f;
    #pragma unroll
    for (int i = 0; i < 3; i++) { float t = e[i] - mean; vs += t * t; }
    float var = block_reduce_sum256(vs, red) * (1.0f / CDM);
    float inv = rsqrtf(var + 1e-5f);
    size_t ro = (size_t)row * CDM;
    #pragma unroll
    for (int i = 0; i < 3; i++) {
        int d = tid + i * 256;
        float val = (e[i] - mean) * inv * gam[d] + bet[d];
        xr[d] = val;
        xb[ro + d] = __float2half_rn(val);
    }
}

__global__ void qg_kernel(const float* __restrict__ x,
                          const float* __restrict__ Wqg,
                          const float* __restrict__ bqg,
                          float* __restrict__ qg) {
    __shared__ float part[4][64];
    int n0 = blockIdx.x * 64;
    int b = blockIdx.y;
    int tid = threadIdx.x;
    int nl = tid & 63, kq = tid >> 6;
    const float* xr = x + (size_t)(b * CS) * CDM;
    float acc = 0.f;
    for (int kk = kq * 192; kk < (kq + 1) * 192; kk++)
        acc += xr[kk] * Wqg[(size_t)kk * CDM + n0 + nl];
    part[kq][nl] = acc;
    __syncthreads();
    if (kq == 0) {
        float t = part[0][nl] + part[1][nl] + part[2][nl] + part[3][nl];
        qg[b * CDM + n0 + nl] = (t + bqg[n0 + nl]) * CSCALE;
    }
}

__global__ void tk_kernel(const float* __restrict__ Wkg,
                          const float* __restrict__ qg,
                          float* __restrict__ t) {
    int k = blockIdx.x * 128 + threadIdx.x;
    int h = blockIdx.y, b = blockIdx.z;
    const float* W = Wkg + (size_t)k * CDM + h * 64;
    const float* q = qg + b * CDM + h * 64;
    float acc = 0.f;
    #pragma unroll
    for (int d = 0; d < 64; d++) acc += W[d] * q[d];
    t[(b * CH + h) * CDM + k] = acc;
}

__global__ __launch_bounds__(256)
void sgl_kernel(const float* __restrict__ x,
                const float* __restrict__ t,
                const int* __restrict__ am,
                float* __restrict__ p) {
    __shared__ float ts[CH][CDM];
    int b = blockIdx.y;
    int tid = threadIdx.x;
    for (int i = tid; i < CH * CDM; i += 256)
        ((float*)ts)[i] = t[b * CH * CDM + i];
    __syncthreads();
    int w = tid >> 5, lane = tid & 31;
    int s = blockIdx.x * 8 + w;
    const float* xr = x + ((size_t)(b * CS + s)) * CDM;
    float acc[CH];
    #pragma unroll
    for (int h = 0; h < CH; h++) acc[h] = 0.f;
    for (int k = lane; k < CDM; k += 32) {
        float xv = xr[k];
        #pragma unroll
        for (int h = 0; h < CH; h++) acc[h] += xv * ts[h][k];
    }
    #pragma unroll
    for (int h = 0; h < CH; h++) {
        #pragma unroll
        for (int o = 16; o > 0; o >>= 1)
            acc[h] += __shfl_xor_sync(0xffffffffu, acc[h], o);
    }
    bool okm = am[b * CS + s] > 0;
    if (lane < CH)
        p[((size_t)(b * CH + lane)) * CS + s] = okm ? acc[lane] : CNEG;
}

__global__ void softmax_p_kernel(float* __restrict__ p) {
    __shared__ float red[256];
    int h = blockIdx.x, b = blockIdx.y;
    int tid = threadIdx.x;
    float* pr = p + ((size_t)(b * CH + h)) * CS;
    float mx = -1e30f;
    for (int s = tid; s < CS; s += 256) mx = fmaxf(mx, pr[s]);
    red[tid] = mx; __syncthreads();
    #pragma unroll
    for (int o = 128; o > 0; o >>= 1) {
        if (tid < o) red[tid] = fmaxf(red[tid], red[tid + o]);
        __syncthreads();
    }
    mx = red[0]; __syncthreads();
    float sm = 0.f;
    for (int s = tid; s < CS; s += 256) {
        float e = __expf(pr[s] - mx);
        pr[s] = e; sm += e;
    }
    float tot = block_reduce_sum256(sm, red);
    float inv = 1.0f / tot;
    for (int s = tid; s < CS; s += 256) pr[s] *= inv;
}

__global__ __launch_bounds__(256)
void u_part_kernel(const float* __restrict__ p,
                   const float* __restrict__ x,
                   float* __restrict__ up) {
    __shared__ float xs[128][64];
    __shared__ float ps[CH][128];
    int kc = blockIdx.x, sc = blockIdx.y, b = blockIdx.z;
    int k0 = kc * 64;
    int tid = threadIdx.x;
    int kl = tid & 63, h0 = tid >> 6;
    #pragma unroll
    for (int i = 0; i < 32; i++) {
        int idx = i * 256 + tid;
        int r = idx >> 6, c = idx & 63;
        xs[r][c] = x[((size_t)(b * CS + sc * 128 + r)) * CDM + k0 + c];
    }
    #pragma unroll
    for (int i = 0; i < 6; i++) {
        int idx = i * 256 + tid;
        int hh = idx >> 7, ss = idx & 127;
        ps[hh][ss] = p[((size_t)(b * CH + hh)) * CS + sc * 128 + ss];
    }
    __syncthreads();
    float acc[3] = {0.f, 0.f, 0.f};
    for (int s = 0; s < 128; s++) {
        float xv = xs[s][kl];
        acc[0] += ps[h0][s] * xv;
        acc[1] += ps[h0 + 4][s] * xv;
        acc[2] += ps[h0 + 8][s] * xv;
    }
    size_t base = ((size_t)(sc * CB + b)) * CH * CDM;
    up[base + (h0)     * CDM + k0 + kl] = acc[0];
    up[base + (h0 + 4) * CDM + k0 + kl] = acc[1];
    up[base + (h0 + 8) * CDM + k0 + kl] = acc[2];
}

__global__ void u_reduce_kernel(const float* __restrict__ up,
                                float* __restrict__ u) {
    int i = blockIdx.x * 256 + threadIdx.x;
    int b = blockIdx.y;
    float acc = 0.f;
    #pragma unroll
    for (int sc = 0; sc < 32; sc++)
        acc += up[((size_t)(sc * CB + b)) * CH * CDM + i];
    u[b * CH * CDM + i] = acc;
}

__global__ void og_kernel(const float* __restrict__ u,
                          const float* __restrict__ Wvg,
                          const float* __restrict__ bvg,
                          __half* __restrict__ outb) {
    __shared__ float part[4][64];
    int h = blockIdx.x, b = blockIdx.y;
    int tid = threadIdx.x;
    int d = tid & 63, kq = tid >> 6;
    const float* upr = u + (b * CH + h) * CDM;
    float acc = 0.f;
    for (int k = kq * 192; k < (kq + 1) * 192; k++)
        acc += upr[k] * Wvg[(size_t)k * CDM + h * 64 + d];
    part[kq][d] = acc;
    __syncthreads();
    if (kq == 0) {
        float t = part[0][d] + part[1][d] + part[2][d] + part[3][d] + bvg[h * 64 + d];
        outb[((size_t)(b * CS)) * CDM + h * 64 + d] = __float2half_rn(t);
    }
}

__global__ void cls_kernel(const float* __restrict__ x,
                           const float* __restrict__ Wc,
                           const float* __restrict__ bc,
                           float* __restrict__ out) {
    __shared__ float red[256];
    int b = blockIdx.x >> 1, c = blockIdx.x & 1;
    int tid = threadIdx.x;
    const float* xr = x + (size_t)(b * CS) * CDM;
    float acc = 0.f;
    for (int d = tid; d < CDM; d += 256) acc += xr[d] * Wc[d * 2 + c];
    float tot = block_reduce_sum256(acc, red);
    if (tid == 0) out[b * 2 + c] = tot + bc[c];
}

// ================= launch =================
extern "C" void kernel_launch(void* const* d_in, const int* in_sizes, int n_in,
                              void* d_out, int out_size) {
    const int*   ids  = (const int*)d_in[0];
    const int*   am   = (const int*)d_in[1];
    const float* we   = (const float*)d_in[2];
    const float* pe   = (const float*)d_in[3];
    const float* lnes = (const float*)d_in[4];
    const float* lneb = (const float*)d_in[5];
    const float* Wq   = (const float*)d_in[6];
    const float* bq   = (const float*)d_in[7];
    const float* Wk   = (const float*)d_in[8];
    const float* bk   = (const float*)d_in[9];
    const float* Wv   = (const float*)d_in[10];
    const float* bv   = (const float*)d_in[11];
    const float* Wqg  = (const float*)d_in[12];
    const float* bqg  = (const float*)d_in[13];
    const float* Wkg  = (const float*)d_in[14];
    const float* bkg  = (const float*)d_in[15];
    const float* Wvg  = (const float*)d_in[16];
    const float* bvg  = (const float*)d_in[17];
    const float* Wo   = (const float*)d_in[18];
    const float* bo   = (const float*)d_in[19];
    const float* ln1s = (const float*)d_in[20];
    const float* ln1b = (const float*)d_in[21];
    const float* W1   = (const float*)d_in[22];
    const float* b1   = (const float*)d_in[23];
    const float* W2   = (const float*)d_in[24];
    const float* b2   = (const float*)d_in[25];
    const float* ln2s = (const float*)d_in[26];
    const float* ln2b = (const float*)d_in[27];
    const float* Wcls = (const float*)d_in[28];
    const float* bcls = (const float*)d_in[29];
    float* out = (float*)d_out;

    float *xp, *yp, *qgp, *biasp, *tp, *pp, *up, *upp;
    __half *qkvp, *xbp, *abp, *hbp, *wbp;
    cudaGetSymbolAddress((void**)&xp,   g_x);
    cudaGetSymbolAddress((void**)&yp,   g_y);
    cudaGetSymbolAddress((void**)&qgp,  g_qg);
    cudaGetSymbolAddress((void**)&biasp, g_bias);
    cudaGetSymbolAddress((void**)&tp,   g_t);
    cudaGetSymbolAddress((void**)&pp,   g_p);
    cudaGetSymbolAddress((void**)&up,   g_u);
    cudaGetSymbolAddress((void**)&upp,  g_up);
    cudaGetSymbolAddress((void**)&qkvp, g_qkv);
    cudaGetSymbolAddress((void**)&xbp,  g_xb);
    cudaGetSymbolAddress((void**)&abp,  g_ab);
    cudaGetSymbolAddress((void**)&hbp,  g_hb);
    cudaGetSymbolAddress((void**)&wbp,  g_wb);

    cudaFuncSetAttribute(gemm_mma_kernel, cudaFuncAttributeMaxDynamicSharedMemorySize, GSM_TOT);
    cudaFuncSetAttribute(flash_band_kernel, cudaFuncAttributeMaxDynamicSharedMemorySize, FB_TOT);

    embed_ln_kernel<<<MROWS, 256>>>(ids, we, pe, lnes, lneb, xp, xbp);

    dim3 wt_dm(CDM / 32, CDM / 32);
    dim3 wt_b(32, 8);
    size_t wseg = (size_t)CDM * CDM;

    for (int l = 0; l < CL; l++) {
        size_t woff = (size_t)l * CDM * CDM;
        size_t boff = (size_t)l * CDM;
        size_t w1off = (size_t)l * CDM * CDFF;
        size_t b1off = (size_t)l * CDFF;
        size_t w2off = (size_t)l * CDFF * CDM;

        // --- fused QKV GEMM (fp16, Q pre-scaled) ---
        split_wt_hi_kernel<<<wt_dm, wt_b>>>(Wq + woff, wbp,            CDM, CDM);
        split_wt_hi_kernel<<<wt_dm, wt_b>>>(Wk + woff, wbp + wseg,     CDM, CDM);
        split_wt_hi_kernel<<<wt_dm, wt_b>>>(Wv + woff, wbp + 2 * wseg, CDM, CDM);
        pack_bias_kernel<<<9, 256>>>(biasp, bq + boff, bk + boff, bv + boff);
        gemm_mma_kernel<<<dim3(QKV_S / 128, MROWS / 128), 256, GSM_TOT>>>(
            xbp, wbp, biasp, nullptr, qkvp, CDM, QKV_S, 3);

        flash_band_kernel<<<dim3(4, CB * CH * CNB), 128, FB_TOT>>>(qkvp, am, abp);

        // --- factored global attention (fp32, no GEMM) ---
        qg_kernel<<<dim3(CDM / 64, CB), 256>>>(xp, Wqg + woff, bqg + boff, qgp);
        tk_kernel<<<dim3(CDM / 128, CH, CB), 128>>>(Wkg + woff, qgp, tp);
        sgl_kernel<<<dim3(CS / 8, CB), 256>>>(xp, tp, am, pp);
        softmax_p_kernel<<<dim3(CH, CB), 256>>>(pp);
        u_part_kernel<<<dim3(CDM / 64, 32, CB), 256>>>(pp, xp, upp);
        u_reduce_kernel<<<dim3(CH * CDM / 256, CB), 256>>>(upp, up);
        og_kernel<<<dim3(CH, CB), 256>>>(up, Wvg + woff, bvg + boff, abp);

        // --- Wo projection + LN1 ---
        split_wt_hi_kernel<<<wt_dm, wt_b>>>(Wo + woff, wbp, CDM, CDM);
        gemm_mma_kernel<<<dim3(CDM / 128, MROWS / 128), 256, GSM_TOT>>>(
            abp, wbp, bo + boff, yp, nullptr, CDM, CDM, 0);
        add_ln_kernel<<<MROWS, 256>>>(xp, yp, ln1s + boff, ln1b + boff, xbp);

        // --- FFN ---
        split_wt_hi_kernel<<<dim3(CDFF / 32, CDM / 32), wt_b>>>(W1 + w1off, wbp, CDM, CDFF);
        gemm_mma_kernel<<<dim3(CDFF / 128, MROWS / 128), 256, GSM_TOT>>>(
            xbp, wbp, b1 + b1off, nullptr, hbp, CDM, CDFF, 2);

        split_wt_hi_kernel<<<dim3(CDM / 32, CDFF / 32), wt_b>>>(W2 + w2off, wbp, CDFF, CDM);
        gemm_mma_kernel<<<dim3(CDM / 128, MROWS / 128), 256, GSM_TOT>>>(
            hbp, wbp, b2 + boff, yp, nullptr, CDFF, CDM, 0);
        add_ln_kernel<<<MROWS, 256>>>(xp, yp, ln2s + boff, ln2b + boff, xbp);
    }

    cls_kernel<<<4, 256>>>(xp, Wcls, bcls, out);
}

// round 17
// speedup vs baseline: 2.6892x; 1.0484x over previous
#include <cuda_runtime.h>
#include <cuda_fp16.h>
#include <math.h>
#include <stdint.h>

// ---------------- problem constants ----------------
#define CB   2
#define CS   4096
#define CH   12
#define CD   64
#define CW   256
#define CDM  768
#define CDFF 3072
#define CNB  16
#define CL   2
#define CNEG (-1000000000.0f)
#define CSCALE 0.125f

#define MROWS (CB*CS)    // 8192
#define QKV_S 2304

// ---------------- scratch ----------------
__device__ float g_x   [MROWS*CDM];
__device__ float g_y   [MROWS*CDM];
__device__ float g_qg  [CB*CDM];
__device__ float g_bias[QKV_S];
__device__ float g_t   [CB*CH*CDM];
__device__ float g_p   [(size_t)CB*CH*CS];
__device__ float g_u   [CB*CH*CDM];
__device__ float g_up  [(size_t)32*CB*CH*CDM];
// single fp16 operand buffers
__device__ __half g_qkv[(size_t)MROWS*QKV_S];
__device__ __half g_xb [(size_t)MROWS*CDM];
__device__ __half g_ab [(size_t)MROWS*CDM];
__device__ __half g_hb [(size_t)MROWS*CDFF];
__device__ __half g_wb [(size_t)CDFF*CDM];

// ---------------- helpers ----------------
__device__ __forceinline__ float gelu_tanh(float x) {
    float x3 = x * x * x;
    return 0.5f * x * (1.0f + tanhf(0.7978845608028654f * (x + 0.044715f * x3)));
}
__device__ __forceinline__ uint32_t smem_u32(const void* p) {
    uint32_t a;
    asm("{ .reg .u64 t; cvta.to.shared.u64 t, %1; cvt.u32.u64 %0, t; }" : "=r"(a) : "l"(p));
    return a;
}
__device__ __forceinline__ uint32_t pack2(float a, float b) {
    __half2 t = __floats2half2_rn(a, b);
    return *(uint32_t*)&t;
}

// ================= split/convert kernels =================
__global__ void split_wt_hi_kernel(const float* __restrict__ W,
                                   __half* __restrict__ Wth, int K, int N) {
    __shared__ float t[32][33];
    int n0 = blockIdx.x * 32, k0 = blockIdx.y * 32;
    int tx = threadIdx.x, ty = threadIdx.y;
    #pragma unroll
    for (int r = 0; r < 4; r++) {
        int k = k0 + ty + r * 8;
        t[ty + r * 8][tx] = W[(size_t)k * N + n0 + tx];
    }
    __syncthreads();
    #pragma unroll
    for (int r = 0; r < 4; r++) {
        int n = n0 + ty + r * 8;
        int k = k0 + tx;
        Wth[(size_t)n * K + k] = __float2half_rn(t[tx][ty + r * 8]);
    }
}

__global__ void pack_bias_kernel(float* __restrict__ dst,
                                 const float* __restrict__ s0,
                                 const float* __restrict__ s1,
                                 const float* __restrict__ s2) {
    int i = blockIdx.x * 256 + threadIdx.x;
    int s = i / 768, r = i - s * 768;
    const float* p = (s == 0) ? s0 : (s == 1 ? s1 : s2);
    dst[i] = p[r];
}

// ================= warp-MMA fp16 GEMM (BK=64, 2-stage) =====================
// Stage = A(128x144B) | B(128x144B) = 36864B; 2 stages used; smem request
// padded to 81920B so at most 2 CTAs/SM co-reside (R13 lesson).
#define G_ROWB 144
#define G_MATB (128*G_ROWB)     // 18432
#define G_STG  (2*G_MATB)       // 36864
#define GSM_TOT 81920

__device__ __forceinline__ void ldm_x4(uint32_t addr, uint32_t& r0, uint32_t& r1,
                                       uint32_t& r2, uint32_t& r3) {
    asm volatile("ldmatrix.sync.aligned.m8n8.x4.shared.b16 {%0,%1,%2,%3}, [%4];"
        : "=r"(r0), "=r"(r1), "=r"(r2), "=r"(r3) : "r"(addr));
}
__device__ __forceinline__ void ldm_x4t(uint32_t addr, uint32_t& r0, uint32_t& r1,
                                        uint32_t& r2, uint32_t& r3) {
    asm volatile("ldmatrix.sync.aligned.m8n8.x4.trans.shared.b16 {%0,%1,%2,%3}, [%4];"
        : "=r"(r0), "=r"(r1), "=r"(r2), "=r"(r3) : "r"(addr));
}
__device__ __forceinline__ void mma_f16(float* c, const uint32_t* a, const uint32_t* b) {
    asm volatile("mma.sync.aligned.m16n8k16.row.col.f32.f16.f16.f32 "
        "{%0,%1,%2,%3}, {%4,%5,%6,%7}, {%8,%9}, {%0,%1,%2,%3};"
        : "+f"(c[0]), "+f"(c[1]), "+f"(c[2]), "+f"(c[3])
        : "r"(a[0]), "r"(a[1]), "r"(a[2]), "r"(a[3]), "r"(b[0]), "r"(b[1]));
}

// mode 0: Cf = acc+bias (fp32)
// mode 2: Cb = fp16(gelu(acc+bias))
// mode 3: Cb = fp16((acc+bias) * (col<768 ? CSCALE : 1))   [QKV]
__global__ __launch_bounds__(256, 2)
void gemm_mma_kernel(const __half* __restrict__ A,
                     const __half* __restrict__ Bt,
                     const float* __restrict__ bias,
                     float* __restrict__ Cf,
                     __half* __restrict__ Cb,
                     int Kp, int N, int mode) {
    extern __shared__ __align__(1024) char smem[];
    uint32_t sb = smem_u32(smem);
    int tid = threadIdx.x;
    int wid = tid >> 5, lane = tid & 31;
    int m0 = blockIdx.y * 128, n0 = blockIdx.x * 128;
    int warp_m = (wid & 1) * 64;
    int warp_n = (wid >> 1) * 32;
    int NC = Kp / 64;

    const __half* Ag = A  + (size_t)m0 * Kp;
    const __half* Bg = Bt + (size_t)n0 * Kp;

    float acc[4][4][4];
    #pragma unroll
    for (int i = 0; i < 4; i++)
        #pragma unroll
        for (int j = 0; j < 4; j++)
            #pragma unroll
            for (int r = 0; r < 4; r++) acc[i][j][r] = 0.f;

    auto load_tile = [&](int c, int bf) {
        uint32_t base = sb + bf * G_STG;
        const __half* srcs[2] = { Ag + (size_t)c * 64, Bg + (size_t)c * 64 };
        #pragma unroll
        for (int m = 0; m < 2; m++) {
            const __half* S = srcs[m];
            uint32_t mb = base + m * G_MATB;
            #pragma unroll
            for (int i = 0; i < 4; i++) {
                int ch = i * 256 + tid;            // 0..1023
                int r = ch >> 3, c8 = (ch & 7) * 8;
                uint32_t d = mb + r * G_ROWB + c8 * 2;
                const void* s = S + (size_t)r * Kp + c8;
                asm volatile("cp.async.cg.shared.global [%0], [%1], 16;" :: "r"(d), "l"(s));
            }
        }
    };

    load_tile(0, 0);
    asm volatile("cp.async.commit_group;" ::: "memory");

    int rsel = lane & 15, hsel = (lane >> 4) * 16;
    for (int c = 0; c < NC; c++) {
        int bf = c & 1;
        if (c + 1 < NC) load_tile(c + 1, bf ^ 1);
        asm volatile("cp.async.commit_group;" ::: "memory");
        asm volatile("cp.async.wait_group 1;" ::: "memory");
        __syncthreads();

        uint32_t ab = sb + bf * G_STG;
        uint32_t bb = ab + G_MATB;

        #pragma unroll
        for (int ks = 0; ks < 4; ks++) {
            uint32_t a[4][4], b[4][2];
            #pragma unroll
            for (int mi = 0; mi < 4; mi++) {
                uint32_t off = (warp_m + mi * 16 + rsel) * G_ROWB + ks * 32 + hsel;
                ldm_x4(ab + off, a[mi][0], a[mi][1], a[mi][2], a[mi][3]);
            }
            #pragma unroll
            for (int np = 0; np < 2; np++) {
                uint32_t off = (warp_n + np * 16 + rsel) * G_ROWB + ks * 32 + hsel;
                uint32_t r0, r1, r2, r3;
                ldm_x4(bb + off, r0, r1, r2, r3);
                b[np * 2 + 0][0] = r0; b[np * 2 + 0][1] = r2;
                b[np * 2 + 1][0] = r1; b[np * 2 + 1][1] = r3;
            }
            #pragma unroll
            for (int mi = 0; mi < 4; mi++)
                #pragma unroll
                for (int nj = 0; nj < 4; nj++)
                    mma_f16(acc[mi][nj], a[mi], b[nj]);
        }
        __syncthreads();
    }

    int g = lane >> 2, t = lane & 3;
    #pragma unroll
    for (int mi = 0; mi < 4; mi++) {
        int row0 = m0 + warp_m + mi * 16 + g;
        #pragma unroll
        for (int nj = 0; nj < 4; nj++) {
            int col = n0 + warp_n + nj * 8 + t * 2;
            float bx = bias[col], by = bias[col + 1];
            float v0 = acc[mi][nj][0] + bx, v1 = acc[mi][nj][1] + by;
            float v2 = acc[mi][nj][2] + bx, v3 = acc[mi][nj][3] + by;
            if (mode == 2) {
                v0 = gelu_tanh(v0); v1 = gelu_tanh(v1);
                v2 = gelu_tanh(v2); v3 = gelu_tanh(v3);
            } else if (mode == 3) {
                float sc = (col < 768) ? CSCALE : 1.0f;
                v0 *= sc; v1 *= sc; v2 *= sc; v3 *= sc;
            }
            if (mode >= 2) {
                size_t ro0 = (size_t)row0 * N + col;
                size_t ro1 = (size_t)(row0 + 8) * N + col;
                *(uint32_t*)&Cb[ro0] = pack2(v0, v1);
                *(uint32_t*)&Cb[ro1] = pack2(v2, v3);
            } else {
                *(float2*)&Cf[(size_t)row0 * N + col]       = make_float2(v0, v1);
                *(float2*)&Cf[(size_t)(row0 + 8) * N + col] = make_float2(v2, v3);
            }
        }
    }
}

// ================= fused flash band attention (single fp16) =================
#define FB_ROWB 144
#define FB_Q  0
#define FB_K  (FB_Q + 64*FB_ROWB)
#define FB_V  (FB_K + 64*FB_ROWB)
#define FB_SG (FB_V + 64*FB_ROWB)
#define FB_V0 (FB_SG + 256)
#define FB_CM (FB_V0 + 256)
#define FB_TOT (FB_CM + 256 + 64)

__global__ __launch_bounds__(128)
void flash_band_kernel(const __half* __restrict__ qkv,
                       const int* __restrict__ am,
                       __half* __restrict__ outb) {
    extern __shared__ char fsmc[];
    float* fp = (float*)fsmc;
    uint32_t sb = smem_u32(fsmc);
    int z = blockIdx.y;
    int n = z % CNB;
    int h = (z / CNB) % CH;
    int b = z / (CNB * CH);
    int qt = blockIdx.x;
    int tid = threadIdx.x;
    int w = tid >> 5, lane = tid & 31;
    int rsel = lane & 15, hsel = (lane >> 4) * 16;
    int t2 = (lane & 3) * 2;

    int base_s    = n * CW + qt * 64;
    int base_kpos = n * CW - CW;
    int am0 = am[b * CS];

    #pragma unroll
    for (int i = 0; i < 8; i++) {
        int sid = i * 128 + tid;
        int r = sid >> 4, c4 = (sid & 15) * 4;
        size_t gb = ((size_t)(b * CS + base_s + r)) * QKV_S + h * 64 + c4;
        *(uint2*)(fsmc + FB_Q + r * FB_ROWB + c4 * 2) = *(const uint2*)&qkv[gb];
    }
    if (tid < 64) {
        size_t gb = ((size_t)(b * CS)) * QKV_S + 1536 + h * 64 + tid;
        fp[FB_V0 / 4 + tid] = __half2float(qkv[gb]);
    }
    __syncthreads();

    {
        int row = tid >> 1, half = tid & 1;
        const __half* qh = (const __half*)(fsmc + FB_Q + row * FB_ROWB);
        size_t k0b = ((size_t)(b * CS)) * QKV_S + 768 + h * 64;
        float sgv = 0.f;
        #pragma unroll
        for (int d = 0; d < 32; d++) {
            int dd = half * 32 + d;
            sgv += __half2float(qh[dd]) * __half2float(qkv[k0b + dd]);
        }
        sgv += __shfl_xor_sync(0xffffffffu, sgv, 1);
        if (half == 0) fp[FB_SG / 4 + row] = sgv;
    }

    uint32_t qh[4][4];
    #pragma unroll
    for (int dk = 0; dk < 4; dk++) {
        uint32_t off = (16 * w + rsel) * FB_ROWB + dk * 32 + hsel;
        ldm_x4(sb + FB_Q + off, qh[dk][0], qh[dk][1], qh[dk][2], qh[dk][3]);
    }

    float o[8][4];
    #pragma unroll
    for (int nn = 0; nn < 8; nn++)
        #pragma unroll
        for (int e = 0; e < 4; e++) o[nn][e] = 0.f;
    float mst0 = -1e30f, mst1 = -1e30f, lst0 = 0.f, lst1 = 0.f;

    int qi0 = qt * 64 + 16 * w + (lane >> 2);
    int qi1 = qi0 + 8;

    for (int kc = 0; kc < 12; kc++) {
        __syncthreads();
        #pragma unroll
        for (int i = 0; i < 8; i++) {
            int sid = i * 128 + tid;
            int r = sid >> 4, c4 = (sid & 15) * 4;
            int kpos = base_kpos + kc * 64 + r;
            uint2 kh = make_uint2(0u, 0u), vh = make_uint2(0u, 0u);
            if (kpos >= 0 && kpos < CS) {
                size_t rb = ((size_t)(b * CS + kpos)) * QKV_S + h * 64 + c4;
                kh = *(const uint2*)&qkv[rb + 768];
                vh = *(const uint2*)&qkv[rb + 1536];
            }
            *(uint2*)(fsmc + FB_K + r * FB_ROWB + c4 * 2) = kh;
            *(uint2*)(fsmc + FB_V + r * FB_ROWB + c4 * 2) = vh;
        }
        if (tid < 64) {
            int kpos = base_kpos + kc * 64 + tid;
            bool ok = (kpos >= 0) && (kpos < CS) && (kpos != 0);
            if (ok) ok = am[b * CS + kpos] > 0;
            fp[FB_CM / 4 + tid] = ok ? 1.f : 0.f;
        }
        __syncthreads();

        float s[8][4];
        #pragma unroll
        for (int nn = 0; nn < 8; nn++)
            #pragma unroll
            for (int e = 0; e < 4; e++) s[nn][e] = 0.f;
        #pragma unroll
        for (int dk = 0; dk < 4; dk++) {
            #pragma unroll
            for (int np = 0; np < 4; np++) {
                uint32_t off = (np * 16 + rsel) * FB_ROWB + dk * 32 + hsel;
                uint32_t r0, r1, r2, r3;
                uint32_t ka[2], kb[2];
                ldm_x4(sb + FB_K + off, r0, r1, r2, r3);
                ka[0] = r0; ka[1] = r2; kb[0] = r1; kb[1] = r3;
                mma_f16(s[2 * np],     qh[dk], ka);
                mma_f16(s[2 * np + 1], qh[dk], kb);
            }
        }

        #pragma unroll
        for (int nn = 0; nn < 8; nn++) {
            #pragma unroll
            for (int e = 0; e < 2; e++) {
                int kj = kc * 64 + 8 * nn + t2 + e;
                float cm = fp[FB_CM / 4 + 8 * nn + t2 + e];
                bool b0 = (kj >= qi0) && (kj <= qi0 + 2 * CW) && (cm > 0.f);
                bool b1 = (kj >= qi1) && (kj <= qi1 + 2 * CW) && (cm > 0.f);
                if (!b0) s[nn][e] = CNEG;
                if (!b1) s[nn][2 + e] = CNEG;
            }
        }

        float mx0 = -1e30f, mx1 = -1e30f;
        #pragma unroll
        for (int nn = 0; nn < 8; nn++) {
            mx0 = fmaxf(mx0, fmaxf(s[nn][0], s[nn][1]));
            mx1 = fmaxf(mx1, fmaxf(s[nn][2], s[nn][3]));
        }
        mx0 = fmaxf(mx0, __shfl_xor_sync(0xffffffffu, mx0, 1));
        mx0 = fmaxf(mx0, __shfl_xor_sync(0xffffffffu, mx0, 2));
        mx1 = fmaxf(mx1, __shfl_xor_sync(0xffffffffu, mx1, 1));
        mx1 = fmaxf(mx1, __shfl_xor_sync(0xffffffffu, mx1, 2));
        float nm0 = fmaxf(mst0, mx0), nm1 = fmaxf(mst1, mx1);
        float a0 = __expf(mst0 - nm0), a1 = __expf(mst1 - nm1);
        mst0 = nm0; mst1 = nm1;
        float rs0 = 0.f, rs1 = 0.f;
        #pragma unroll
        for (int nn = 0; nn < 8; nn++) {
            s[nn][0] = __expf(s[nn][0] - nm0); rs0 += s[nn][0];
            s[nn][1] = __expf(s[nn][1] - nm0); rs0 += s[nn][1];
            s[nn][2] = __expf(s[nn][2] - nm1); rs1 += s[nn][2];
            s[nn][3] = __expf(s[nn][3] - nm1); rs1 += s[nn][3];
        }
        rs0 += __shfl_xor_sync(0xffffffffu, rs0, 1);
        rs0 += __shfl_xor_sync(0xffffffffu, rs0, 2);
        rs1 += __shfl_xor_sync(0xffffffffu, rs1, 1);
        rs1 += __shfl_xor_sync(0xffffffffu, rs1, 2);
        lst0 = lst0 * a0 + rs0;
        lst1 = lst1 * a1 + rs1;
        #pragma unroll
        for (int nn = 0; nn < 8; nn++) {
            o[nn][0] *= a0; o[nn][1] *= a0;
            o[nn][2] *= a1; o[nn][3] *= a1;
        }

        uint32_t ph[4][4];
        #pragma unroll
        for (int qf = 0; qf < 4; qf++) {
            ph[qf][0] = pack2(s[2 * qf][0],     s[2 * qf][1]);
            ph[qf][1] = pack2(s[2 * qf][2],     s[2 * qf][3]);
            ph[qf][2] = pack2(s[2 * qf + 1][0], s[2 * qf + 1][1]);
            ph[qf][3] = pack2(s[2 * qf + 1][2], s[2 * qf + 1][3]);
        }

        #pragma unroll
        for (int qf = 0; qf < 4; qf++) {
            #pragma unroll
            for (int dp = 0; dp < 4; dp++) {
                uint32_t off = (qf * 16 + rsel) * FB_ROWB + dp * 32 + hsel;
                uint32_t r0, r1, r2, r3;
                uint32_t va[2], vb[2];
                ldm_x4t(sb + FB_V + off, r0, r1, r2, r3);
                va[0] = r0; va[1] = r1; vb[0] = r2; vb[1] = r3;
                mma_f16(o[2 * dp],     ph[qf], va);
                mma_f16(o[2 * dp + 1], ph[qf], vb);
            }
        }
    }

    #pragma unroll
    for (int rr = 0; rr < 2; rr++) {
        int row = 16 * w + (lane >> 2) + 8 * rr;
        float mst = rr ? mst1 : mst0;
        float lst = rr ? lst1 : lst0;
        float sg = fp[FB_SG / 4 + row];
        if (am0 <= 0) sg = CNEG;
        float nm = fmaxf(mst, sg);
        float alpha = __expf(mst - nm);
        float pg = __expf(sg - nm);
        float l = lst * alpha + pg;
        float inv = 1.0f / l;
        int srow = base_s + row;
        size_t ob = ((size_t)(b * CS + srow)) * CDM + h * 64;
        #pragma unroll
        for (int nn = 0; nn < 8; nn++) {
            int d = 8 * nn + t2;
            float v0 = (o[nn][2 * rr + 0] * alpha + pg * fp[FB_V0 / 4 + d])     * inv;
            float v1 = (o[nn][2 * rr + 1] * alpha + pg * fp[FB_V0 / 4 + d + 1]) * inv;
            *(uint32_t*)&outb[ob + d] = pack2(v0, v1);
        }
    }
}

// ================= small kernels =================
__device__ __forceinline__ float block_reduce_sum256(float v, float* red) {
    int tid = threadIdx.x;
    red[tid] = v; __syncthreads();
    #pragma unroll
    for (int o = 128; o > 0; o >>= 1) {
        if (tid < o) red[tid] += red[tid + o];
        __syncthreads();
    }
    float r = red[0]; __syncthreads();
    return r;
}

__global__ void embed_ln_kernel(const int* __restrict__ ids,
                                const float* __restrict__ we,
                                const float* __restrict__ pe,
                                const float* __restrict__ gam,
                                const float* __restrict__ bet,
                                float* __restrict__ x,
                                __half* __restrict__ xb) {
    __shared__ float red[256];
    int row = blockIdx.x;
    int s = row % CS;
    int id = ids[row];
    int tid = threadIdx.x;
    const float* wp = we + (size_t)id * CDM;
    const float* pp = pe + (size_t)s * CDM;
    float e[3];
    float sm = 0.f;
    #pragma unroll
    for (int i = 0; i < 3; i++) { int d = tid + i * 256; e[i] = wp[d] + pp[d]; sm += e[i]; }
    float mean = block_reduce_sum256(sm, red) * (1.0f / CDM);
    float vs = 0.f;
    #pragma unroll
    for (int i = 0; i < 3; i++) { float t = e[i] - mean; vs += t * t; }
    float var = block_reduce_sum256(vs, red) * (1.0f / CDM);
    float inv = rsqrtf(var + 1e-5f);
    float* xr = x + (size_t)row * CDM;
    size_t ro = (size_t)row * CDM;
    #pragma unroll
    for (int i = 0; i < 3; i++) {
        int d = tid + i * 256;
        float val = (e[i] - mean) * inv * gam[d] + bet[d];
        xr[d] = val;
        xb[ro + d] = __float2half_rn(val);
    }
}

__global__ void add_ln_kernel(float* __restrict__ x,
                              const float* __restrict__ y,
                              const float* __restrict__ gam,
                              const float* __restrict__ bet,
                              __half* __restrict__ xb) {
    __shared__ float red[256];
    int row = blockIdx.x;
    int tid = threadIdx.x;
    float* xr = x + (size_t)row * CDM;
    const float* yr = y + (size_t)row * CDM;
    float e[3];
    float sm = 0.f;
    #pragma unroll
    for (int i = 0; i < 3; i++) { int d = tid + i * 256; e[i] = xr[d] + yr[d]; sm += e[i]; }
    float mean = block_reduce_sum256(sm, red) * (1.0f / CDM);
    float vs = 0.f;
    #pragma unroll
    for (int i = 0; i < 3; i++) { float t = e[i] - mean; vs += t * t; }
    float var = block_reduce_sum256(vs, red) * (1.0f / CDM);
    float inv = rsqrtf(var + 1e-5f);
    size_t ro = (size_t)row * CDM;
    #pragma unroll
    for (int i = 0; i < 3; i++) {
        int d = tid + i * 256;
        float val = (e[i] - mean) * inv * gam[d] + bet[d];
        xr[d] = val;
        xb[ro + d] = __float2half_rn(val);
    }
}

// qg from fp16 xb
__global__ void qg_kernel(const __half* __restrict__ xb,
                          const float* __restrict__ Wqg,
                          const float* __restrict__ bqg,
                          float* __restrict__ qg) {
    __shared__ float part[4][64];
    int n0 = blockIdx.x * 64;
    int b = blockIdx.y;
    int tid = threadIdx.x;
    int nl = tid & 63, kq = tid >> 6;
    const __half* xr = xb + (size_t)(b * CS) * CDM;
    float acc = 0.f;
    for (int kk = kq * 192; kk < (kq + 1) * 192; kk++)
        acc += __half2float(xr[kk]) * Wqg[(size_t)kk * CDM + n0 + nl];
    part[kq][nl] = acc;
    __syncthreads();
    if (kq == 0) {
        float t = part[0][nl] + part[1][nl] + part[2][nl] + part[3][nl];
        qg[b * CDM + n0 + nl] = (t + bqg[n0 + nl]) * CSCALE;
    }
}

__global__ void tk_kernel(const float* __restrict__ Wkg,
                          const float* __restrict__ qg,
                          float* __restrict__ t) {
    int k = blockIdx.x * 128 + threadIdx.x;
    int h = blockIdx.y, b = blockIdx.z;
    const float* W = Wkg + (size_t)k * CDM + h * 64;
    const float* q = qg + b * CDM + h * 64;
    float acc = 0.f;
    #pragma unroll
    for (int d = 0; d < 64; d++) acc += W[d] * q[d];
    t[(b * CH + h) * CDM + k] = acc;
}

// sgl from fp16 xb
__global__ __launch_bounds__(256)
void sgl_kernel(const __half* __restrict__ xb,
                const float* __restrict__ t,
                const int* __restrict__ am,
                float* __restrict__ p) {
    __shared__ float ts[CH][CDM];
    int b = blockIdx.y;
    int tid = threadIdx.x;
    for (int i = tid; i < CH * CDM; i += 256)
        ((float*)ts)[i] = t[b * CH * CDM + i];
    __syncthreads();
    int w = tid >> 5, lane = tid & 31;
    int s = blockIdx.x * 8 + w;
    const __half* xr = xb + ((size_t)(b * CS + s)) * CDM;
    float acc[CH];
    #pragma unroll
    for (int h = 0; h < CH; h++) acc[h] = 0.f;
    for (int k = lane; k < CDM; k += 32) {
        float xv = __half2float(xr[k]);
        #pragma unroll
        for (int h = 0; h < CH; h++) acc[h] += xv * ts[h][k];
    }
    #pragma unroll
    for (int h = 0; h < CH; h++) {
        #pragma unroll
        for (int o = 16; o > 0; o >>= 1)
            acc[h] += __shfl_xor_sync(0xffffffffu, acc[h], o);
    }
    bool okm = am[b * CS + s] > 0;
    if (lane < CH)
        p[((size_t)(b * CH + lane)) * CS + s] = okm ? acc[lane] : CNEG;
}

__global__ void softmax_p_kernel(float* __restrict__ p) {
    __shared__ float red[256];
    int h = blockIdx.x, b = blockIdx.y;
    int tid = threadIdx.x;
    float* pr = p + ((size_t)(b * CH + h)) * CS;
    float mx = -1e30f;
    for (int s = tid; s < CS; s += 256) mx = fmaxf(mx, pr[s]);
    red[tid] = mx; __syncthreads();
    #pragma unroll
    for (int o = 128; o > 0; o >>= 1) {
        if (tid < o) red[tid] = fmaxf(red[tid], red[tid + o]);
        __syncthreads();
    }
    mx = red[0]; __syncthreads();
    float sm = 0.f;
    for (int s = tid; s < CS; s += 256) {
        float e = __expf(pr[s] - mx);
        pr[s] = e; sm += e;
    }
    float tot = block_reduce_sum256(sm, red);
    float inv = 1.0f / tot;
    for (int s = tid; s < CS; s += 256) pr[s] *= inv;
}

// u partials from fp16 xb
__global__ __launch_bounds__(256)
void u_part_kernel(const float* __restrict__ p,
                   const __half* __restrict__ xb,
                   float* __restrict__ up) {
    __shared__ float xs[128][64];
    __shared__ float ps[CH][128];
    int kc = blockIdx.x, sc = blockIdx.y, b = blockIdx.z;
    int k0 = kc * 64;
    int tid = threadIdx.x;
    int kl = tid & 63, h0 = tid >> 6;
    #pragma unroll
    for (int i = 0; i < 32; i++) {
        int idx = i * 256 + tid;
        int r = idx >> 6, c = idx & 63;
        xs[r][c] = __half2float(xb[((size_t)(b * CS + sc * 128 + r)) * CDM + k0 + c]);
    }
    #pragma unroll
    for (int i = 0; i < 6; i++) {
        int idx = i * 256 + tid;
        int hh = idx >> 7, ss = idx & 127;
        ps[hh][ss] = p[((size_t)(b * CH + hh)) * CS + sc * 128 + ss];
    }
    __syncthreads();
    float acc[3] = {0.f, 0.f, 0.f};
    for (int s = 0; s < 128; s++) {
        float xv = xs[s][kl];
        acc[0] += ps[h0][s] * xv;
        acc[1] += ps[h0 + 4][s] * xv;
        acc[2] += ps[h0 + 8][s] * xv;
    }
    size_t base = ((size_t)(sc * CB + b)) * CH * CDM;
    up[base + (h0)     * CDM + k0 + kl] = acc[0];
    up[base + (h0 + 4) * CDM + k0 + kl] = acc[1];
    up[base + (h0 + 8) * CDM + k0 + kl] = acc[2];
}

__global__ void u_reduce_kernel(const float* __restrict__ up,
                                float* __restrict__ u) {
    int i = blockIdx.x * 256 + threadIdx.x;
    int b = blockIdx.y;
    float acc = 0.f;
    #pragma unroll
    for (int sc = 0; sc < 32; sc++)
        acc += up[((size_t)(sc * CB + b)) * CH * CDM + i];
    u[b * CH * CDM + i] = acc;
}

__global__ void og_kernel(const float* __restrict__ u,
                          const float* __restrict__ Wvg,
                          const float* __restrict__ bvg,
                          __half* __restrict__ outb) {
    __shared__ float part[4][64];
    int h = blockIdx.x, b = blockIdx.y;
    int tid = threadIdx.x;
    int d = tid & 63, kq = tid >> 6;
    const float* upr = u + (b * CH + h) * CDM;
    float acc = 0.f;
    for (int k = kq * 192; k < (kq + 1) * 192; k++)
        acc += upr[k] * Wvg[(size_t)k * CDM + h * 64 + d];
    part[kq][d] = acc;
    __syncthreads();
    if (kq == 0) {
        float t = part[0][d] + part[1][d] + part[2][d] + part[3][d] + bvg[h * 64 + d];
        outb[((size_t)(b * CS)) * CDM + h * 64 + d] = __float2half_rn(t);
    }
}

__global__ void cls_kernel(const float* __restrict__ x,
                           const float* __restrict__ Wc,
                           const float* __restrict__ bc,
                           float* __restrict__ out) {
    __shared__ float red[256];
    int b = blockIdx.x >> 1, c = blockIdx.x & 1;
    int tid = threadIdx.x;
    const float* xr = x + (size_t)(b * CS) * CDM;
    float acc = 0.f;
    for (int d = tid; d < CDM; d += 256) acc += xr[d] * Wc[d * 2 + c];
    float tot = block_reduce_sum256(acc, red);
    if (tid == 0) out[b * 2 + c] = tot + bc[c];
}

// ================= launch =================
extern "C" void kernel_launch(void* const* d_in, const int* in_sizes, int n_in,
                              void* d_out, int out_size) {
    const int*   ids  = (const int*)d_in[0];
    const int*   am   = (const int*)d_in[1];
    const float* we   = (const float*)d_in[2];
    const float* pe   = (const float*)d_in[3];
    const float* lnes = (const float*)d_in[4];
    const float* lneb = (const float*)d_in[5];
    const float* Wq   = (const float*)d_in[6];
    const float* bq   = (const float*)d_in[7];
    const float* Wk   = (const float*)d_in[8];
    const float* bk   = (const float*)d_in[9];
    const float* Wv   = (const float*)d_in[10];
    const float* bv   = (const float*)d_in[11];
    const float* Wqg  = (const float*)d_in[12];
    const float* bqg  = (const float*)d_in[13];
    const float* Wkg  = (const float*)d_in[14];
    const float* bkg  = (const float*)d_in[15];
    const float* Wvg  = (const float*)d_in[16];
    const float* bvg  = (const float*)d_in[17];
    const float* Wo   = (const float*)d_in[18];
    const float* bo   = (const float*)d_in[19];
    const float* ln1s = (const float*)d_in[20];
    const float* ln1b = (const float*)d_in[21];
    const float* W1   = (const float*)d_in[22];
    const float* b1   = (const float*)d_in[23];
    const float* W2   = (const float*)d_in[24];
    const float* b2   = (const float*)d_in[25];
    const float* ln2s = (const float*)d_in[26];
    const float* ln2b = (const float*)d_in[27];
    const float* Wcls = (const float*)d_in[28];
    const float* bcls = (const float*)d_in[29];
    float* out = (float*)d_out;

    float *xp, *yp, *qgp, *biasp, *tp, *pp, *up, *upp;
    __half *qkvp, *xbp, *abp, *hbp, *wbp;
    cudaGetSymbolAddress((void**)&xp,   g_x);
    cudaGetSymbolAddress((void**)&yp,   g_y);
    cudaGetSymbolAddress((void**)&qgp,  g_qg);
    cudaGetSymbolAddress((void**)&biasp, g_bias);
    cudaGetSymbolAddress((void**)&tp,   g_t);
    cudaGetSymbolAddress((void**)&pp,   g_p);
    cudaGetSymbolAddress((void**)&up,   g_u);
    cudaGetSymbolAddress((void**)&upp,  g_up);
    cudaGetSymbolAddress((void**)&qkvp, g_qkv);
    cudaGetSymbolAddress((void**)&xbp,  g_xb);
    cudaGetSymbolAddress((void**)&abp,  g_ab);
    cudaGetSymbolAddress((void**)&hbp,  g_hb);
    cudaGetSymbolAddress((void**)&wbp,  g_wb);

    cudaFuncSetAttribute(gemm_mma_kernel, cudaFuncAttributeMaxDynamicSharedMemorySize, GSM_TOT);
    cudaFuncSetAttribute(flash_band_kernel, cudaFuncAttributeMaxDynamicSharedMemorySize, FB_TOT);

    embed_ln_kernel<<<MROWS, 256>>>(ids, we, pe, lnes, lneb, xp, xbp);

    dim3 wt_dm(CDM / 32, CDM / 32);
    dim3 wt_b(32, 8);
    size_t wseg = (size_t)CDM * CDM;

    for (int l = 0; l < CL; l++) {
        size_t woff = (size_t)l * CDM * CDM;
        size_t boff = (size_t)l * CDM;
        size_t w1off = (size_t)l * CDM * CDFF;
        size_t b1off = (size_t)l * CDFF;
        size_t w2off = (size_t)l * CDFF * CDM;

        // --- fused QKV GEMM (fp16, Q pre-scaled) ---
        split_wt_hi_kernel<<<wt_dm, wt_b>>>(Wq + woff, wbp,            CDM, CDM);
        split_wt_hi_kernel<<<wt_dm, wt_b>>>(Wk + woff, wbp + wseg,     CDM, CDM);
        split_wt_hi_kernel<<<wt_dm, wt_b>>>(Wv + woff, wbp + 2 * wseg, CDM, CDM);
        pack_bias_kernel<<<9, 256>>>(biasp, bq + boff, bk + boff, bv + boff);
        gemm_mma_kernel<<<dim3(QKV_S / 128, MROWS / 128), 256, GSM_TOT>>>(
            xbp, wbp, biasp, nullptr, qkvp, CDM, QKV_S, 3);

        flash_band_kernel<<<dim3(4, CB * CH * CNB), 128, FB_TOT>>>(qkvp, am, abp);

        // --- factored global attention ---
        qg_kernel<<<dim3(CDM / 64, CB), 256>>>(xbp, Wqg + woff, bqg + boff, qgp);
        tk_kernel<<<dim3(CDM / 128, CH, CB), 128>>>(Wkg + woff, qgp, tp);
        sgl_kernel<<<dim3(CS / 8, CB), 256>>>(xbp, tp, am, pp);
        softmax_p_kernel<<<dim3(CH, CB), 256>>>(pp);
        u_part_kernel<<<dim3(CDM / 64, 32, CB), 256>>>(pp, xbp, upp);
        u_reduce_kernel<<<dim3(CH * CDM / 256, CB), 256>>>(upp, up);
        og_kernel<<<dim3(CH, CB), 256>>>(up, Wvg + woff, bvg + boff, abp);

        // --- Wo projection + LN1 ---
        split_wt_hi_kernel<<<wt_dm, wt_b>>>(Wo + woff, wbp, CDM, CDM);
        gemm_mma_kernel<<<dim3(CDM / 128, MROWS / 128), 256, GSM_TOT>>>(
            abp, wbp, bo + boff, yp, nullptr, CDM, CDM, 0);
        add_ln_kernel<<<MROWS, 256>>>(xp, yp, ln1s + boff, ln1b + boff, xbp);

        // --- FFN ---
        split_wt_hi_kernel<<<dim3(CDFF / 32, CDM / 32), wt_b>>>(W1 + w1off, wbp, CDM, CDFF);
        gemm_mma_kernel<<<dim3(CDFF / 128, MROWS / 128), 256, GSM_TOT>>>(
            xbp, wbp, b1 + b1off, nullptr, hbp, CDM, CDFF, 2);

        split_wt_hi_kernel<<<dim3(CDM / 32, CDFF / 32), wt_b>>>(W2 + w2off, wbp, CDFF, CDM);
        gemm_mma_kernel<<<dim3(CDM / 128, MROWS / 128), 256, GSM_TOT>>>(
            hbp, wbp, b2 + boff, yp, nullptr, CDFF, CDM, 0);
        add_ln_kernel<<<MROWS, 256>>>(xp, yp, ln2s + boff, ln2b + boff, xbp);
    }

    cls_kernel<<<4, 256>>>(xp, Wcls, bcls, out);
}